// round 6
// baseline (speedup 1.0000x reference)
#include <cuda_runtime.h>
#include <cuda_bf16.h>
#include <cuda_fp16.h>
#include <cstdint>

#define Nn 50000
#define Ee 800000
#define Hd 128
#define SCB 49       // scan blocks (ceil(Nn/1024))
#define PMAX 1600    // max stats-partial blocks (gemm12 uses 1563)

// ---------------- scratch ----------------
__device__ int   g_deg[Nn];
__device__ int   g_cnt[Nn];
__device__ int   g_rowptr[Nn + 1];
__device__ int   g_tmpptr[Nn];
__device__ float g_dinv[Nn];
__device__ int2  g_epk[Ee];          // (src, weight-bits)
__device__ int   g_bsum[SCB];
__device__ int   g_boff[SCB];

__device__ __align__(256) float g_t1[Nn * Hd];
__device__ __align__(256) float g_t2[Nn * Hd];
__device__ __align__(256) float g_t3[Nn * Hd];
__device__ __align__(256) float g_out[Nn * Hd];

// fp16 gather mirrors (h, t1, t2 are the only gathered tensors)
__device__ __align__(256) __half g_h16[Nn * Hd];
__device__ __align__(256) __half g_u16[Nn * Hd];
__device__ __align__(256) __half g_v16[Nn * Hd];

__device__ float g_s1[Nn * 3];
__device__ float g_s2[Nn * 3];
__device__ float g_s3[Nn * 3];

__device__ float g_part [PMAX * Hd];
__device__ float g_part2[PMAX * Hd];
__device__ float g_scale[Hd];
__device__ float g_shift[Hd];

// ---------------- helpers ----------------
__device__ __forceinline__ uint32_t f2tf32(float f) {
    uint32_t u;
    asm("cvt.rna.tf32.f32 %0, %1;" : "=r"(u) : "f"(f));
    return u;
}
__device__ __forceinline__ void split_tf32(float f, uint32_t& hi, uint32_t& lo) {
    hi = f2tf32(f);
    lo = f2tf32(f - __uint_as_float(hi));
}
__device__ __forceinline__ void mma_tf32(float* c, const uint32_t* a, const uint32_t* b) {
    asm volatile(
        "mma.sync.aligned.m16n8k8.row.col.f32.tf32.tf32.f32 "
        "{%0,%1,%2,%3}, {%4,%5,%6,%7}, {%8,%9}, {%0,%1,%2,%3};"
        : "+f"(c[0]), "+f"(c[1]), "+f"(c[2]), "+f"(c[3])
        : "r"(a[0]), "r"(a[1]), "r"(a[2]), "r"(a[3]), "r"(b[0]), "r"(b[1]));
}

// ---------------- graph build ----------------
__global__ void k_init() {
    int i = blockIdx.x * blockDim.x + threadIdx.x;
    if (i < Nn) { g_deg[i] = 0; g_cnt[i] = 0; }
}

__global__ void k_count(const int* __restrict__ ei) {
    int e = blockIdx.x * blockDim.x + threadIdx.x;
    if (e < Ee) {
        int s = ei[e];
        int d = ei[e + Ee];
        if ((unsigned)s < Nn) atomicAdd(&g_deg[s], 1);
        if ((unsigned)d < Nn) atomicAdd(&g_cnt[d], 1);
    }
}

__global__ void k_dinv() {
    int i = blockIdx.x * blockDim.x + threadIdx.x;
    if (i < Nn) {
        int d = g_deg[i];
        g_dinv[i] = (d > 0) ? rsqrtf((float)d) : 0.0f;
    }
}

__global__ void k_scan1() {
    __shared__ int sd[1024];
    int b = blockIdx.x, tid = threadIdx.x;
    int i = b * 1024 + tid;
    int v = (i < Nn) ? g_cnt[i] : 0;
    sd[tid] = v;
    __syncthreads();
    for (int off = 1; off < 1024; off <<= 1) {
        int t = (tid >= off) ? sd[tid - off] : 0;
        __syncthreads();
        sd[tid] += t;
        __syncthreads();
    }
    if (i < Nn) g_rowptr[i + 1] = sd[tid];
    if (tid == 1023) g_bsum[b] = sd[1023];
}
__global__ void k_scan2() {
    if (threadIdx.x == 0) {
        int acc = 0;
        for (int b = 0; b < SCB; b++) { g_boff[b] = acc; acc += g_bsum[b]; }
        g_rowptr[0] = 0;
    }
}
__global__ void k_scan3() {
    int i = blockIdx.x * blockDim.x + threadIdx.x;
    if (i < Nn) {
        int r = g_rowptr[i + 1] + g_boff[i >> 10];
        g_rowptr[i + 1] = r;
        g_tmpptr[i] = r - g_cnt[i];
    }
}

__global__ void k_fill(const int* __restrict__ ei) {
    int e = blockIdx.x * blockDim.x + threadIdx.x;
    if (e < Ee) {
        int s = ei[e];
        int d = ei[e + Ee];
        if ((unsigned)s >= Nn || (unsigned)d >= Nn) return;
        int p = atomicAdd(&g_tmpptr[d], 1);
        float w = -g_dinv[s] * g_dinv[d];
        g_epk[p] = make_int2(s, __float_as_int(w));
    }
}

// ---------------- propagation ----------------
__global__ void k_prop3(const float* __restrict__ hin,
                        const float* __restrict__ sub,
                        float* __restrict__ out) {
    int v = blockIdx.x * blockDim.x + threadIdx.x;
    if (v >= Nn) return;
    float a0 = 0.f, a1 = 0.f, a2 = 0.f;
    int b = g_rowptr[v], en = g_rowptr[v + 1];
    for (int i = b; i < en; i++) {
        int2 e = g_epk[i];
        float w = __int_as_float(e.y);
        const float* hp = hin + e.x * 3;
        a0 += w * hp[0]; a1 += w * hp[1]; a2 += w * hp[2];
    }
    float* o = out + v * 3;
    if (sub) {
        const float* sv = sub + v * 3;
        o[0] = 2.f * a0 - sv[0]; o[1] = 2.f * a1 - sv[1]; o[2] = 2.f * a2 - sv[2];
    } else {
        o[0] = a0; o[1] = a1; o[2] = a2;
    }
}

// warp per node; gathers fp16 mirror, accumulates fp32.
// mode: 1 = BN analytic on gathered h (no sub), 2 = BN applied to sub,
//       0 = plain 2*acc - sub (or plain acc if sub==null).
__global__ void k_prop128(const __half* __restrict__ hin16,
                          const float* __restrict__ sub,
                          float* __restrict__ out,
                          __half* __restrict__ out16,
                          const float* __restrict__ sc,
                          const float* __restrict__ sh,
                          int mode) {
    int v = blockIdx.x * 4 + (threadIdx.x >> 5);
    if (v >= Nn) return;
    int lane = threadIdx.x & 31;
    float4 sc4, sh4;
    if (mode) {
        sc4 = ((const float4*)sc)[lane];
        sh4 = ((const float4*)sh)[lane];
    }
    int b = g_rowptr[v], en = g_rowptr[v + 1];
    float4 acc = make_float4(0.f, 0.f, 0.f, 0.f);
    float wsum = 0.f;
    int i = b;
    for (; i + 1 < en; i += 2) {
        int2 e0 = g_epk[i];
        int2 e1 = g_epk[i + 1];
        float w0 = __int_as_float(e0.y);
        float w1 = __int_as_float(e1.y);
        uint2 p0 = *(const uint2*)(hin16 + e0.x * Hd + lane * 4);
        uint2 p1 = *(const uint2*)(hin16 + e1.x * Hd + lane * 4);
        float2 a01 = __half22float2(*(__half2*)&p0.x);
        float2 a23 = __half22float2(*(__half2*)&p0.y);
        float2 b01 = __half22float2(*(__half2*)&p1.x);
        float2 b23 = __half22float2(*(__half2*)&p1.y);
        acc.x += w0 * a01.x + w1 * b01.x;
        acc.y += w0 * a01.y + w1 * b01.y;
        acc.z += w0 * a23.x + w1 * b23.x;
        acc.w += w0 * a23.y + w1 * b23.y;
        wsum += w0 + w1;
    }
    if (i < en) {
        int2 e = g_epk[i];
        float w = __int_as_float(e.y);
        uint2 p0 = *(const uint2*)(hin16 + e.x * Hd + lane * 4);
        float2 a01 = __half22float2(*(__half2*)&p0.x);
        float2 a23 = __half22float2(*(__half2*)&p0.y);
        acc.x += w * a01.x; acc.y += w * a01.y;
        acc.z += w * a23.x; acc.w += w * a23.y;
        wsum += w;
    }
    float4 r;
    if (mode == 1) {
        r.x = sc4.x * acc.x + sh4.x * wsum;
        r.y = sc4.y * acc.y + sh4.y * wsum;
        r.z = sc4.z * acc.z + sh4.z * wsum;
        r.w = sc4.w * acc.w + sh4.w * wsum;
    } else if (mode == 2) {
        float4 sv = *(const float4*)(sub + v * Hd + lane * 4);
        r.x = 2.f * acc.x - (sc4.x * sv.x + sh4.x);
        r.y = 2.f * acc.y - (sc4.y * sv.y + sh4.y);
        r.z = 2.f * acc.z - (sc4.z * sv.z + sh4.z);
        r.w = 2.f * acc.w - (sc4.w * sv.w + sh4.w);
    } else if (sub) {
        float4 sv = *(const float4*)(sub + v * Hd + lane * 4);
        r.x = 2.f * acc.x - sv.x; r.y = 2.f * acc.y - sv.y;
        r.z = 2.f * acc.z - sv.z; r.w = 2.f * acc.w - sv.w;
    } else {
        r = acc;
    }
    *(float4*)(out + v * Hd + lane * 4) = r;
    if (out16) {
        uint2 pk;
        *(__half2*)&pk.x = __floats2half2_rn(r.x, r.y);
        *(__half2*)&pk.y = __floats2half2_rn(r.z, r.w);
        *(uint2*)(out16 + v * Hd + lane * 4) = pk;
    }
}

// ---------------- layer 1 GEMM: K=12 (+ fused stats + fp16 mirror) ----------
__global__ void k_gemm12(const float* __restrict__ x,  const float* __restrict__ t1,
                         const float* __restrict__ t2, const float* __restrict__ t3,
                         const float* __restrict__ W,  const float* __restrict__ bias,
                         float* __restrict__ out, __half* __restrict__ out16) {
    __shared__ float sW[12 * Hd];
    int c = threadIdx.x;
    #pragma unroll
    for (int j = 0; j < 12; j++) sW[j * Hd + c] = W[j * Hd + c];
    __syncthreads();
    const int RPB = 32;
    int v0 = blockIdx.x * RPB;
    float bv = bias[c];
    float s = 0.f, s2 = 0.f;
    for (int r = 0; r < RPB; r++) {
        int v = v0 + r;
        if (v >= Nn) break;
        float a[12];
        #pragma unroll
        for (int f = 0; f < 3; f++) {
            a[f]     = x [v * 3 + f];
            a[3 + f] = t1[v * 3 + f];
            a[6 + f] = t2[v * 3 + f];
            a[9 + f] = t3[v * 3 + f];
        }
        float acc = bv;
        #pragma unroll
        for (int j = 0; j < 12; j++) acc += a[j] * sW[j * Hd + c];
        acc = (acc > 0.f) ? acc : 0.01f * acc;   // leaky relu
        out[v * Hd + c] = acc;
        out16[v * Hd + c] = __float2half(acc);
        s += acc; s2 += acc * acc;
    }
    g_part [blockIdx.x * Hd + c] = s;
    g_part2[blockIdx.x * Hd + c] = s2;
}

// ---------------- 3xTF32 tensor-core GEMM + fused epilogues ----------------
// mode: 1 = leaky+stats, 2 = relu+stats, 0 = no-act + row-L2-normalize
#define BM 128
#define BK 16
#define ASTR (BK + 4)     // 20
#define BSTR (Hd + 8)     // 136

__global__ __launch_bounds__(256)
void k_gemm_mma(const float* __restrict__ A0, const float* __restrict__ A1,
                const float* __restrict__ A2, const float* __restrict__ A3,
                const float* __restrict__ W,  const float* __restrict__ bias,
                float* __restrict__ out, __half* __restrict__ out16,
                const float* __restrict__ scA, const float* __restrict__ shA,
                int mode) {
    __shared__ uint32_t Ah[BM][ASTR];
    __shared__ uint32_t Al[BM][ASTR];
    __shared__ uint32_t Bh[BK][BSTR];
    __shared__ uint32_t Bl[BK][BSTR];
    __shared__ float sred [8][64];
    __shared__ float sred2[8][64];
    __shared__ float rows2[2][BM];
    const float* Abuf[4] = {A0, A1, A2, A3};

    int tid = threadIdx.x;
    int wid = tid >> 5;
    int lane = tid & 31;
    int grp = lane >> 2;       // 0..7
    int tig = lane & 3;        // 0..3
    int m_base = (wid >> 1) * 32;
    int n_base = (wid & 1) * 64;
    int row0 = blockIdx.x * BM;

    float c[2][8][4];
    #pragma unroll
    for (int mi = 0; mi < 2; mi++)
        #pragma unroll
        for (int ni = 0; ni < 8; ni++)
            #pragma unroll
            for (int q = 0; q < 4; q++) c[mi][ni][q] = 0.f;

    int la_r  = tid >> 1;
    int la_c4 = (tid & 1) * 8;
    int lb_k  = tid >> 5;
    int lb_c4 = (tid & 31) * 4;

    for (int kt = 0; kt < 32; kt++) {
        const float* A = Abuf[kt >> 3];
        int cb = (kt & 7) * BK;
        {
            int gr = row0 + la_r;
            float4 v0 = make_float4(0.f,0.f,0.f,0.f), v1 = v0;
            if (gr < Nn) {
                const float4* src = (const float4*)(A + gr * Hd + cb + la_c4);
                v0 = src[0]; v1 = src[1];
            }
            if (scA && (kt >> 3) == 0) {   // A0 = BN(h) applied inline
                float4 s0 = *(const float4*)(scA + cb + la_c4);
                float4 s1 = *(const float4*)(scA + cb + la_c4 + 4);
                float4 h0 = *(const float4*)(shA + cb + la_c4);
                float4 h1 = *(const float4*)(shA + cb + la_c4 + 4);
                v0.x = v0.x * s0.x + h0.x; v0.y = v0.y * s0.y + h0.y;
                v0.z = v0.z * s0.z + h0.z; v0.w = v0.w * s0.w + h0.w;
                v1.x = v1.x * s1.x + h1.x; v1.y = v1.y * s1.y + h1.y;
                v1.z = v1.z * s1.z + h1.z; v1.w = v1.w * s1.w + h1.w;
                if (gr >= Nn) { v0 = make_float4(0,0,0,0); v1 = v0; }
            }
            uint32_t h, l;
            uint4 uh0, ul0, uh1, ul1;
            split_tf32(v0.x, h, l); uh0.x = h; ul0.x = l;
            split_tf32(v0.y, h, l); uh0.y = h; ul0.y = l;
            split_tf32(v0.z, h, l); uh0.z = h; ul0.z = l;
            split_tf32(v0.w, h, l); uh0.w = h; ul0.w = l;
            split_tf32(v1.x, h, l); uh1.x = h; ul1.x = l;
            split_tf32(v1.y, h, l); uh1.y = h; ul1.y = l;
            split_tf32(v1.z, h, l); uh1.z = h; ul1.z = l;
            split_tf32(v1.w, h, l); uh1.w = h; ul1.w = l;
            *(uint4*)&Ah[la_r][la_c4]     = uh0;
            *(uint4*)&Ah[la_r][la_c4 + 4] = uh1;
            *(uint4*)&Al[la_r][la_c4]     = ul0;
            *(uint4*)&Al[la_r][la_c4 + 4] = ul1;
        }
        {
            #pragma unroll
            for (int p = 0; p < 2; p++) {
                int kk = lb_k + p * 8;
                float4 v = *(const float4*)(W + (kt * BK + kk) * Hd + lb_c4);
                uint32_t h, l;
                uint4 uh, ul;
                split_tf32(v.x, h, l); uh.x = h; ul.x = l;
                split_tf32(v.y, h, l); uh.y = h; ul.y = l;
                split_tf32(v.z, h, l); uh.z = h; ul.z = l;
                split_tf32(v.w, h, l); uh.w = h; ul.w = l;
                *(uint4*)&Bh[kk][lb_c4] = uh;
                *(uint4*)&Bl[kk][lb_c4] = ul;
            }
        }
        __syncthreads();
        #pragma unroll
        for (int ks = 0; ks < 2; ks++) {
            int kk0 = ks * 8;
            uint32_t ah[2][4], al[2][4];
            #pragma unroll
            for (int mi = 0; mi < 2; mi++) {
                int m0 = m_base + mi * 16 + grp;
                ah[mi][0] = Ah[m0][kk0 + tig];
                ah[mi][1] = Ah[m0 + 8][kk0 + tig];
                ah[mi][2] = Ah[m0][kk0 + tig + 4];
                ah[mi][3] = Ah[m0 + 8][kk0 + tig + 4];
                al[mi][0] = Al[m0][kk0 + tig];
                al[mi][1] = Al[m0 + 8][kk0 + tig];
                al[mi][2] = Al[m0][kk0 + tig + 4];
                al[mi][3] = Al[m0 + 8][kk0 + tig + 4];
            }
            #pragma unroll
            for (int ni = 0; ni < 8; ni++) {
                int nc = n_base + ni * 8 + grp;
                uint32_t bh[2], bl[2];
                bh[0] = Bh[kk0 + tig][nc];
                bh[1] = Bh[kk0 + tig + 4][nc];
                bl[0] = Bl[kk0 + tig][nc];
                bl[1] = Bl[kk0 + tig + 4][nc];
                #pragma unroll
                for (int mi = 0; mi < 2; mi++) {
                    mma_tf32(c[mi][ni], al[mi], bh);
                    mma_tf32(c[mi][ni], ah[mi], bl);
                    mma_tf32(c[mi][ni], ah[mi], bh);
                }
            }
        }
        __syncthreads();
    }

    // ---- bias + activation (zero invalid rows) ----
    #pragma unroll
    for (int mi = 0; mi < 2; mi++) {
        #pragma unroll
        for (int half = 0; half < 2; half++) {
            int row = row0 + m_base + mi * 16 + grp + half * 8;
            bool valid = row < Nn;
            #pragma unroll
            for (int ni = 0; ni < 8; ni++) {
                #pragma unroll
                for (int par = 0; par < 2; par++) {
                    int q = half * 2 + par;
                    int col = n_base + ni * 8 + tig * 2 + par;
                    float f = c[mi][ni][q] + __ldg(bias + col);
                    if (mode == 1)      f = (f > 0.f) ? f : 0.01f * f;
                    else if (mode == 2) f = fmaxf(f, 0.f);
                    c[mi][ni][q] = valid ? f : 0.f;
                }
            }
        }
    }

    float rscale[2][2] = {{1.f,1.f},{1.f,1.f}};

    if (mode != 0) {
        // ---- fused BN stats partials (deterministic) ----
        float ls[8][2], ls2[8][2];
        #pragma unroll
        for (int ni = 0; ni < 8; ni++)
            #pragma unroll
            for (int par = 0; par < 2; par++) {
                float s = 0.f, s2 = 0.f;
                #pragma unroll
                for (int mi = 0; mi < 2; mi++)
                    #pragma unroll
                    for (int half = 0; half < 2; half++) {
                        float f = c[mi][ni][half * 2 + par];
                        s += f; s2 += f * f;
                    }
                ls[ni][par] = s; ls2[ni][par] = s2;
            }
        #pragma unroll
        for (int off = 4; off < 32; off <<= 1) {
            #pragma unroll
            for (int ni = 0; ni < 8; ni++)
                #pragma unroll
                for (int par = 0; par < 2; par++) {
                    ls [ni][par] += __shfl_xor_sync(0xffffffffu, ls [ni][par], off);
                    ls2[ni][par] += __shfl_xor_sync(0xffffffffu, ls2[ni][par], off);
                }
        }
        if (lane < 4) {
            #pragma unroll
            for (int ni = 0; ni < 8; ni++)
                #pragma unroll
                for (int par = 0; par < 2; par++) {
                    sred [wid][ni * 8 + tig * 2 + par] = ls [ni][par];
                    sred2[wid][ni * 8 + tig * 2 + par] = ls2[ni][par];
                }
        }
        __syncthreads();
        if (tid < Hd) {
            int hf = tid >> 6, cl = tid & 63;
            float s = 0.f, s2 = 0.f;
            #pragma unroll
            for (int j = 0; j < 4; j++) {
                s  += sred [2 * j + hf][cl];
                s2 += sred2[2 * j + hf][cl];
            }
            g_part [blockIdx.x * Hd + tid] = s;
            g_part2[blockIdx.x * Hd + tid] = s2;
        }
    } else {
        // ---- fused row L2 normalize ----
        #pragma unroll
        for (int mi = 0; mi < 2; mi++)
            #pragma unroll
            for (int half = 0; half < 2; half++) {
                float rsq = 0.f;
                #pragma unroll
                for (int ni = 0; ni < 8; ni++) {
                    float f0 = c[mi][ni][half * 2 + 0];
                    float f1 = c[mi][ni][half * 2 + 1];
                    rsq += f0 * f0 + f1 * f1;
                }
                rsq += __shfl_xor_sync(0xffffffffu, rsq, 1);
                rsq += __shfl_xor_sync(0xffffffffu, rsq, 2);
                if (tig == 0)
                    rows2[wid & 1][m_base + mi * 16 + grp + half * 8] = rsq;
            }
        __syncthreads();
        #pragma unroll
        for (int mi = 0; mi < 2; mi++)
            #pragma unroll
            for (int half = 0; half < 2; half++) {
                int rl = m_base + mi * 16 + grp + half * 8;
                float tot = rows2[0][rl] + rows2[1][rl];
                rscale[mi][half] = 1.f / fmaxf(sqrtf(tot), 1e-12f);
            }
    }

    // ---- store (fp32 + optional fp16 mirror) ----
    #pragma unroll
    for (int mi = 0; mi < 2; mi++) {
        #pragma unroll
        for (int half = 0; half < 2; half++) {
            int row = row0 + m_base + mi * 16 + grp + half * 8;
            if (row < Nn) {
                float rs = rscale[mi][half];
                #pragma unroll
                for (int ni = 0; ni < 8; ni++) {
                    int col = n_base + ni * 8 + tig * 2;
                    float f0 = c[mi][ni][half * 2 + 0] * rs;
                    float f1 = c[mi][ni][half * 2 + 1] * rs;
                    *(float2*)(out + row * Hd + col) = make_float2(f0, f1);
                    if (out16)
                        *(__half2*)(out16 + row * Hd + col) = __floats2half2_rn(f0, f1);
                }
            }
        }
    }
}

// ---------------- BN finalize ----------------
__global__ void k_bnfin(const float* __restrict__ gamma, const float* __restrict__ beta,
                        int nb) {
    int c = threadIdx.x;
    float s = 0.f, s2 = 0.f;
    for (int b = 0; b < nb; b++) { s += g_part[b * Hd + c]; s2 += g_part2[b * Hd + c]; }
    float m   = s / (float)Nn;
    float var = s2 / (float)Nn - m * m;
    float inv = rsqrtf(var + 1e-5f);
    float sc  = gamma[c] * inv;
    g_scale[c] = sc;
    g_shift[c] = beta[c] - m * sc;
}

// ---------------- host ----------------
extern "C" void kernel_launch(void* const* d_in, const int* in_sizes, int n_in,
                              void* d_out, int out_size) {
    const float* x  = (const float*)d_in[0];
    const int*   ei = (const int*)d_in[1];   // int32 (JAX x64 disabled)
    const float* W1 = (const float*)d_in[2];  const float* b1 = (const float*)d_in[3];
    const float* W2 = (const float*)d_in[4];  const float* b2 = (const float*)d_in[5];
    const float* W3 = (const float*)d_in[6];  const float* b3 = (const float*)d_in[7];
    const float* W4 = (const float*)d_in[8];  const float* b4 = (const float*)d_in[9];
    const float* g1 = (const float*)d_in[10]; const float* be1 = (const float*)d_in[11];
    const float* g2 = (const float*)d_in[12]; const float* be2 = (const float*)d_in[13];
    const float* g3 = (const float*)d_in[14]; const float* be3 = (const float*)d_in[15];

    float *p_t1, *p_t2, *p_t3, *p_out, *p_s1, *p_s2, *p_s3, *p_sc, *p_sh;
    __half *p_h16, *p_u16, *p_v16;
    cudaGetSymbolAddress((void**)&p_t1,  g_t1);
    cudaGetSymbolAddress((void**)&p_t2,  g_t2);
    cudaGetSymbolAddress((void**)&p_t3,  g_t3);
    cudaGetSymbolAddress((void**)&p_out, g_out);
    cudaGetSymbolAddress((void**)&p_s1,  g_s1);
    cudaGetSymbolAddress((void**)&p_s2,  g_s2);
    cudaGetSymbolAddress((void**)&p_s3,  g_s3);
    cudaGetSymbolAddress((void**)&p_sc,  g_scale);
    cudaGetSymbolAddress((void**)&p_sh,  g_shift);
    cudaGetSymbolAddress((void**)&p_h16, g_h16);
    cudaGetSymbolAddress((void**)&p_u16, g_u16);
    cudaGetSymbolAddress((void**)&p_v16, g_v16);

    const int TB = 256;
    // graph build
    k_init <<<(Nn + TB - 1) / TB, TB>>>();
    k_count<<<(Ee + TB - 1) / TB, TB>>>(ei);
    k_dinv <<<(Nn + TB - 1) / TB, TB>>>();
    k_scan1<<<SCB, 1024>>>();
    k_scan2<<<1, 64>>>();
    k_scan3<<<(Nn + TB - 1) / TB, TB>>>();
    k_fill <<<(Ee + TB - 1) / TB, TB>>>(ei);

    int gP128 = (Nn + 3) / 4;
    int gGemm = (Nn + BM - 1) / BM;      // 391
    int g12   = (Nn + 31) / 32;          // 1563

    // layer 1 (F=3)
    k_prop3<<<(Nn + TB - 1) / TB, TB>>>(x, nullptr, p_s1);
    k_prop3<<<(Nn + TB - 1) / TB, TB>>>(p_s1, x, p_s2);
    k_prop3<<<(Nn + TB - 1) / TB, TB>>>(p_s2, p_s1, p_s3);
    k_gemm12<<<g12, Hd>>>(x, p_s1, p_s2, p_s3, W1, b1, p_out, p_h16);
    k_bnfin<<<1, Hd>>>(g1, be1, g12);

    // layer 2
    k_prop128<<<gP128, 128>>>(p_h16, nullptr, p_t1, p_u16, p_sc, p_sh, 1);
    k_prop128<<<gP128, 128>>>(p_u16, p_out, p_t2, p_v16, p_sc, p_sh, 2);
    k_prop128<<<gP128, 128>>>(p_v16, p_t1, p_t3, nullptr, nullptr, nullptr, 0);
    k_gemm_mma<<<gGemm, 256>>>(p_out, p_t1, p_t2, p_t3, W2, b2, p_out, p_h16, p_sc, p_sh, 1);
    k_bnfin<<<1, Hd>>>(g2, be2, gGemm);

    // layer 3
    k_prop128<<<gP128, 128>>>(p_h16, nullptr, p_t1, p_u16, p_sc, p_sh, 1);
    k_prop128<<<gP128, 128>>>(p_u16, p_out, p_t2, p_v16, p_sc, p_sh, 2);
    k_prop128<<<gP128, 128>>>(p_v16, p_t1, p_t3, nullptr, nullptr, nullptr, 0);
    k_gemm_mma<<<gGemm, 256>>>(p_out, p_t1, p_t2, p_t3, W3, b3, p_out, p_h16, p_sc, p_sh, 2);
    k_bnfin<<<1, Hd>>>(g3, be3, gGemm);

    // layer 4: props + GEMM with fused row-normalize, straight to d_out
    k_prop128<<<gP128, 128>>>(p_h16, nullptr, p_t1, p_u16, p_sc, p_sh, 1);
    k_prop128<<<gP128, 128>>>(p_u16, p_out, p_t2, p_v16, p_sc, p_sh, 2);
    k_prop128<<<gP128, 128>>>(p_v16, p_t1, p_t3, nullptr, nullptr, nullptr, 0);
    k_gemm_mma<<<gGemm, 256>>>(p_out, p_t1, p_t2, p_t3, W4, b4, (float*)d_out,
                               nullptr, p_sc, p_sh, 0);
}

// round 7
// speedup vs baseline: 1.1090x; 1.1090x over previous
#include <cuda_runtime.h>
#include <cuda_bf16.h>
#include <cuda_fp16.h>
#include <cstdint>

#define Nn 50000
#define Ee 800000
#define Hd 128
#define SCB 49       // scan blocks (ceil(Nn/1024))
#define PMAX 1600    // max stats-partial blocks (gemm12 uses 1563)

// ---------------- scratch ----------------
__device__ int   g_deg[Nn];
__device__ int   g_cnt[Nn];
__device__ int   g_rowptr[Nn + 1];
__device__ int   g_tmpptr[Nn];
__device__ float g_dinv[Nn];
__device__ int2  g_epk[Ee];          // (src, weight-bits)
__device__ int   g_bsum[SCB];
__device__ int   g_boff[SCB];

__device__ __align__(256) float g_t1[Nn * Hd];
__device__ __align__(256) float g_t2[Nn * Hd];
__device__ __align__(256) float g_t3[Nn * Hd];
__device__ __align__(256) float g_out[Nn * Hd];

// fp16 gather mirrors (h, t1, t2 are the only gathered tensors)
__device__ __align__(256) __half g_h16[Nn * Hd];
__device__ __align__(256) __half g_u16[Nn * Hd];
__device__ __align__(256) __half g_v16[Nn * Hd];

__device__ float g_s1[Nn * 3];
__device__ float g_s2[Nn * 3];
__device__ float g_s3[Nn * 3];

__device__ float g_part [PMAX * Hd];
__device__ float g_part2[PMAX * Hd];
__device__ float g_scale[Hd];
__device__ float g_shift[Hd];

// ---------------- helpers ----------------
__device__ __forceinline__ uint32_t f2tf32(float f) {
    uint32_t u;
    asm("cvt.rna.tf32.f32 %0, %1;" : "=r"(u) : "f"(f));
    return u;
}
__device__ __forceinline__ void split_tf32(float f, uint32_t& hi, uint32_t& lo) {
    hi = f2tf32(f);
    lo = f2tf32(f - __uint_as_float(hi));
}
__device__ __forceinline__ void mma_tf32(float* c, const uint32_t* a, const uint32_t* b) {
    asm volatile(
        "mma.sync.aligned.m16n8k8.row.col.f32.tf32.tf32.f32 "
        "{%0,%1,%2,%3}, {%4,%5,%6,%7}, {%8,%9}, {%0,%1,%2,%3};"
        : "+f"(c[0]), "+f"(c[1]), "+f"(c[2]), "+f"(c[3])
        : "r"(a[0]), "r"(a[1]), "r"(a[2]), "r"(a[3]), "r"(b[0]), "r"(b[1]));
}

// ---------------- graph build ----------------
__global__ void k_init() {
    int i = blockIdx.x * blockDim.x + threadIdx.x;
    if (i < Nn) { g_deg[i] = 0; g_cnt[i] = 0; }
}

__global__ void k_count(const int* __restrict__ ei) {
    int e = blockIdx.x * blockDim.x + threadIdx.x;
    if (e < Ee) {
        int s = ei[e];
        int d = ei[e + Ee];
        if ((unsigned)s < Nn) atomicAdd(&g_deg[s], 1);
        if ((unsigned)d < Nn) atomicAdd(&g_cnt[d], 1);
    }
}

__global__ void k_dinv() {
    int i = blockIdx.x * blockDim.x + threadIdx.x;
    if (i < Nn) {
        int d = g_deg[i];
        g_dinv[i] = (d > 0) ? rsqrtf((float)d) : 0.0f;
    }
}

__global__ void k_scan1() {
    __shared__ int sd[1024];
    int b = blockIdx.x, tid = threadIdx.x;
    int i = b * 1024 + tid;
    int v = (i < Nn) ? g_cnt[i] : 0;
    sd[tid] = v;
    __syncthreads();
    for (int off = 1; off < 1024; off <<= 1) {
        int t = (tid >= off) ? sd[tid - off] : 0;
        __syncthreads();
        sd[tid] += t;
        __syncthreads();
    }
    if (i < Nn) g_rowptr[i + 1] = sd[tid];
    if (tid == 1023) g_bsum[b] = sd[1023];
}
__global__ void k_scan2() {
    if (threadIdx.x == 0) {
        int acc = 0;
        for (int b = 0; b < SCB; b++) { g_boff[b] = acc; acc += g_bsum[b]; }
        g_rowptr[0] = 0;
    }
}
__global__ void k_scan3() {
    int i = blockIdx.x * blockDim.x + threadIdx.x;
    if (i < Nn) {
        int r = g_rowptr[i + 1] + g_boff[i >> 10];
        g_rowptr[i + 1] = r;
        g_tmpptr[i] = r - g_cnt[i];
    }
}

__global__ void k_fill(const int* __restrict__ ei) {
    int e = blockIdx.x * blockDim.x + threadIdx.x;
    if (e < Ee) {
        int s = ei[e];
        int d = ei[e + Ee];
        if ((unsigned)s >= Nn || (unsigned)d >= Nn) return;
        int p = atomicAdd(&g_tmpptr[d], 1);
        float w = -g_dinv[s] * g_dinv[d];
        g_epk[p] = make_int2(s, __float_as_int(w));
    }
}

// ---------------- propagation ----------------
__global__ void k_prop3(const float* __restrict__ hin,
                        const float* __restrict__ sub,
                        float* __restrict__ out) {
    int v = blockIdx.x * blockDim.x + threadIdx.x;
    if (v >= Nn) return;
    float a0 = 0.f, a1 = 0.f, a2 = 0.f;
    int b = g_rowptr[v], en = g_rowptr[v + 1];
    for (int i = b; i < en; i++) {
        int2 e = g_epk[i];
        float w = __int_as_float(e.y);
        const float* hp = hin + e.x * 3;
        a0 += w * hp[0]; a1 += w * hp[1]; a2 += w * hp[2];
    }
    float* o = out + v * 3;
    if (sub) {
        const float* sv = sub + v * 3;
        o[0] = 2.f * a0 - sv[0]; o[1] = 2.f * a1 - sv[1]; o[2] = 2.f * a2 - sv[2];
    } else {
        o[0] = a0; o[1] = a1; o[2] = a2;
    }
}

// warp per node; gathers fp16 mirror, accumulates fp32.
// mode: 1 = BN analytic on gathered h (no sub), 2 = BN applied to sub,
//       0 = plain 2*acc - sub (or plain acc if sub==null).
__global__ void k_prop128(const __half* __restrict__ hin16,
                          const float* __restrict__ sub,
                          float* __restrict__ out,
                          __half* __restrict__ out16,
                          const float* __restrict__ sc,
                          const float* __restrict__ sh,
                          int mode) {
    int v = blockIdx.x * 4 + (threadIdx.x >> 5);
    if (v >= Nn) return;
    int lane = threadIdx.x & 31;
    float4 sc4, sh4;
    if (mode) {
        sc4 = ((const float4*)sc)[lane];
        sh4 = ((const float4*)sh)[lane];
    }
    int b = g_rowptr[v], en = g_rowptr[v + 1];
    float4 acc = make_float4(0.f, 0.f, 0.f, 0.f);
    float wsum = 0.f;
    int i = b;
    for (; i + 1 < en; i += 2) {
        int2 e0 = g_epk[i];
        int2 e1 = g_epk[i + 1];
        float w0 = __int_as_float(e0.y);
        float w1 = __int_as_float(e1.y);
        uint2 p0 = *(const uint2*)(hin16 + e0.x * Hd + lane * 4);
        uint2 p1 = *(const uint2*)(hin16 + e1.x * Hd + lane * 4);
        float2 a01 = __half22float2(*(__half2*)&p0.x);
        float2 a23 = __half22float2(*(__half2*)&p0.y);
        float2 b01 = __half22float2(*(__half2*)&p1.x);
        float2 b23 = __half22float2(*(__half2*)&p1.y);
        acc.x += w0 * a01.x + w1 * b01.x;
        acc.y += w0 * a01.y + w1 * b01.y;
        acc.z += w0 * a23.x + w1 * b23.x;
        acc.w += w0 * a23.y + w1 * b23.y;
        wsum += w0 + w1;
    }
    if (i < en) {
        int2 e = g_epk[i];
        float w = __int_as_float(e.y);
        uint2 p0 = *(const uint2*)(hin16 + e.x * Hd + lane * 4);
        float2 a01 = __half22float2(*(__half2*)&p0.x);
        float2 a23 = __half22float2(*(__half2*)&p0.y);
        acc.x += w * a01.x; acc.y += w * a01.y;
        acc.z += w * a23.x; acc.w += w * a23.y;
        wsum += w;
    }
    float4 r;
    if (mode == 1) {
        r.x = sc4.x * acc.x + sh4.x * wsum;
        r.y = sc4.y * acc.y + sh4.y * wsum;
        r.z = sc4.z * acc.z + sh4.z * wsum;
        r.w = sc4.w * acc.w + sh4.w * wsum;
    } else if (mode == 2) {
        float4 sv = *(const float4*)(sub + v * Hd + lane * 4);
        r.x = 2.f * acc.x - (sc4.x * sv.x + sh4.x);
        r.y = 2.f * acc.y - (sc4.y * sv.y + sh4.y);
        r.z = 2.f * acc.z - (sc4.z * sv.z + sh4.z);
        r.w = 2.f * acc.w - (sc4.w * sv.w + sh4.w);
    } else if (sub) {
        float4 sv = *(const float4*)(sub + v * Hd + lane * 4);
        r.x = 2.f * acc.x - sv.x; r.y = 2.f * acc.y - sv.y;
        r.z = 2.f * acc.z - sv.z; r.w = 2.f * acc.w - sv.w;
    } else {
        r = acc;
    }
    *(float4*)(out + v * Hd + lane * 4) = r;
    if (out16) {
        uint2 pk;
        *(__half2*)&pk.x = __floats2half2_rn(r.x, r.y);
        *(__half2*)&pk.y = __floats2half2_rn(r.z, r.w);
        *(uint2*)(out16 + v * Hd + lane * 4) = pk;
    }
}

// ---------------- layer 1 GEMM: K=12 (+ fused stats + fp16 mirror) ----------
__global__ void k_gemm12(const float* __restrict__ x,  const float* __restrict__ t1,
                         const float* __restrict__ t2, const float* __restrict__ t3,
                         const float* __restrict__ W,  const float* __restrict__ bias,
                         float* __restrict__ out, __half* __restrict__ out16) {
    __shared__ float sW[12 * Hd];
    int c = threadIdx.x;
    #pragma unroll
    for (int j = 0; j < 12; j++) sW[j * Hd + c] = W[j * Hd + c];
    __syncthreads();
    const int RPB = 32;
    int v0 = blockIdx.x * RPB;
    float bv = bias[c];
    float s = 0.f, s2 = 0.f;
    for (int r = 0; r < RPB; r++) {
        int v = v0 + r;
        if (v >= Nn) break;
        float a[12];
        #pragma unroll
        for (int f = 0; f < 3; f++) {
            a[f]     = x [v * 3 + f];
            a[3 + f] = t1[v * 3 + f];
            a[6 + f] = t2[v * 3 + f];
            a[9 + f] = t3[v * 3 + f];
        }
        float acc = bv;
        #pragma unroll
        for (int j = 0; j < 12; j++) acc += a[j] * sW[j * Hd + c];
        acc = (acc > 0.f) ? acc : 0.01f * acc;   // leaky relu
        out[v * Hd + c] = acc;
        out16[v * Hd + c] = __float2half(acc);
        s += acc; s2 += acc * acc;
    }
    g_part [blockIdx.x * Hd + c] = s;
    g_part2[blockIdx.x * Hd + c] = s2;
}

// ---------------- split-A 2xTF32 tensor-core GEMM + fused epilogues --------
// mode: 1 = leaky+stats, 2 = relu+stats, 0 = no-act + row-L2-normalize
#define BM 128
#define BK 16
#define ASTR (BK + 4)     // 20
#define BSTR (Hd + 8)     // 136

__global__ __launch_bounds__(256)
void k_gemm_mma(const float* __restrict__ A0, const float* __restrict__ A1,
                const float* __restrict__ A2, const float* __restrict__ A3,
                const float* __restrict__ W,  const float* __restrict__ bias,
                float* __restrict__ out, __half* __restrict__ out16,
                const float* __restrict__ scA, const float* __restrict__ shA,
                int mode) {
    __shared__ uint32_t Ah[BM][ASTR];
    __shared__ uint32_t Al[BM][ASTR];
    __shared__ uint32_t Bs[BK][BSTR];
    __shared__ float sred [8][64];
    __shared__ float sred2[8][64];
    __shared__ float rows2[2][BM];
    const float* Abuf[4] = {A0, A1, A2, A3};

    int tid = threadIdx.x;
    int wid = tid >> 5;
    int lane = tid & 31;
    int grp = lane >> 2;       // 0..7
    int tig = lane & 3;        // 0..3
    int m_base = (wid >> 1) * 32;
    int n_base = (wid & 1) * 64;
    int row0 = blockIdx.x * BM;

    float c[2][8][4];
    #pragma unroll
    for (int mi = 0; mi < 2; mi++)
        #pragma unroll
        for (int ni = 0; ni < 8; ni++)
            #pragma unroll
            for (int q = 0; q < 4; q++) c[mi][ni][q] = 0.f;

    int la_r  = tid >> 1;
    int la_c4 = (tid & 1) * 8;
    int lb_k  = tid >> 5;
    int lb_c4 = (tid & 31) * 4;

    for (int kt = 0; kt < 32; kt++) {
        const float* A = Abuf[kt >> 3];
        int cb = (kt & 7) * BK;
        {
            int gr = row0 + la_r;
            float4 v0 = make_float4(0.f,0.f,0.f,0.f), v1 = v0;
            if (gr < Nn) {
                const float4* src = (const float4*)(A + gr * Hd + cb + la_c4);
                v0 = src[0]; v1 = src[1];
            }
            if (scA && (kt >> 3) == 0) {   // A0 = BN(h) applied inline
                float4 s0 = *(const float4*)(scA + cb + la_c4);
                float4 s1 = *(const float4*)(scA + cb + la_c4 + 4);
                float4 h0 = *(const float4*)(shA + cb + la_c4);
                float4 h1 = *(const float4*)(shA + cb + la_c4 + 4);
                v0.x = v0.x * s0.x + h0.x; v0.y = v0.y * s0.y + h0.y;
                v0.z = v0.z * s0.z + h0.z; v0.w = v0.w * s0.w + h0.w;
                v1.x = v1.x * s1.x + h1.x; v1.y = v1.y * s1.y + h1.y;
                v1.z = v1.z * s1.z + h1.z; v1.w = v1.w * s1.w + h1.w;
                if (gr >= Nn) { v0 = make_float4(0,0,0,0); v1 = v0; }
            }
            uint32_t h, l;
            uint4 uh0, ul0, uh1, ul1;
            split_tf32(v0.x, h, l); uh0.x = h; ul0.x = l;
            split_tf32(v0.y, h, l); uh0.y = h; ul0.y = l;
            split_tf32(v0.z, h, l); uh0.z = h; ul0.z = l;
            split_tf32(v0.w, h, l); uh0.w = h; ul0.w = l;
            split_tf32(v1.x, h, l); uh1.x = h; ul1.x = l;
            split_tf32(v1.y, h, l); uh1.y = h; ul1.y = l;
            split_tf32(v1.z, h, l); uh1.z = h; ul1.z = l;
            split_tf32(v1.w, h, l); uh1.w = h; ul1.w = l;
            *(uint4*)&Ah[la_r][la_c4]     = uh0;
            *(uint4*)&Ah[la_r][la_c4 + 4] = uh1;
            *(uint4*)&Al[la_r][la_c4]     = ul0;
            *(uint4*)&Al[la_r][la_c4 + 4] = ul1;
        }
        {
            #pragma unroll
            for (int p = 0; p < 2; p++) {
                int kk = lb_k + p * 8;
                float4 v = *(const float4*)(W + (kt * BK + kk) * Hd + lb_c4);
                uint4 u = make_uint4(f2tf32(v.x), f2tf32(v.y), f2tf32(v.z), f2tf32(v.w));
                *(uint4*)&Bs[kk][lb_c4] = u;
            }
        }
        __syncthreads();
        #pragma unroll
        for (int ks = 0; ks < 2; ks++) {
            int kk0 = ks * 8;
            uint32_t ah[2][4], al[2][4];
            #pragma unroll
            for (int mi = 0; mi < 2; mi++) {
                int m0 = m_base + mi * 16 + grp;
                ah[mi][0] = Ah[m0][kk0 + tig];
                ah[mi][1] = Ah[m0 + 8][kk0 + tig];
                ah[mi][2] = Ah[m0][kk0 + tig + 4];
                ah[mi][3] = Ah[m0 + 8][kk0 + tig + 4];
                al[mi][0] = Al[m0][kk0 + tig];
                al[mi][1] = Al[m0 + 8][kk0 + tig];
                al[mi][2] = Al[m0][kk0 + tig + 4];
                al[mi][3] = Al[m0 + 8][kk0 + tig + 4];
            }
            #pragma unroll
            for (int ni = 0; ni < 8; ni++) {
                int nc = n_base + ni * 8 + grp;
                uint32_t b[2];
                b[0] = Bs[kk0 + tig][nc];
                b[1] = Bs[kk0 + tig + 4][nc];
                #pragma unroll
                for (int mi = 0; mi < 2; mi++) {
                    mma_tf32(c[mi][ni], al[mi], b);
                    mma_tf32(c[mi][ni], ah[mi], b);
                }
            }
        }
        __syncthreads();
    }

    // ---- bias + activation (zero invalid rows) ----
    #pragma unroll
    for (int mi = 0; mi < 2; mi++) {
        #pragma unroll
        for (int half = 0; half < 2; half++) {
            int row = row0 + m_base + mi * 16 + grp + half * 8;
            bool valid = row < Nn;
            #pragma unroll
            for (int ni = 0; ni < 8; ni++) {
                #pragma unroll
                for (int par = 0; par < 2; par++) {
                    int q = half * 2 + par;
                    int col = n_base + ni * 8 + tig * 2 + par;
                    float f = c[mi][ni][q] + __ldg(bias + col);
                    if (mode == 1)      f = (f > 0.f) ? f : 0.01f * f;
                    else if (mode == 2) f = fmaxf(f, 0.f);
                    c[mi][ni][q] = valid ? f : 0.f;
                }
            }
        }
    }

    float rscale[2][2] = {{1.f,1.f},{1.f,1.f}};

    if (mode != 0) {
        // ---- fused BN stats partials (deterministic) ----
        float ls[8][2], ls2[8][2];
        #pragma unroll
        for (int ni = 0; ni < 8; ni++)
            #pragma unroll
            for (int par = 0; par < 2; par++) {
                float s = 0.f, s2 = 0.f;
                #pragma unroll
                for (int mi = 0; mi < 2; mi++)
                    #pragma unroll
                    for (int half = 0; half < 2; half++) {
                        float f = c[mi][ni][half * 2 + par];
                        s += f; s2 += f * f;
                    }
                ls[ni][par] = s; ls2[ni][par] = s2;
            }
        #pragma unroll
        for (int off = 4; off < 32; off <<= 1) {
            #pragma unroll
            for (int ni = 0; ni < 8; ni++)
                #pragma unroll
                for (int par = 0; par < 2; par++) {
                    ls [ni][par] += __shfl_xor_sync(0xffffffffu, ls [ni][par], off);
                    ls2[ni][par] += __shfl_xor_sync(0xffffffffu, ls2[ni][par], off);
                }
        }
        if (lane < 4) {
            #pragma unroll
            for (int ni = 0; ni < 8; ni++)
                #pragma unroll
                for (int par = 0; par < 2; par++) {
                    sred [wid][ni * 8 + tig * 2 + par] = ls [ni][par];
                    sred2[wid][ni * 8 + tig * 2 + par] = ls2[ni][par];
                }
        }
        __syncthreads();
        if (tid < Hd) {
            int hf = tid >> 6, cl = tid & 63;
            float s = 0.f, s2 = 0.f;
            #pragma unroll
            for (int j = 0; j < 4; j++) {
                s  += sred [2 * j + hf][cl];
                s2 += sred2[2 * j + hf][cl];
            }
            g_part [blockIdx.x * Hd + tid] = s;
            g_part2[blockIdx.x * Hd + tid] = s2;
        }
    } else {
        // ---- fused row L2 normalize ----
        #pragma unroll
        for (int mi = 0; mi < 2; mi++)
            #pragma unroll
            for (int half = 0; half < 2; half++) {
                float rsq = 0.f;
                #pragma unroll
                for (int ni = 0; ni < 8; ni++) {
                    float f0 = c[mi][ni][half * 2 + 0];
                    float f1 = c[mi][ni][half * 2 + 1];
                    rsq += f0 * f0 + f1 * f1;
                }
                rsq += __shfl_xor_sync(0xffffffffu, rsq, 1);
                rsq += __shfl_xor_sync(0xffffffffu, rsq, 2);
                if (tig == 0)
                    rows2[wid & 1][m_base + mi * 16 + grp + half * 8] = rsq;
            }
        __syncthreads();
        #pragma unroll
        for (int mi = 0; mi < 2; mi++)
            #pragma unroll
            for (int half = 0; half < 2; half++) {
                int rl = m_base + mi * 16 + grp + half * 8;
                float tot = rows2[0][rl] + rows2[1][rl];
                rscale[mi][half] = 1.f / fmaxf(sqrtf(tot), 1e-12f);
            }
    }

    // ---- store (fp32 + optional fp16 mirror) ----
    #pragma unroll
    for (int mi = 0; mi < 2; mi++) {
        #pragma unroll
        for (int half = 0; half < 2; half++) {
            int row = row0 + m_base + mi * 16 + grp + half * 8;
            if (row < Nn) {
                float rs = rscale[mi][half];
                #pragma unroll
                for (int ni = 0; ni < 8; ni++) {
                    int col = n_base + ni * 8 + tig * 2;
                    float f0 = c[mi][ni][half * 2 + 0] * rs;
                    float f1 = c[mi][ni][half * 2 + 1] * rs;
                    *(float2*)(out + row * Hd + col) = make_float2(f0, f1);
                    if (out16)
                        *(__half2*)(out16 + row * Hd + col) = __floats2half2_rn(f0, f1);
                }
            }
        }
    }
}

// ---------------- BN finalize ----------------
__global__ void k_bnfin(const float* __restrict__ gamma, const float* __restrict__ beta,
                        int nb) {
    int c = threadIdx.x;
    float s = 0.f, s2 = 0.f;
    for (int b = 0; b < nb; b++) { s += g_part[b * Hd + c]; s2 += g_part2[b * Hd + c]; }
    float m   = s / (float)Nn;
    float var = s2 / (float)Nn - m * m;
    float inv = rsqrtf(var + 1e-5f);
    float sc  = gamma[c] * inv;
    g_scale[c] = sc;
    g_shift[c] = beta[c] - m * sc;
}

// ---------------- host ----------------
extern "C" void kernel_launch(void* const* d_in, const int* in_sizes, int n_in,
                              void* d_out, int out_size) {
    const float* x  = (const float*)d_in[0];
    const int*   ei = (const int*)d_in[1];   // int32 (JAX x64 disabled)
    const float* W1 = (const float*)d_in[2];  const float* b1 = (const float*)d_in[3];
    const float* W2 = (const float*)d_in[4];  const float* b2 = (const float*)d_in[5];
    const float* W3 = (const float*)d_in[6];  const float* b3 = (const float*)d_in[7];
    const float* W4 = (const float*)d_in[8];  const float* b4 = (const float*)d_in[9];
    const float* g1 = (const float*)d_in[10]; const float* be1 = (const float*)d_in[11];
    const float* g2 = (const float*)d_in[12]; const float* be2 = (const float*)d_in[13];
    const float* g3 = (const float*)d_in[14]; const float* be3 = (const float*)d_in[15];

    float *p_t1, *p_t2, *p_t3, *p_out, *p_s1, *p_s2, *p_s3, *p_sc, *p_sh;
    __half *p_h16, *p_u16, *p_v16;
    cudaGetSymbolAddress((void**)&p_t1,  g_t1);
    cudaGetSymbolAddress((void**)&p_t2,  g_t2);
    cudaGetSymbolAddress((void**)&p_t3,  g_t3);
    cudaGetSymbolAddress((void**)&p_out, g_out);
    cudaGetSymbolAddress((void**)&p_s1,  g_s1);
    cudaGetSymbolAddress((void**)&p_s2,  g_s2);
    cudaGetSymbolAddress((void**)&p_s3,  g_s3);
    cudaGetSymbolAddress((void**)&p_sc,  g_scale);
    cudaGetSymbolAddress((void**)&p_sh,  g_shift);
    cudaGetSymbolAddress((void**)&p_h16, g_h16);
    cudaGetSymbolAddress((void**)&p_u16, g_u16);
    cudaGetSymbolAddress((void**)&p_v16, g_v16);

    const int TB = 256;
    // graph build
    k_init <<<(Nn + TB - 1) / TB, TB>>>();
    k_count<<<(Ee + TB - 1) / TB, TB>>>(ei);
    k_dinv <<<(Nn + TB - 1) / TB, TB>>>();
    k_scan1<<<SCB, 1024>>>();
    k_scan2<<<1, 64>>>();
    k_scan3<<<(Nn + TB - 1) / TB, TB>>>();
    k_fill <<<(Ee + TB - 1) / TB, TB>>>(ei);

    int gP128 = (Nn + 3) / 4;
    int gGemm = (Nn + BM - 1) / BM;      // 391
    int g12   = (Nn + 31) / 32;          // 1563

    // layer 1 (F=3)
    k_prop3<<<(Nn + TB - 1) / TB, TB>>>(x, nullptr, p_s1);
    k_prop3<<<(Nn + TB - 1) / TB, TB>>>(p_s1, x, p_s2);
    k_prop3<<<(Nn + TB - 1) / TB, TB>>>(p_s2, p_s1, p_s3);
    k_gemm12<<<g12, Hd>>>(x, p_s1, p_s2, p_s3, W1, b1, p_out, p_h16);
    k_bnfin<<<1, Hd>>>(g1, be1, g12);

    // layer 2
    k_prop128<<<gP128, 128>>>(p_h16, nullptr, p_t1, p_u16, p_sc, p_sh, 1);
    k_prop128<<<gP128, 128>>>(p_u16, p_out, p_t2, p_v16, p_sc, p_sh, 2);
    k_prop128<<<gP128, 128>>>(p_v16, p_t1, p_t3, nullptr, nullptr, nullptr, 0);
    k_gemm_mma<<<gGemm, 256>>>(p_out, p_t1, p_t2, p_t3, W2, b2, p_out, p_h16, p_sc, p_sh, 1);
    k_bnfin<<<1, Hd>>>(g2, be2, gGemm);

    // layer 3
    k_prop128<<<gP128, 128>>>(p_h16, nullptr, p_t1, p_u16, p_sc, p_sh, 1);
    k_prop128<<<gP128, 128>>>(p_u16, p_out, p_t2, p_v16, p_sc, p_sh, 2);
    k_prop128<<<gP128, 128>>>(p_v16, p_t1, p_t3, nullptr, nullptr, nullptr, 0);
    k_gemm_mma<<<gGemm, 256>>>(p_out, p_t1, p_t2, p_t3, W3, b3, p_out, p_h16, p_sc, p_sh, 2);
    k_bnfin<<<1, Hd>>>(g3, be3, gGemm);

    // layer 4: props + GEMM with fused row-normalize, straight to d_out
    k_prop128<<<gP128, 128>>>(p_h16, nullptr, p_t1, p_u16, p_sc, p_sh, 1);
    k_prop128<<<gP128, 128>>>(p_u16, p_out, p_t2, p_v16, p_sc, p_sh, 2);
    k_prop128<<<gP128, 128>>>(p_v16, p_t1, p_t3, nullptr, nullptr, nullptr, 0);
    k_gemm_mma<<<gGemm, 256>>>(p_out, p_t1, p_t2, p_t3, W4, b4, (float*)d_out,
                               nullptr, p_sc, p_sh, 0);
}

// round 8
// speedup vs baseline: 1.2286x; 1.1079x over previous
#include <cuda_runtime.h>
#include <cuda_bf16.h>
#include <cstdint>

#define Nn 50000
#define Ee 800000
#define Hd 128
#define SCB 49       // scan blocks (ceil(Nn/1024))
#define PMAX 1600    // max stats-partial blocks (gemm12 uses 1563)

// ---------------- scratch ----------------
__device__ int   g_deg[Nn];
__device__ int   g_cnt[Nn];
__device__ int   g_rowptr[Nn + 1];
__device__ int   g_tmpptr[Nn];
__device__ float g_dinv[Nn];
__device__ int2  g_epk[Ee];          // (src, weight-bits)
__device__ int   g_bsum[SCB];
__device__ int   g_boff[SCB];

__device__ __align__(256) float g_t1[Nn * Hd];
__device__ __align__(256) float g_t2[Nn * Hd];
__device__ __align__(256) float g_t3[Nn * Hd];
__device__ __align__(256) float g_out[Nn * Hd];

__device__ float g_s1[Nn * 3];
__device__ float g_s2[Nn * 3];
__device__ float g_s3[Nn * 3];

__device__ float g_part [PMAX * Hd];
__device__ float g_part2[PMAX * Hd];
__device__ float g_scale[Hd];
__device__ float g_shift[Hd];

// ---------------- helpers ----------------
__device__ __forceinline__ uint32_t f2tf32(float f) {
    uint32_t u;
    asm("cvt.rna.tf32.f32 %0, %1;" : "=r"(u) : "f"(f));
    return u;
}
__device__ __forceinline__ void mma_tf32(float* c, const uint32_t* a, const uint32_t* b) {
    asm volatile(
        "mma.sync.aligned.m16n8k8.row.col.f32.tf32.tf32.f32 "
        "{%0,%1,%2,%3}, {%4,%5,%6,%7}, {%8,%9}, {%0,%1,%2,%3};"
        : "+f"(c[0]), "+f"(c[1]), "+f"(c[2]), "+f"(c[3])
        : "r"(a[0]), "r"(a[1]), "r"(a[2]), "r"(a[3]), "r"(b[0]), "r"(b[1]));
}

// ---------------- graph build ----------------
__global__ void k_init() {
    int i = blockIdx.x * blockDim.x + threadIdx.x;
    if (i < Nn) { g_deg[i] = 0; g_cnt[i] = 0; }
}

__global__ void k_count(const int* __restrict__ ei) {
    int e = blockIdx.x * blockDim.x + threadIdx.x;
    if (e < Ee) {
        int s = ei[e];
        int d = ei[e + Ee];
        if ((unsigned)s < Nn) atomicAdd(&g_deg[s], 1);
        if ((unsigned)d < Nn) atomicAdd(&g_cnt[d], 1);
    }
}

__global__ void k_dinv() {
    int i = blockIdx.x * blockDim.x + threadIdx.x;
    if (i < Nn) {
        int d = g_deg[i];
        g_dinv[i] = (d > 0) ? rsqrtf((float)d) : 0.0f;
    }
}

__global__ void k_scan1() {
    __shared__ int sd[1024];
    int b = blockIdx.x, tid = threadIdx.x;
    int i = b * 1024 + tid;
    int v = (i < Nn) ? g_cnt[i] : 0;
    sd[tid] = v;
    __syncthreads();
    for (int off = 1; off < 1024; off <<= 1) {
        int t = (tid >= off) ? sd[tid - off] : 0;
        __syncthreads();
        sd[tid] += t;
        __syncthreads();
    }
    if (i < Nn) g_rowptr[i + 1] = sd[tid];
    if (tid == 1023) g_bsum[b] = sd[1023];
}
__global__ void k_scan2() {
    if (threadIdx.x == 0) {
        int acc = 0;
        for (int b = 0; b < SCB; b++) { g_boff[b] = acc; acc += g_bsum[b]; }
        g_rowptr[0] = 0;
    }
}
__global__ void k_scan3() {
    int i = blockIdx.x * blockDim.x + threadIdx.x;
    if (i < Nn) {
        int r = g_rowptr[i + 1] + g_boff[i >> 10];
        g_rowptr[i + 1] = r;
        g_tmpptr[i] = r - g_cnt[i];
    }
}

__global__ void k_fill(const int* __restrict__ ei) {
    int e = blockIdx.x * blockDim.x + threadIdx.x;
    if (e < Ee) {
        int s = ei[e];
        int d = ei[e + Ee];
        if ((unsigned)s >= Nn || (unsigned)d >= Nn) return;
        int p = atomicAdd(&g_tmpptr[d], 1);
        float w = -g_dinv[s] * g_dinv[d];
        g_epk[p] = make_int2(s, __float_as_int(w));
    }
}

// ---------------- propagation ----------------
__global__ void k_prop3(const float* __restrict__ hin,
                        const float* __restrict__ sub,
                        float* __restrict__ out) {
    int v = blockIdx.x * blockDim.x + threadIdx.x;
    if (v >= Nn) return;
    float a0 = 0.f, a1 = 0.f, a2 = 0.f;
    int b = g_rowptr[v], en = g_rowptr[v + 1];
    int i = b;
    for (; i + 3 < en; i += 4) {
        int2 e0 = g_epk[i];
        int2 e1 = g_epk[i + 1];
        int2 e2 = g_epk[i + 2];
        int2 e3 = g_epk[i + 3];
        const float* h0 = hin + e0.x * 3;
        const float* h1 = hin + e1.x * 3;
        const float* h2 = hin + e2.x * 3;
        const float* h3 = hin + e3.x * 3;
        float x0 = h0[0], y0 = h0[1], z0 = h0[2];
        float x1 = h1[0], y1 = h1[1], z1 = h1[2];
        float x2 = h2[0], y2 = h2[1], z2 = h2[2];
        float x3 = h3[0], y3 = h3[1], z3 = h3[2];
        float w0 = __int_as_float(e0.y), w1 = __int_as_float(e1.y);
        float w2 = __int_as_float(e2.y), w3 = __int_as_float(e3.y);
        a0 += w0 * x0 + w1 * x1 + w2 * x2 + w3 * x3;
        a1 += w0 * y0 + w1 * y1 + w2 * y2 + w3 * y3;
        a2 += w0 * z0 + w1 * z1 + w2 * z2 + w3 * z3;
    }
    for (; i < en; i++) {
        int2 e = g_epk[i];
        float w = __int_as_float(e.y);
        const float* hp = hin + e.x * 3;
        a0 += w * hp[0]; a1 += w * hp[1]; a2 += w * hp[2];
    }
    float* o = out + v * 3;
    if (sub) {
        const float* sv = sub + v * 3;
        o[0] = 2.f * a0 - sv[0]; o[1] = 2.f * a1 - sv[1]; o[2] = 2.f * a2 - sv[2];
    } else {
        o[0] = a0; o[1] = a1; o[2] = a2;
    }
}

// warp per node; 4 edges in flight (MLP-4).
// mode: 0 = plain (optional sub), 1 = BN on hin, 2 = BN on sub.
__global__ void k_prop128(const float* __restrict__ hin,
                          const float* __restrict__ sub,
                          float* __restrict__ out,
                          const float* __restrict__ sc,
                          const float* __restrict__ sh,
                          int mode) {
    int v = blockIdx.x * 4 + (threadIdx.x >> 5);
    if (v >= Nn) return;
    int lane = threadIdx.x & 31;
    float4 sc4, sh4;
    if (mode) {
        sc4 = ((const float4*)sc)[lane];
        sh4 = ((const float4*)sh)[lane];
    }
    int b = g_rowptr[v], en = g_rowptr[v + 1];
    float4 acc = make_float4(0.f, 0.f, 0.f, 0.f);
    float wsum = 0.f;
    int i = b;
    for (; i + 3 < en; i += 4) {
        int2 e0 = g_epk[i];
        int2 e1 = g_epk[i + 1];
        int2 e2 = g_epk[i + 2];
        int2 e3 = g_epk[i + 3];
        float4 v0 = *(const float4*)(hin + e0.x * Hd + lane * 4);
        float4 v1 = *(const float4*)(hin + e1.x * Hd + lane * 4);
        float4 v2 = *(const float4*)(hin + e2.x * Hd + lane * 4);
        float4 v3 = *(const float4*)(hin + e3.x * Hd + lane * 4);
        float w0 = __int_as_float(e0.y), w1 = __int_as_float(e1.y);
        float w2 = __int_as_float(e2.y), w3 = __int_as_float(e3.y);
        acc.x += w0 * v0.x + w1 * v1.x + w2 * v2.x + w3 * v3.x;
        acc.y += w0 * v0.y + w1 * v1.y + w2 * v2.y + w3 * v3.y;
        acc.z += w0 * v0.z + w1 * v1.z + w2 * v2.z + w3 * v3.z;
        acc.w += w0 * v0.w + w1 * v1.w + w2 * v2.w + w3 * v3.w;
        wsum += (w0 + w1) + (w2 + w3);
    }
    for (; i < en; i++) {
        int2 e = g_epk[i];
        float w = __int_as_float(e.y);
        float4 g = *(const float4*)(hin + e.x * Hd + lane * 4);
        acc.x += w * g.x; acc.y += w * g.y; acc.z += w * g.z; acc.w += w * g.w;
        wsum += w;
    }
    float4 r;
    if (mode == 1) {
        r.x = sc4.x * acc.x + sh4.x * wsum;
        r.y = sc4.y * acc.y + sh4.y * wsum;
        r.z = sc4.z * acc.z + sh4.z * wsum;
        r.w = sc4.w * acc.w + sh4.w * wsum;
    } else if (mode == 2) {
        float4 sv = *(const float4*)(sub + v * Hd + lane * 4);
        r.x = 2.f * acc.x - (sc4.x * sv.x + sh4.x);
        r.y = 2.f * acc.y - (sc4.y * sv.y + sh4.y);
        r.z = 2.f * acc.z - (sc4.z * sv.z + sh4.z);
        r.w = 2.f * acc.w - (sc4.w * sv.w + sh4.w);
    } else if (sub) {
        float4 sv = *(const float4*)(sub + v * Hd + lane * 4);
        r.x = 2.f * acc.x - sv.x; r.y = 2.f * acc.y - sv.y;
        r.z = 2.f * acc.z - sv.z; r.w = 2.f * acc.w - sv.w;
    } else {
        r = acc;
    }
    *(float4*)(out + v * Hd + lane * 4) = r;
}

// ---------------- layer 1 GEMM: K=12 (+ fused stats partials) ----------------
__global__ void k_gemm12(const float* __restrict__ x,  const float* __restrict__ t1,
                         const float* __restrict__ t2, const float* __restrict__ t3,
                         const float* __restrict__ W,  const float* __restrict__ bias,
                         float* __restrict__ out) {
    __shared__ float sW[12 * Hd];
    int c = threadIdx.x;
    #pragma unroll
    for (int j = 0; j < 12; j++) sW[j * Hd + c] = W[j * Hd + c];
    __syncthreads();
    const int RPB = 32;
    int v0 = blockIdx.x * RPB;
    float bv = bias[c];
    float s = 0.f, s2 = 0.f;
    for (int r = 0; r < RPB; r++) {
        int v = v0 + r;
        if (v >= Nn) break;
        float a[12];
        #pragma unroll
        for (int f = 0; f < 3; f++) {
            a[f]     = x [v * 3 + f];
            a[3 + f] = t1[v * 3 + f];
            a[6 + f] = t2[v * 3 + f];
            a[9 + f] = t3[v * 3 + f];
        }
        float acc = bv;
        #pragma unroll
        for (int j = 0; j < 12; j++) acc += a[j] * sW[j * Hd + c];
        acc = (acc > 0.f) ? acc : 0.01f * acc;   // leaky relu
        out[v * Hd + c] = acc;
        s += acc; s2 += acc * acc;
    }
    g_part [blockIdx.x * Hd + c] = s;
    g_part2[blockIdx.x * Hd + c] = s2;
}

// ---------------- tensor-core GEMM (mma.sync tf32) + fused epilogues --------
// mode: 1 = leaky+stats, 2 = relu+stats, 0 = no-act + row-L2-normalize
#define BM 128
#define BK 16
#define ASTR (BK + 4)     // 20
#define BSTR (Hd + 8)     // 136: B frag banks = 8*tig + grp, conflict-free

__global__ __launch_bounds__(256)
void k_gemm_mma(const float* __restrict__ A0, const float* __restrict__ A1,
                const float* __restrict__ A2, const float* __restrict__ A3,
                const float* __restrict__ W,  const float* __restrict__ bias,
                float* __restrict__ out,
                const float* __restrict__ scA, const float* __restrict__ shA,
                int mode) {
    __shared__ uint32_t As[BM][ASTR];
    __shared__ uint32_t Bs[BK][BSTR];
    __shared__ float sred [8][64];
    __shared__ float sred2[8][64];
    __shared__ float rows2[2][BM];
    const float* Abuf[4] = {A0, A1, A2, A3};

    int tid = threadIdx.x;
    int wid = tid >> 5;
    int lane = tid & 31;
    int grp = lane >> 2;       // 0..7
    int tig = lane & 3;        // 0..3
    int m_base = (wid >> 1) * 32;
    int n_base = (wid & 1) * 64;
    int row0 = blockIdx.x * BM;

    float c[2][8][4];
    #pragma unroll
    for (int mi = 0; mi < 2; mi++)
        #pragma unroll
        for (int ni = 0; ni < 8; ni++)
            #pragma unroll
            for (int q = 0; q < 4; q++) c[mi][ni][q] = 0.f;

    int la_r  = tid >> 1;
    int la_c4 = (tid & 1) * 8;
    int lb_k  = tid >> 5;
    int lb_c4 = (tid & 31) * 4;

    for (int kt = 0; kt < 32; kt++) {
        const float* A = Abuf[kt >> 3];
        int cb = (kt & 7) * BK;
        {
            int gr = row0 + la_r;
            float4 v0 = make_float4(0.f,0.f,0.f,0.f), v1 = v0;
            if (gr < Nn) {
                const float4* src = (const float4*)(A + gr * Hd + cb + la_c4);
                v0 = src[0]; v1 = src[1];
            }
            if (scA && (kt >> 3) == 0) {   // A0 = BN(h) applied inline
                float4 s0 = *(const float4*)(scA + cb + la_c4);
                float4 s1 = *(const float4*)(scA + cb + la_c4 + 4);
                float4 h0 = *(const float4*)(shA + cb + la_c4);
                float4 h1 = *(const float4*)(shA + cb + la_c4 + 4);
                v0.x = v0.x * s0.x + h0.x; v0.y = v0.y * s0.y + h0.y;
                v0.z = v0.z * s0.z + h0.z; v0.w = v0.w * s0.w + h0.w;
                v1.x = v1.x * s1.x + h1.x; v1.y = v1.y * s1.y + h1.y;
                v1.z = v1.z * s1.z + h1.z; v1.w = v1.w * s1.w + h1.w;
                if (gr >= Nn) { v0 = make_float4(0,0,0,0); v1 = v0; }
            }
            uint4 u0 = make_uint4(f2tf32(v0.x), f2tf32(v0.y), f2tf32(v0.z), f2tf32(v0.w));
            uint4 u1 = make_uint4(f2tf32(v1.x), f2tf32(v1.y), f2tf32(v1.z), f2tf32(v1.w));
            *(uint4*)&As[la_r][la_c4]     = u0;
            *(uint4*)&As[la_r][la_c4 + 4] = u1;
        }
        {
            #pragma unroll
            for (int p = 0; p < 2; p++) {
                int kk = lb_k + p * 8;
                float4 v = *(const float4*)(W + (kt * BK + kk) * Hd + lb_c4);
                uint4 u = make_uint4(f2tf32(v.x), f2tf32(v.y), f2tf32(v.z), f2tf32(v.w));
                *(uint4*)&Bs[kk][lb_c4] = u;
            }
        }
        __syncthreads();
        #pragma unroll
        for (int ks = 0; ks < 2; ks++) {
            int kk0 = ks * 8;
            uint32_t a[2][4], b[8][2];
            #pragma unroll
            for (int mi = 0; mi < 2; mi++) {
                int m0 = m_base + mi * 16 + grp;
                a[mi][0] = As[m0][kk0 + tig];
                a[mi][1] = As[m0 + 8][kk0 + tig];
                a[mi][2] = As[m0][kk0 + tig + 4];
                a[mi][3] = As[m0 + 8][kk0 + tig + 4];
            }
            #pragma unroll
            for (int ni = 0; ni < 8; ni++) {
                int nc = n_base + ni * 8 + grp;
                b[ni][0] = Bs[kk0 + tig][nc];
                b[ni][1] = Bs[kk0 + tig + 4][nc];
            }
            #pragma unroll
            for (int mi = 0; mi < 2; mi++)
                #pragma unroll
                for (int ni = 0; ni < 8; ni++)
                    mma_tf32(c[mi][ni], a[mi], b[ni]);
        }
        __syncthreads();
    }

    // ---- bias + activation (zero invalid rows) ----
    #pragma unroll
    for (int mi = 0; mi < 2; mi++) {
        #pragma unroll
        for (int half = 0; half < 2; half++) {
            int row = row0 + m_base + mi * 16 + grp + half * 8;
            bool valid = row < Nn;
            #pragma unroll
            for (int ni = 0; ni < 8; ni++) {
                #pragma unroll
                for (int par = 0; par < 2; par++) {
                    int q = half * 2 + par;
                    int col = n_base + ni * 8 + tig * 2 + par;
                    float f = c[mi][ni][q] + __ldg(bias + col);
                    if (mode == 1)      f = (f > 0.f) ? f : 0.01f * f;
                    else if (mode == 2) f = fmaxf(f, 0.f);
                    c[mi][ni][q] = valid ? f : 0.f;
                }
            }
        }
    }

    float rscale[2][2] = {{1.f,1.f},{1.f,1.f}};

    if (mode != 0) {
        // ---- fused BN stats partials (deterministic) ----
        float ls[8][2], ls2[8][2];
        #pragma unroll
        for (int ni = 0; ni < 8; ni++)
            #pragma unroll
            for (int par = 0; par < 2; par++) {
                float s = 0.f, s2 = 0.f;
                #pragma unroll
                for (int mi = 0; mi < 2; mi++)
                    #pragma unroll
                    for (int half = 0; half < 2; half++) {
                        float f = c[mi][ni][half * 2 + par];
                        s += f; s2 += f * f;
                    }
                ls[ni][par] = s; ls2[ni][par] = s2;
            }
        #pragma unroll
        for (int off = 4; off < 32; off <<= 1) {
            #pragma unroll
            for (int ni = 0; ni < 8; ni++)
                #pragma unroll
                for (int par = 0; par < 2; par++) {
                    ls [ni][par] += __shfl_xor_sync(0xffffffffu, ls [ni][par], off);
                    ls2[ni][par] += __shfl_xor_sync(0xffffffffu, ls2[ni][par], off);
                }
        }
        if (lane < 4) {
            #pragma unroll
            for (int ni = 0; ni < 8; ni++)
                #pragma unroll
                for (int par = 0; par < 2; par++) {
                    sred [wid][ni * 8 + tig * 2 + par] = ls [ni][par];
                    sred2[wid][ni * 8 + tig * 2 + par] = ls2[ni][par];
                }
        }
        __syncthreads();
        if (tid < Hd) {
            int hf = tid >> 6, cl = tid & 63;
            float s = 0.f, s2 = 0.f;
            #pragma unroll
            for (int j = 0; j < 4; j++) {
                s  += sred [2 * j + hf][cl];
                s2 += sred2[2 * j + hf][cl];
            }
            g_part [blockIdx.x * Hd + tid] = s;
            g_part2[blockIdx.x * Hd + tid] = s2;
        }
    } else {
        // ---- fused row L2 normalize ----
        #pragma unroll
        for (int mi = 0; mi < 2; mi++)
            #pragma unroll
            for (int half = 0; half < 2; half++) {
                float rsq = 0.f;
                #pragma unroll
                for (int ni = 0; ni < 8; ni++) {
                    float f0 = c[mi][ni][half * 2 + 0];
                    float f1 = c[mi][ni][half * 2 + 1];
                    rsq += f0 * f0 + f1 * f1;
                }
                rsq += __shfl_xor_sync(0xffffffffu, rsq, 1);
                rsq += __shfl_xor_sync(0xffffffffu, rsq, 2);
                if (tig == 0)
                    rows2[wid & 1][m_base + mi * 16 + grp + half * 8] = rsq;
            }
        __syncthreads();
        #pragma unroll
        for (int mi = 0; mi < 2; mi++)
            #pragma unroll
            for (int half = 0; half < 2; half++) {
                int rl = m_base + mi * 16 + grp + half * 8;
                float tot = rows2[0][rl] + rows2[1][rl];
                rscale[mi][half] = 1.f / fmaxf(sqrtf(tot), 1e-12f);
            }
    }

    // ---- store ----
    #pragma unroll
    for (int mi = 0; mi < 2; mi++) {
        #pragma unroll
        for (int half = 0; half < 2; half++) {
            int row = row0 + m_base + mi * 16 + grp + half * 8;
            if (row < Nn) {
                float rs = rscale[mi][half];
                #pragma unroll
                for (int ni = 0; ni < 8; ni++) {
                    int col = n_base + ni * 8 + tig * 2;
                    float f0 = c[mi][ni][half * 2 + 0] * rs;
                    float f1 = c[mi][ni][half * 2 + 1] * rs;
                    *(float2*)(out + row * Hd + col) = make_float2(f0, f1);
                }
            }
        }
    }
}

// ---------------- BN finalize ----------------
__global__ void k_bnfin(const float* __restrict__ gamma, const float* __restrict__ beta,
                        int nb) {
    int c = threadIdx.x;
    float s = 0.f, s2 = 0.f;
    for (int b = 0; b < nb; b++) { s += g_part[b * Hd + c]; s2 += g_part2[b * Hd + c]; }
    float m   = s / (float)Nn;
    float var = s2 / (float)Nn - m * m;
    float inv = rsqrtf(var + 1e-5f);
    float sc  = gamma[c] * inv;
    g_scale[c] = sc;
    g_shift[c] = beta[c] - m * sc;
}

// ---------------- host ----------------
extern "C" void kernel_launch(void* const* d_in, const int* in_sizes, int n_in,
                              void* d_out, int out_size) {
    const float* x  = (const float*)d_in[0];
    const int*   ei = (const int*)d_in[1];   // int32 (JAX x64 disabled)
    const float* W1 = (const float*)d_in[2];  const float* b1 = (const float*)d_in[3];
    const float* W2 = (const float*)d_in[4];  const float* b2 = (const float*)d_in[5];
    const float* W3 = (const float*)d_in[6];  const float* b3 = (const float*)d_in[7];
    const float* W4 = (const float*)d_in[8];  const float* b4 = (const float*)d_in[9];
    const float* g1 = (const float*)d_in[10]; const float* be1 = (const float*)d_in[11];
    const float* g2 = (const float*)d_in[12]; const float* be2 = (const float*)d_in[13];
    const float* g3 = (const float*)d_in[14]; const float* be3 = (const float*)d_in[15];

    float *p_t1, *p_t2, *p_t3, *p_out, *p_s1, *p_s2, *p_s3, *p_sc, *p_sh;
    cudaGetSymbolAddress((void**)&p_t1,  g_t1);
    cudaGetSymbolAddress((void**)&p_t2,  g_t2);
    cudaGetSymbolAddress((void**)&p_t3,  g_t3);
    cudaGetSymbolAddress((void**)&p_out, g_out);
    cudaGetSymbolAddress((void**)&p_s1,  g_s1);
    cudaGetSymbolAddress((void**)&p_s2,  g_s2);
    cudaGetSymbolAddress((void**)&p_s3,  g_s3);
    cudaGetSymbolAddress((void**)&p_sc,  g_scale);
    cudaGetSymbolAddress((void**)&p_sh,  g_shift);

    const int TB = 256;
    // graph build
    k_init <<<(Nn + TB - 1) / TB, TB>>>();
    k_count<<<(Ee + TB - 1) / TB, TB>>>(ei);
    k_dinv <<<(Nn + TB - 1) / TB, TB>>>();
    k_scan1<<<SCB, 1024>>>();
    k_scan2<<<1, 64>>>();
    k_scan3<<<(Nn + TB - 1) / TB, TB>>>();
    k_fill <<<(Ee + TB - 1) / TB, TB>>>(ei);

    int gP128 = (Nn + 3) / 4;
    int gGemm = (Nn + BM - 1) / BM;      // 391
    int g12   = (Nn + 31) / 32;          // 1563

    // layer 1 (F=3)
    k_prop3<<<(Nn + TB - 1) / TB, TB>>>(x, nullptr, p_s1);
    k_prop3<<<(Nn + TB - 1) / TB, TB>>>(p_s1, x, p_s2);
    k_prop3<<<(Nn + TB - 1) / TB, TB>>>(p_s2, p_s1, p_s3);
    k_gemm12<<<g12, Hd>>>(x, p_s1, p_s2, p_s3, W1, b1, p_out);
    k_bnfin<<<1, Hd>>>(g1, be1, g12);

    // layer 2 (props consume BN(h) via fused scale/shift)
    k_prop128<<<gP128, 128>>>(p_out, nullptr, p_t1, p_sc, p_sh, 1);
    k_prop128<<<gP128, 128>>>(p_t1, p_out, p_t2, p_sc, p_sh, 2);
    k_prop128<<<gP128, 128>>>(p_t2, p_t1, p_t3, nullptr, nullptr, 0);
    k_gemm_mma<<<gGemm, 256>>>(p_out, p_t1, p_t2, p_t3, W2, b2, p_out, p_sc, p_sh, 1);
    k_bnfin<<<1, Hd>>>(g2, be2, gGemm);

    // layer 3
    k_prop128<<<gP128, 128>>>(p_out, nullptr, p_t1, p_sc, p_sh, 1);
    k_prop128<<<gP128, 128>>>(p_t1, p_out, p_t2, p_sc, p_sh, 2);
    k_prop128<<<gP128, 128>>>(p_t2, p_t1, p_t3, nullptr, nullptr, 0);
    k_gemm_mma<<<gGemm, 256>>>(p_out, p_t1, p_t2, p_t3, W3, b3, p_out, p_sc, p_sh, 2);
    k_bnfin<<<1, Hd>>>(g3, be3, gGemm);

    // layer 4: props + GEMM with fused row-normalize, straight to d_out
    k_prop128<<<gP128, 128>>>(p_out, nullptr, p_t1, p_sc, p_sh, 1);
    k_prop128<<<gP128, 128>>>(p_t1, p_out, p_t2, p_sc, p_sh, 2);
    k_prop128<<<gP128, 128>>>(p_t2, p_t1, p_t3, nullptr, nullptr, 0);
    k_gemm_mma<<<gGemm, 256>>>(p_out, p_t1, p_t2, p_t3, W4, b4, (float*)d_out,
                               p_sc, p_sh, 0);
}

// round 9
// speedup vs baseline: 1.3702x; 1.1152x over previous
#include <cuda_runtime.h>
#include <cuda_bf16.h>
#include <cstdint>

#define Nn 50000
#define Ee 800000
#define Hd 128
#define SCB 49       // scan blocks (ceil(Nn/1024))
#define PMAX 1600    // max stats-partial blocks (gemm12 uses 1563)

// ---------------- scratch ----------------
__device__ int   g_deg[Nn];
__device__ int   g_cnt[Nn];
__device__ int   g_rowptr[Nn + 1];
__device__ int   g_tmpptr[Nn];
__device__ float g_dinv[Nn];
__device__ int2  g_epk[Ee];          // (src, weight-bits)
__device__ int   g_bsum[SCB];
__device__ int   g_boff[SCB];

__device__ __align__(256) float g_t1[Nn * Hd];
__device__ __align__(256) float g_t2[Nn * Hd];
__device__ __align__(256) float g_t3[Nn * Hd];
__device__ __align__(256) float g_out[Nn * Hd];

__device__ float g_s1[Nn * 3];
__device__ float g_s2[Nn * 3];
__device__ float g_s3[Nn * 3];

__device__ float g_part [PMAX * Hd];
__device__ float g_part2[PMAX * Hd];
__device__ float g_scale[Hd];
__device__ float g_shift[Hd];

// ---------------- helpers ----------------
__device__ __forceinline__ uint32_t f2tf32(float f) {
    uint32_t u;
    asm("cvt.rna.tf32.f32 %0, %1;" : "=r"(u) : "f"(f));
    return u;
}
__device__ __forceinline__ void mma_tf32(float* c, const uint32_t* a, const uint32_t* b) {
    asm volatile(
        "mma.sync.aligned.m16n8k8.row.col.f32.tf32.tf32.f32 "
        "{%0,%1,%2,%3}, {%4,%5,%6,%7}, {%8,%9}, {%0,%1,%2,%3};"
        : "+f"(c[0]), "+f"(c[1]), "+f"(c[2]), "+f"(c[3])
        : "r"(a[0]), "r"(a[1]), "r"(a[2]), "r"(a[3]), "r"(b[0]), "r"(b[1]));
}

// ---------------- graph build ----------------
__global__ void k_init() {
    int i = blockIdx.x * blockDim.x + threadIdx.x;
    if (i < Nn) { g_deg[i] = 0; g_cnt[i] = 0; }
}

__global__ void k_count(const int* __restrict__ ei) {
    int e = blockIdx.x * blockDim.x + threadIdx.x;
    if (e < Ee) {
        int s = ei[e];
        int d = ei[e + Ee];
        if ((unsigned)s < Nn) atomicAdd(&g_deg[s], 1);
        if ((unsigned)d < Nn) atomicAdd(&g_cnt[d], 1);
    }
}

__global__ void k_dinv() {
    int i = blockIdx.x * blockDim.x + threadIdx.x;
    if (i < Nn) {
        int d = g_deg[i];
        g_dinv[i] = (d > 0) ? rsqrtf((float)d) : 0.0f;
    }
}

__global__ void k_scan1() {
    __shared__ int sd[1024];
    int b = blockIdx.x, tid = threadIdx.x;
    int i = b * 1024 + tid;
    int v = (i < Nn) ? g_cnt[i] : 0;
    sd[tid] = v;
    __syncthreads();
    for (int off = 1; off < 1024; off <<= 1) {
        int t = (tid >= off) ? sd[tid - off] : 0;
        __syncthreads();
        sd[tid] += t;
        __syncthreads();
    }
    if (i < Nn) g_rowptr[i + 1] = sd[tid];
    if (tid == 1023) g_bsum[b] = sd[1023];
}
__global__ void k_scan2() {
    if (threadIdx.x == 0) {
        int acc = 0;
        for (int b = 0; b < SCB; b++) { g_boff[b] = acc; acc += g_bsum[b]; }
        g_rowptr[0] = 0;
    }
}
__global__ void k_scan3() {
    int i = blockIdx.x * blockDim.x + threadIdx.x;
    if (i < Nn) {
        int r = g_rowptr[i + 1] + g_boff[i >> 10];
        g_rowptr[i + 1] = r;
        g_tmpptr[i] = r - g_cnt[i];
    }
}

__global__ void k_fill(const int* __restrict__ ei) {
    int e = blockIdx.x * blockDim.x + threadIdx.x;
    if (e < Ee) {
        int s = ei[e];
        int d = ei[e + Ee];
        if ((unsigned)s >= Nn || (unsigned)d >= Nn) return;
        int p = atomicAdd(&g_tmpptr[d], 1);
        float w = -g_dinv[s] * g_dinv[d];
        g_epk[p] = make_int2(s, __float_as_int(w));
    }
}

// ---------------- propagation ----------------
__global__ void k_prop3(const float* __restrict__ hin,
                        const float* __restrict__ sub,
                        float* __restrict__ out) {
    int v = blockIdx.x * blockDim.x + threadIdx.x;
    if (v >= Nn) return;
    float a0 = 0.f, a1 = 0.f, a2 = 0.f;
    int b = g_rowptr[v], en = g_rowptr[v + 1];
    for (int i = b; i < en; i++) {
        int2 e = g_epk[i];
        float w = __int_as_float(e.y);
        const float* hp = hin + e.x * 3;
        a0 += w * hp[0]; a1 += w * hp[1]; a2 += w * hp[2];
    }
    float* o = out + v * 3;
    if (sub) {
        const float* sv = sub + v * 3;
        o[0] = 2.f * a0 - sv[0]; o[1] = 2.f * a1 - sv[1]; o[2] = 2.f * a2 - sv[2];
    } else {
        o[0] = a0; o[1] = a1; o[2] = a2;
    }
}

// warp per node. mode: 0 = plain (optional sub), 1 = BN on hin (no sub),
// 2 = BN on sub (hin plain).
__global__ void k_prop128(const float* __restrict__ hin,
                          const float* __restrict__ sub,
                          float* __restrict__ out,
                          const float* __restrict__ sc,
                          const float* __restrict__ sh,
                          int mode) {
    int v = blockIdx.x * 4 + (threadIdx.x >> 5);
    if (v >= Nn) return;
    int lane = threadIdx.x & 31;
    float4 sc4, sh4;
    if (mode) {
        sc4 = ((const float4*)sc)[lane];
        sh4 = ((const float4*)sh)[lane];
    }
    int b = g_rowptr[v], en = g_rowptr[v + 1];
    float4 acc = make_float4(0.f, 0.f, 0.f, 0.f);
    float wsum = 0.f;
    int i = b;
    for (; i + 1 < en; i += 2) {
        int2 e0 = g_epk[i];
        int2 e1 = g_epk[i + 1];
        float w0 = __int_as_float(e0.y);
        float w1 = __int_as_float(e1.y);
        float4 v0 = *(const float4*)(hin + e0.x * Hd + lane * 4);
        float4 v1 = *(const float4*)(hin + e1.x * Hd + lane * 4);
        acc.x += w0 * v0.x + w1 * v1.x;
        acc.y += w0 * v0.y + w1 * v1.y;
        acc.z += w0 * v0.z + w1 * v1.z;
        acc.w += w0 * v0.w + w1 * v1.w;
        wsum += w0 + w1;
    }
    if (i < en) {
        int2 e = g_epk[i];
        float w = __int_as_float(e.y);
        float4 g = *(const float4*)(hin + e.x * Hd + lane * 4);
        acc.x += w * g.x; acc.y += w * g.y; acc.z += w * g.z; acc.w += w * g.w;
        wsum += w;
    }
    float4 r;
    if (mode == 1) {
        r.x = sc4.x * acc.x + sh4.x * wsum;
        r.y = sc4.y * acc.y + sh4.y * wsum;
        r.z = sc4.z * acc.z + sh4.z * wsum;
        r.w = sc4.w * acc.w + sh4.w * wsum;
    } else if (mode == 2) {
        float4 sv = *(const float4*)(sub + v * Hd + lane * 4);
        r.x = 2.f * acc.x - (sc4.x * sv.x + sh4.x);
        r.y = 2.f * acc.y - (sc4.y * sv.y + sh4.y);
        r.z = 2.f * acc.z - (sc4.z * sv.z + sh4.z);
        r.w = 2.f * acc.w - (sc4.w * sv.w + sh4.w);
    } else if (sub) {
        float4 sv = *(const float4*)(sub + v * Hd + lane * 4);
        r.x = 2.f * acc.x - sv.x; r.y = 2.f * acc.y - sv.y;
        r.z = 2.f * acc.z - sv.z; r.w = 2.f * acc.w - sv.w;
    } else {
        r = acc;
    }
    *(float4*)(out + v * Hd + lane * 4) = r;
}

// ---------------- layer 1 GEMM: K=12 (+ fused stats partials) ----------------
__global__ void k_gemm12(const float* __restrict__ x,  const float* __restrict__ t1,
                         const float* __restrict__ t2, const float* __restrict__ t3,
                         const float* __restrict__ W,  const float* __restrict__ bias,
                         float* __restrict__ out) {
    __shared__ float sW[12 * Hd];
    int c = threadIdx.x;
    #pragma unroll
    for (int j = 0; j < 12; j++) sW[j * Hd + c] = W[j * Hd + c];
    __syncthreads();
    const int RPB = 32;
    int v0 = blockIdx.x * RPB;
    float bv = bias[c];
    float s = 0.f, s2 = 0.f;
    for (int r = 0; r < RPB; r++) {
        int v = v0 + r;
        if (v >= Nn) break;
        float a[12];
        #pragma unroll
        for (int f = 0; f < 3; f++) {
            a[f]     = x [v * 3 + f];
            a[3 + f] = t1[v * 3 + f];
            a[6 + f] = t2[v * 3 + f];
            a[9 + f] = t3[v * 3 + f];
        }
        float acc = bv;
        #pragma unroll
        for (int j = 0; j < 12; j++) acc += a[j] * sW[j * Hd + c];
        acc = (acc > 0.f) ? acc : 0.01f * acc;   // leaky relu
        out[v * Hd + c] = acc;
        s += acc; s2 += acc * acc;
    }
    g_part [blockIdx.x * Hd + c] = s;
    g_part2[blockIdx.x * Hd + c] = s2;
}

// ---------------- tensor-core GEMM (mma.sync tf32) + fused epilogues --------
// mode: 1 = leaky+stats, 2 = relu+stats, 0 = no-act + row-L2-normalize
#define BM 128
#define BK 16
#define ASTR (BK + 4)     // 20
#define BSTR (Hd + 8)     // 136: B frag banks = 8*tig + grp, conflict-free

__global__ __launch_bounds__(256)
void k_gemm_mma(const float* __restrict__ A0, const float* __restrict__ A1,
                const float* __restrict__ A2, const float* __restrict__ A3,
                const float* __restrict__ W,  const float* __restrict__ bias,
                float* __restrict__ out,
                const float* __restrict__ scA, const float* __restrict__ shA,
                int mode) {
    __shared__ uint32_t As[BM][ASTR];
    __shared__ uint32_t Bs[BK][BSTR];
    __shared__ float sred [8][64];
    __shared__ float sred2[8][64];
    __shared__ float rows2[2][BM];
    const float* Abuf[4] = {A0, A1, A2, A3};

    int tid = threadIdx.x;
    int wid = tid >> 5;
    int lane = tid & 31;
    int grp = lane >> 2;       // 0..7
    int tig = lane & 3;        // 0..3
    int m_base = (wid >> 1) * 32;
    int n_base = (wid & 1) * 64;
    int row0 = blockIdx.x * BM;

    float c[2][8][4];
    #pragma unroll
    for (int mi = 0; mi < 2; mi++)
        #pragma unroll
        for (int ni = 0; ni < 8; ni++)
            #pragma unroll
            for (int q = 0; q < 4; q++) c[mi][ni][q] = 0.f;

    int la_r  = tid >> 1;
    int la_c4 = (tid & 1) * 8;
    int lb_k  = tid >> 5;
    int lb_c4 = (tid & 31) * 4;

    for (int kt = 0; kt < 32; kt++) {
        const float* A = Abuf[kt >> 3];
        int cb = (kt & 7) * BK;
        {
            int gr = row0 + la_r;
            float4 v0 = make_float4(0.f,0.f,0.f,0.f), v1 = v0;
            if (gr < Nn) {
                const float4* src = (const float4*)(A + gr * Hd + cb + la_c4);
                v0 = src[0]; v1 = src[1];
            }
            if (scA && (kt >> 3) == 0) {   // A0 = BN(h) applied inline
                float4 s0 = *(const float4*)(scA + cb + la_c4);
                float4 s1 = *(const float4*)(scA + cb + la_c4 + 4);
                float4 h0 = *(const float4*)(shA + cb + la_c4);
                float4 h1 = *(const float4*)(shA + cb + la_c4 + 4);
                v0.x = v0.x * s0.x + h0.x; v0.y = v0.y * s0.y + h0.y;
                v0.z = v0.z * s0.z + h0.z; v0.w = v0.w * s0.w + h0.w;
                v1.x = v1.x * s1.x + h1.x; v1.y = v1.y * s1.y + h1.y;
                v1.z = v1.z * s1.z + h1.z; v1.w = v1.w * s1.w + h1.w;
                if (gr >= Nn) { v0 = make_float4(0,0,0,0); v1 = v0; }
            }
            uint4 u0 = make_uint4(f2tf32(v0.x), f2tf32(v0.y), f2tf32(v0.z), f2tf32(v0.w));
            uint4 u1 = make_uint4(f2tf32(v1.x), f2tf32(v1.y), f2tf32(v1.z), f2tf32(v1.w));
            *(uint4*)&As[la_r][la_c4]     = u0;
            *(uint4*)&As[la_r][la_c4 + 4] = u1;
        }
        {
            #pragma unroll
            for (int p = 0; p < 2; p++) {
                int kk = lb_k + p * 8;
                float4 v = *(const float4*)(W + (kt * BK + kk) * Hd + lb_c4);
                uint4 u = make_uint4(f2tf32(v.x), f2tf32(v.y), f2tf32(v.z), f2tf32(v.w));
                *(uint4*)&Bs[kk][lb_c4] = u;
            }
        }
        __syncthreads();
        #pragma unroll
        for (int ks = 0; ks < 2; ks++) {
            int kk0 = ks * 8;
            uint32_t a[2][4], b[8][2];
            #pragma unroll
            for (int mi = 0; mi < 2; mi++) {
                int m0 = m_base + mi * 16 + grp;
                a[mi][0] = As[m0][kk0 + tig];
                a[mi][1] = As[m0 + 8][kk0 + tig];
                a[mi][2] = As[m0][kk0 + tig + 4];
                a[mi][3] = As[m0 + 8][kk0 + tig + 4];
            }
            #pragma unroll
            for (int ni = 0; ni < 8; ni++) {
                int nc = n_base + ni * 8 + grp;
                b[ni][0] = Bs[kk0 + tig][nc];
                b[ni][1] = Bs[kk0 + tig + 4][nc];
            }
            #pragma unroll
            for (int mi = 0; mi < 2; mi++)
                #pragma unroll
                for (int ni = 0; ni < 8; ni++)
                    mma_tf32(c[mi][ni], a[mi], b[ni]);
        }
        __syncthreads();
    }

    // ---- bias + activation (zero invalid rows) ----
    #pragma unroll
    for (int mi = 0; mi < 2; mi++) {
        #pragma unroll
        for (int half = 0; half < 2; half++) {
            int row = row0 + m_base + mi * 16 + grp + half * 8;
            bool valid = row < Nn;
            #pragma unroll
            for (int ni = 0; ni < 8; ni++) {
                #pragma unroll
                for (int par = 0; par < 2; par++) {
                    int q = half * 2 + par;
                    int col = n_base + ni * 8 + tig * 2 + par;
                    float f = c[mi][ni][q] + __ldg(bias + col);
                    if (mode == 1)      f = (f > 0.f) ? f : 0.01f * f;
                    else if (mode == 2) f = fmaxf(f, 0.f);
                    c[mi][ni][q] = valid ? f : 0.f;
                }
            }
        }
    }

    float rscale[2][2] = {{1.f,1.f},{1.f,1.f}};

    if (mode != 0) {
        // ---- fused BN stats partials (deterministic) ----
        float ls[8][2], ls2[8][2];
        #pragma unroll
        for (int ni = 0; ni < 8; ni++)
            #pragma unroll
            for (int par = 0; par < 2; par++) {
                float s = 0.f, s2 = 0.f;
                #pragma unroll
                for (int mi = 0; mi < 2; mi++)
                    #pragma unroll
                    for (int half = 0; half < 2; half++) {
                        float f = c[mi][ni][half * 2 + par];
                        s += f; s2 += f * f;
                    }
                ls[ni][par] = s; ls2[ni][par] = s2;
            }
        #pragma unroll
        for (int off = 4; off < 32; off <<= 1) {
            #pragma unroll
            for (int ni = 0; ni < 8; ni++)
                #pragma unroll
                for (int par = 0; par < 2; par++) {
                    ls [ni][par] += __shfl_xor_sync(0xffffffffu, ls [ni][par], off);
                    ls2[ni][par] += __shfl_xor_sync(0xffffffffu, ls2[ni][par], off);
                }
        }
        if (lane < 4) {
            #pragma unroll
            for (int ni = 0; ni < 8; ni++)
                #pragma unroll
                for (int par = 0; par < 2; par++) {
                    sred [wid][ni * 8 + tig * 2 + par] = ls [ni][par];
                    sred2[wid][ni * 8 + tig * 2 + par] = ls2[ni][par];
                }
        }
        __syncthreads();
        if (tid < Hd) {
            int hf = tid >> 6, cl = tid & 63;
            float s = 0.f, s2 = 0.f;
            #pragma unroll
            for (int j = 0; j < 4; j++) {
                s  += sred [2 * j + hf][cl];
                s2 += sred2[2 * j + hf][cl];
            }
            g_part [blockIdx.x * Hd + tid] = s;
            g_part2[blockIdx.x * Hd + tid] = s2;
        }
    } else {
        // ---- fused row L2 normalize ----
        #pragma unroll
        for (int mi = 0; mi < 2; mi++)
            #pragma unroll
            for (int half = 0; half < 2; half++) {
                float rsq = 0.f;
                #pragma unroll
                for (int ni = 0; ni < 8; ni++) {
                    float f0 = c[mi][ni][half * 2 + 0];
                    float f1 = c[mi][ni][half * 2 + 1];
                    rsq += f0 * f0 + f1 * f1;
                }
                rsq += __shfl_xor_sync(0xffffffffu, rsq, 1);
                rsq += __shfl_xor_sync(0xffffffffu, rsq, 2);
                if (tig == 0)
                    rows2[wid & 1][m_base + mi * 16 + grp + half * 8] = rsq;
            }
        __syncthreads();
        #pragma unroll
        for (int mi = 0; mi < 2; mi++)
            #pragma unroll
            for (int half = 0; half < 2; half++) {
                int rl = m_base + mi * 16 + grp + half * 8;
                float tot = rows2[0][rl] + rows2[1][rl];
                rscale[mi][half] = 1.f / fmaxf(sqrtf(tot), 1e-12f);
            }
    }

    // ---- store ----
    #pragma unroll
    for (int mi = 0; mi < 2; mi++) {
        #pragma unroll
        for (int half = 0; half < 2; half++) {
            int row = row0 + m_base + mi * 16 + grp + half * 8;
            if (row < Nn) {
                float rs = rscale[mi][half];
                #pragma unroll
                for (int ni = 0; ni < 8; ni++) {
                    int col = n_base + ni * 8 + tig * 2;
                    float f0 = c[mi][ni][half * 2 + 0] * rs;
                    float f1 = c[mi][ni][half * 2 + 1] * rs;
                    *(float2*)(out + row * Hd + col) = make_float2(f0, f1);
                }
            }
        }
    }
}

// ---------------- BN finalize (parallel: one block per channel) -------------
__global__ void k_bnfin(const float* __restrict__ gamma, const float* __restrict__ beta,
                        int nb) {
    int c = blockIdx.x;          // channel 0..127
    int t = threadIdx.x;         // 256 threads
    float s = 0.f, s2 = 0.f;
    for (int b = t; b < nb; b += 256) {
        s  += g_part [b * Hd + c];
        s2 += g_part2[b * Hd + c];
    }
    __shared__ float ss[256], ss2[256];
    ss[t] = s; ss2[t] = s2;
    __syncthreads();
    #pragma unroll
    for (int off = 128; off; off >>= 1) {
        if (t < off) { ss[t] += ss[t + off]; ss2[t] += ss2[t + off]; }
        __syncthreads();
    }
    if (t == 0) {
        float m   = ss[0] / (float)Nn;
        float var = ss2[0] / (float)Nn - m * m;
        float inv = rsqrtf(var + 1e-5f);
        float sc  = gamma[c] * inv;
        g_scale[c] = sc;
        g_shift[c] = beta[c] - m * sc;
    }
}

// ---------------- host ----------------
extern "C" void kernel_launch(void* const* d_in, const int* in_sizes, int n_in,
                              void* d_out, int out_size) {
    const float* x  = (const float*)d_in[0];
    const int*   ei = (const int*)d_in[1];   // int32 (JAX x64 disabled)
    const float* W1 = (const float*)d_in[2];  const float* b1 = (const float*)d_in[3];
    const float* W2 = (const float*)d_in[4];  const float* b2 = (const float*)d_in[5];
    const float* W3 = (const float*)d_in[6];  const float* b3 = (const float*)d_in[7];
    const float* W4 = (const float*)d_in[8];  const float* b4 = (const float*)d_in[9];
    const float* g1 = (const float*)d_in[10]; const float* be1 = (const float*)d_in[11];
    const float* g2 = (const float*)d_in[12]; const float* be2 = (const float*)d_in[13];
    const float* g3 = (const float*)d_in[14]; const float* be3 = (const float*)d_in[15];

    float *p_t1, *p_t2, *p_t3, *p_out, *p_s1, *p_s2, *p_s3, *p_sc, *p_sh;
    cudaGetSymbolAddress((void**)&p_t1,  g_t1);
    cudaGetSymbolAddress((void**)&p_t2,  g_t2);
    cudaGetSymbolAddress((void**)&p_t3,  g_t3);
    cudaGetSymbolAddress((void**)&p_out, g_out);
    cudaGetSymbolAddress((void**)&p_s1,  g_s1);
    cudaGetSymbolAddress((void**)&p_s2,  g_s2);
    cudaGetSymbolAddress((void**)&p_s3,  g_s3);
    cudaGetSymbolAddress((void**)&p_sc,  g_scale);
    cudaGetSymbolAddress((void**)&p_sh,  g_shift);

    const int TB = 256;
    // graph build
    k_init <<<(Nn + TB - 1) / TB, TB>>>();
    k_count<<<(Ee + TB - 1) / TB, TB>>>(ei);
    k_dinv <<<(Nn + TB - 1) / TB, TB>>>();
    k_scan1<<<SCB, 1024>>>();
    k_scan2<<<1, 64>>>();
    k_scan3<<<(Nn + TB - 1) / TB, TB>>>();
    k_fill <<<(Ee + TB - 1) / TB, TB>>>(ei);

    int gP128 = (Nn + 3) / 4;
    int gGemm = (Nn + BM - 1) / BM;      // 391
    int g12   = (Nn + 31) / 32;          // 1563

    // layer 1 (F=3)
    k_prop3<<<(Nn + TB - 1) / TB, TB>>>(x, nullptr, p_s1);
    k_prop3<<<(Nn + TB - 1) / TB, TB>>>(p_s1, x, p_s2);
    k_prop3<<<(Nn + TB - 1) / TB, TB>>>(p_s2, p_s1, p_s3);
    k_gemm12<<<g12, Hd>>>(x, p_s1, p_s2, p_s3, W1, b1, p_out);
    k_bnfin<<<Hd, 256>>>(g1, be1, g12);

    // layer 2 (props consume BN(h) via fused scale/shift)
    k_prop128<<<gP128, 128>>>(p_out, nullptr, p_t1, p_sc, p_sh, 1);
    k_prop128<<<gP128, 128>>>(p_t1, p_out, p_t2, p_sc, p_sh, 2);
    k_prop128<<<gP128, 128>>>(p_t2, p_t1, p_t3, nullptr, nullptr, 0);
    k_gemm_mma<<<gGemm, 256>>>(p_out, p_t1, p_t2, p_t3, W2, b2, p_out, p_sc, p_sh, 1);
    k_bnfin<<<Hd, 256>>>(g2, be2, gGemm);

    // layer 3
    k_prop128<<<gP128, 128>>>(p_out, nullptr, p_t1, p_sc, p_sh, 1);
    k_prop128<<<gP128, 128>>>(p_t1, p_out, p_t2, p_sc, p_sh, 2);
    k_prop128<<<gP128, 128>>>(p_t2, p_t1, p_t3, nullptr, nullptr, 0);
    k_gemm_mma<<<gGemm, 256>>>(p_out, p_t1, p_t2, p_t3, W3, b3, p_out, p_sc, p_sh, 2);
    k_bnfin<<<Hd, 256>>>(g3, be3, gGemm);

    // layer 4: props + GEMM with fused row-normalize, straight to d_out
    k_prop128<<<gP128, 128>>>(p_out, nullptr, p_t1, p_sc, p_sh, 1);
    k_prop128<<<gP128, 128>>>(p_t1, p_out, p_t2, p_sc, p_sh, 2);
    k_prop128<<<gP128, 128>>>(p_t2, p_t1, p_t3, nullptr, nullptr, 0);
    k_gemm_mma<<<gGemm, 256>>>(p_out, p_t1, p_t2, p_t3, W4, b4, (float*)d_out,
                               p_sc, p_sh, 0);
}

// round 10
// speedup vs baseline: 1.4580x; 1.0641x over previous
#include <cuda_runtime.h>
#include <cuda_bf16.h>
#include <cuda_fp16.h>
#include <cstdint>

#define Nn 50000
#define Ee 800000
#define Hd 128
#define SCB 49       // scan blocks (ceil(Nn/1024))
#define PMAX 1600    // max stats-partial blocks (gemm12 uses 1563)

// ---------------- scratch ----------------
__device__ int   g_deg[Nn];
__device__ int   g_cnt[Nn];
__device__ int   g_rowptr[Nn + 1];
__device__ int   g_tmpptr[Nn];
__device__ float g_dinv[Nn];
__device__ int2  g_epk[Ee];          // (src, weight-bits)
__device__ int   g_bsum[SCB];
__device__ int   g_boff[SCB];

__device__ __align__(256) float g_t1[Nn * Hd];
__device__ __align__(256) float g_t2[Nn * Hd];
__device__ __align__(256) float g_t3[Nn * Hd];
__device__ __align__(256) float g_out[Nn * Hd];

__device__ float g_s1[Nn * 3];
__device__ float g_s2[Nn * 3];
__device__ float g_s3[Nn * 3];

__device__ float g_part [PMAX * Hd];
__device__ float g_part2[PMAX * Hd];
__device__ float g_scale[Hd];
__device__ float g_shift[Hd];

// ---------------- helpers ----------------
__device__ __forceinline__ void mma_f16(float* c, const uint32_t* a, const uint32_t* b) {
    asm volatile(
        "mma.sync.aligned.m16n8k16.row.col.f32.f16.f16.f32 "
        "{%0,%1,%2,%3}, {%4,%5,%6,%7}, {%8,%9}, {%0,%1,%2,%3};"
        : "+f"(c[0]), "+f"(c[1]), "+f"(c[2]), "+f"(c[3])
        : "r"(a[0]), "r"(a[1]), "r"(a[2]), "r"(a[3]), "r"(b[0]), "r"(b[1]));
}
__device__ __forceinline__ uint32_t pack_h2(float a, float b) {
    __half2 h = __floats2half2_rn(a, b);
    return *(uint32_t*)&h;
}

// ---------------- graph build ----------------
__global__ void k_init() {
    int i = blockIdx.x * blockDim.x + threadIdx.x;
    if (i < Nn) { g_deg[i] = 0; g_cnt[i] = 0; }
}

__global__ void k_count(const int* __restrict__ ei) {
    int e = blockIdx.x * blockDim.x + threadIdx.x;
    if (e < Ee) {
        int s = ei[e];
        int d = ei[e + Ee];
        if ((unsigned)s < Nn) atomicAdd(&g_deg[s], 1);
        if ((unsigned)d < Nn) atomicAdd(&g_cnt[d], 1);
    }
}

__global__ void k_dinv() {
    int i = blockIdx.x * blockDim.x + threadIdx.x;
    if (i < Nn) {
        int d = g_deg[i];
        g_dinv[i] = (d > 0) ? rsqrtf((float)d) : 0.0f;
    }
}

__global__ void k_scan1() {
    __shared__ int sd[1024];
    int b = blockIdx.x, tid = threadIdx.x;
    int i = b * 1024 + tid;
    int v = (i < Nn) ? g_cnt[i] : 0;
    sd[tid] = v;
    __syncthreads();
    for (int off = 1; off < 1024; off <<= 1) {
        int t = (tid >= off) ? sd[tid - off] : 0;
        __syncthreads();
        sd[tid] += t;
        __syncthreads();
    }
    if (i < Nn) g_rowptr[i + 1] = sd[tid];
    if (tid == 1023) g_bsum[b] = sd[1023];
}
__global__ void k_scan2() {
    if (threadIdx.x == 0) {
        int acc = 0;
        for (int b = 0; b < SCB; b++) { g_boff[b] = acc; acc += g_bsum[b]; }
        g_rowptr[0] = 0;
    }
}
__global__ void k_scan3() {
    int i = blockIdx.x * blockDim.x + threadIdx.x;
    if (i < Nn) {
        int r = g_rowptr[i + 1] + g_boff[i >> 10];
        g_rowptr[i + 1] = r;
        g_tmpptr[i] = r - g_cnt[i];
    }
}

__global__ void k_fill(const int* __restrict__ ei) {
    int e = blockIdx.x * blockDim.x + threadIdx.x;
    if (e < Ee) {
        int s = ei[e];
        int d = ei[e + Ee];
        if ((unsigned)s >= Nn || (unsigned)d >= Nn) return;
        int p = atomicAdd(&g_tmpptr[d], 1);
        float w = -g_dinv[s] * g_dinv[d];
        g_epk[p] = make_int2(s, __float_as_int(w));
    }
}

// ---------------- propagation ----------------
__global__ void k_prop3(const float* __restrict__ hin,
                        const float* __restrict__ sub,
                        float* __restrict__ out) {
    int v = blockIdx.x * blockDim.x + threadIdx.x;
    if (v >= Nn) return;
    float a0 = 0.f, a1 = 0.f, a2 = 0.f;
    int b = g_rowptr[v], en = g_rowptr[v + 1];
    for (int i = b; i < en; i++) {
        int2 e = g_epk[i];
        float w = __int_as_float(e.y);
        const float* hp = hin + e.x * 3;
        a0 += w * hp[0]; a1 += w * hp[1]; a2 += w * hp[2];
    }
    float* o = out + v * 3;
    if (sub) {
        const float* sv = sub + v * 3;
        o[0] = 2.f * a0 - sv[0]; o[1] = 2.f * a1 - sv[1]; o[2] = 2.f * a2 - sv[2];
    } else {
        o[0] = a0; o[1] = a1; o[2] = a2;
    }
}

// warp per node. mode: 0 = plain (optional sub), 1 = BN on hin (no sub),
// 2 = BN on sub (hin plain).
__global__ void k_prop128(const float* __restrict__ hin,
                          const float* __restrict__ sub,
                          float* __restrict__ out,
                          const float* __restrict__ sc,
                          const float* __restrict__ sh,
                          int mode) {
    int v = blockIdx.x * 4 + (threadIdx.x >> 5);
    if (v >= Nn) return;
    int lane = threadIdx.x & 31;
    float4 sc4, sh4;
    if (mode) {
        sc4 = ((const float4*)sc)[lane];
        sh4 = ((const float4*)sh)[lane];
    }
    int b = g_rowptr[v], en = g_rowptr[v + 1];
    float4 acc = make_float4(0.f, 0.f, 0.f, 0.f);
    float wsum = 0.f;
    int i = b;
    for (; i + 1 < en; i += 2) {
        int2 e0 = g_epk[i];
        int2 e1 = g_epk[i + 1];
        float w0 = __int_as_float(e0.y);
        float w1 = __int_as_float(e1.y);
        float4 v0 = *(const float4*)(hin + e0.x * Hd + lane * 4);
        float4 v1 = *(const float4*)(hin + e1.x * Hd + lane * 4);
        acc.x += w0 * v0.x + w1 * v1.x;
        acc.y += w0 * v0.y + w1 * v1.y;
        acc.z += w0 * v0.z + w1 * v1.z;
        acc.w += w0 * v0.w + w1 * v1.w;
        wsum += w0 + w1;
    }
    if (i < en) {
        int2 e = g_epk[i];
        float w = __int_as_float(e.y);
        float4 g = *(const float4*)(hin + e.x * Hd + lane * 4);
        acc.x += w * g.x; acc.y += w * g.y; acc.z += w * g.z; acc.w += w * g.w;
        wsum += w;
    }
    float4 r;
    if (mode == 1) {
        r.x = sc4.x * acc.x + sh4.x * wsum;
        r.y = sc4.y * acc.y + sh4.y * wsum;
        r.z = sc4.z * acc.z + sh4.z * wsum;
        r.w = sc4.w * acc.w + sh4.w * wsum;
    } else if (mode == 2) {
        float4 sv = *(const float4*)(sub + v * Hd + lane * 4);
        r.x = 2.f * acc.x - (sc4.x * sv.x + sh4.x);
        r.y = 2.f * acc.y - (sc4.y * sv.y + sh4.y);
        r.z = 2.f * acc.z - (sc4.z * sv.z + sh4.z);
        r.w = 2.f * acc.w - (sc4.w * sv.w + sh4.w);
    } else if (sub) {
        float4 sv = *(const float4*)(sub + v * Hd + lane * 4);
        r.x = 2.f * acc.x - sv.x; r.y = 2.f * acc.y - sv.y;
        r.z = 2.f * acc.z - sv.z; r.w = 2.f * acc.w - sv.w;
    } else {
        r = acc;
    }
    *(float4*)(out + v * Hd + lane * 4) = r;
}

// ---------------- layer 1 GEMM: K=12 (+ fused stats partials) ----------------
__global__ void k_gemm12(const float* __restrict__ x,  const float* __restrict__ t1,
                         const float* __restrict__ t2, const float* __restrict__ t3,
                         const float* __restrict__ W,  const float* __restrict__ bias,
                         float* __restrict__ out) {
    __shared__ float sW[12 * Hd];
    int c = threadIdx.x;
    #pragma unroll
    for (int j = 0; j < 12; j++) sW[j * Hd + c] = W[j * Hd + c];
    __syncthreads();
    const int RPB = 32;
    int v0 = blockIdx.x * RPB;
    float bv = bias[c];
    float s = 0.f, s2 = 0.f;
    for (int r = 0; r < RPB; r++) {
        int v = v0 + r;
        if (v >= Nn) break;
        float a[12];
        #pragma unroll
        for (int f = 0; f < 3; f++) {
            a[f]     = x [v * 3 + f];
            a[3 + f] = t1[v * 3 + f];
            a[6 + f] = t2[v * 3 + f];
            a[9 + f] = t3[v * 3 + f];
        }
        float acc = bv;
        #pragma unroll
        for (int j = 0; j < 12; j++) acc += a[j] * sW[j * Hd + c];
        acc = (acc > 0.f) ? acc : 0.01f * acc;   // leaky relu
        out[v * Hd + c] = acc;
        s += acc; s2 += acc * acc;
    }
    g_part [blockIdx.x * Hd + c] = s;
    g_part2[blockIdx.x * Hd + c] = s2;
}

// ---------------- tensor-core GEMM (mma.sync fp16 m16n8k16) + fused epilogues
// mode: 1 = leaky+stats, 2 = relu+stats, 0 = no-act + row-L2-normalize
#define BM 128
#define BK 16
#define ASTR2 12      // 8 k-pairs + 4 pad words: frag banks (grp*12+tig) bijective
#define BSTR2 136     // frag banks 8*tig + grp, conflict-free

__global__ __launch_bounds__(256)
void k_gemm_mma(const float* __restrict__ A0, const float* __restrict__ A1,
                const float* __restrict__ A2, const float* __restrict__ A3,
                const float* __restrict__ W,  const float* __restrict__ bias,
                float* __restrict__ out,
                const float* __restrict__ scA, const float* __restrict__ shA,
                int mode) {
    __shared__ uint32_t As[BM][ASTR2];   // half2 (k-pair) per word, m-major
    __shared__ uint32_t Bs[8][BSTR2];    // [kpair][col] half2 along k
    __shared__ float sred [8][64];
    __shared__ float sred2[8][64];
    __shared__ float rows2[2][BM];
    const float* Abuf[4] = {A0, A1, A2, A3};

    int tid = threadIdx.x;
    int wid = tid >> 5;
    int lane = tid & 31;
    int grp = lane >> 2;       // 0..7
    int tig = lane & 3;        // 0..3
    int m_base = (wid >> 1) * 32;
    int n_base = (wid & 1) * 64;
    int row0 = blockIdx.x * BM;

    float c[2][8][4];
    #pragma unroll
    for (int mi = 0; mi < 2; mi++)
        #pragma unroll
        for (int ni = 0; ni < 8; ni++)
            #pragma unroll
            for (int q = 0; q < 4; q++) c[mi][ni][q] = 0.f;

    int la_r  = tid >> 1;              // 0..127
    int la_c4 = (tid & 1) * 8;         // float offset 0 or 8
    int lb_k  = tid >> 5;              // kpair 0..7
    int lb_c4 = (tid & 31) * 4;        // col 0..124

    for (int kt = 0; kt < 32; kt++) {
        const float* A = Abuf[kt >> 3];
        int cb = (kt & 7) * BK;
        // ---- A tile: 128 rows x 16 k, packed to half2 k-pairs ----
        {
            int gr = row0 + la_r;
            float4 v0 = make_float4(0.f,0.f,0.f,0.f), v1 = v0;
            if (gr < Nn) {
                const float4* src = (const float4*)(A + gr * Hd + cb + la_c4);
                v0 = src[0]; v1 = src[1];
            }
            if (scA && (kt >> 3) == 0) {   // A0 = BN(h) applied inline
                float4 s0 = *(const float4*)(scA + cb + la_c4);
                float4 s1 = *(const float4*)(scA + cb + la_c4 + 4);
                float4 h0 = *(const float4*)(shA + cb + la_c4);
                float4 h1 = *(const float4*)(shA + cb + la_c4 + 4);
                v0.x = v0.x * s0.x + h0.x; v0.y = v0.y * s0.y + h0.y;
                v0.z = v0.z * s0.z + h0.z; v0.w = v0.w * s0.w + h0.w;
                v1.x = v1.x * s1.x + h1.x; v1.y = v1.y * s1.y + h1.y;
                v1.z = v1.z * s1.z + h1.z; v1.w = v1.w * s1.w + h1.w;
                if (gr >= Nn) { v0 = make_float4(0,0,0,0); v1 = v0; }
            }
            uint4 u;
            u.x = pack_h2(v0.x, v0.y);
            u.y = pack_h2(v0.z, v0.w);
            u.z = pack_h2(v1.x, v1.y);
            u.w = pack_h2(v1.z, v1.w);
            *(uint4*)&As[la_r][la_c4 >> 1] = u;   // kpairs la_c4/2 .. +3
        }
        // ---- B tile: 16 k x 128 n, packed half2 along k ----
        {
            const float4* s0 = (const float4*)(W + (kt * BK + 2 * lb_k) * Hd + lb_c4);
            const float4* s1 = (const float4*)(W + (kt * BK + 2 * lb_k + 1) * Hd + lb_c4);
            float4 r0 = s0[0], r1 = s1[0];
            uint4 u;
            u.x = pack_h2(r0.x, r1.x);
            u.y = pack_h2(r0.y, r1.y);
            u.z = pack_h2(r0.z, r1.z);
            u.w = pack_h2(r0.w, r1.w);
            *(uint4*)&Bs[lb_k][lb_c4] = u;
        }
        __syncthreads();
        // ---- one m16n8k16 k-step covers full BK=16 ----
        {
            uint32_t a[2][4], b[8][2];
            #pragma unroll
            for (int mi = 0; mi < 2; mi++) {
                int m0 = m_base + mi * 16 + grp;
                a[mi][0] = As[m0][tig];
                a[mi][1] = As[m0 + 8][tig];
                a[mi][2] = As[m0][tig + 4];
                a[mi][3] = As[m0 + 8][tig + 4];
            }
            #pragma unroll
            for (int ni = 0; ni < 8; ni++) {
                int nc = n_base + ni * 8 + grp;
                b[ni][0] = Bs[tig][nc];
                b[ni][1] = Bs[tig + 4][nc];
            }
            #pragma unroll
            for (int mi = 0; mi < 2; mi++)
                #pragma unroll
                for (int ni = 0; ni < 8; ni++)
                    mma_f16(c[mi][ni], a[mi], b[ni]);
        }
        __syncthreads();
    }

    // ---- bias + activation (zero invalid rows) ----
    #pragma unroll
    for (int mi = 0; mi < 2; mi++) {
        #pragma unroll
        for (int half = 0; half < 2; half++) {
            int row = row0 + m_base + mi * 16 + grp + half * 8;
            bool valid = row < Nn;
            #pragma unroll
            for (int ni = 0; ni < 8; ni++) {
                #pragma unroll
                for (int par = 0; par < 2; par++) {
                    int q = half * 2 + par;
                    int col = n_base + ni * 8 + tig * 2 + par;
                    float f = c[mi][ni][q] + __ldg(bias + col);
                    if (mode == 1)      f = (f > 0.f) ? f : 0.01f * f;
                    else if (mode == 2) f = fmaxf(f, 0.f);
                    c[mi][ni][q] = valid ? f : 0.f;
                }
            }
        }
    }

    float rscale[2][2] = {{1.f,1.f},{1.f,1.f}};

    if (mode != 0) {
        // ---- fused BN stats partials (deterministic) ----
        float ls[8][2], ls2[8][2];
        #pragma unroll
        for (int ni = 0; ni < 8; ni++)
            #pragma unroll
            for (int par = 0; par < 2; par++) {
                float s = 0.f, s2 = 0.f;
                #pragma unroll
                for (int mi = 0; mi < 2; mi++)
                    #pragma unroll
                    for (int half = 0; half < 2; half++) {
                        float f = c[mi][ni][half * 2 + par];
                        s += f; s2 += f * f;
                    }
                ls[ni][par] = s; ls2[ni][par] = s2;
            }
        #pragma unroll
        for (int off = 4; off < 32; off <<= 1) {
            #pragma unroll
            for (int ni = 0; ni < 8; ni++)
                #pragma unroll
                for (int par = 0; par < 2; par++) {
                    ls [ni][par] += __shfl_xor_sync(0xffffffffu, ls [ni][par], off);
                    ls2[ni][par] += __shfl_xor_sync(0xffffffffu, ls2[ni][par], off);
                }
        }
        if (lane < 4) {
            #pragma unroll
            for (int ni = 0; ni < 8; ni++)
                #pragma unroll
                for (int par = 0; par < 2; par++) {
                    sred [wid][ni * 8 + tig * 2 + par] = ls [ni][par];
                    sred2[wid][ni * 8 + tig * 2 + par] = ls2[ni][par];
                }
        }
        __syncthreads();
        if (tid < Hd) {
            int hf = tid >> 6, cl = tid & 63;
            float s = 0.f, s2 = 0.f;
            #pragma unroll
            for (int j = 0; j < 4; j++) {
                s  += sred [2 * j + hf][cl];
                s2 += sred2[2 * j + hf][cl];
            }
            g_part [blockIdx.x * Hd + tid] = s;
            g_part2[blockIdx.x * Hd + tid] = s2;
        }
    } else {
        // ---- fused row L2 normalize ----
        #pragma unroll
        for (int mi = 0; mi < 2; mi++)
            #pragma unroll
            for (int half = 0; half < 2; half++) {
                float rsq = 0.f;
                #pragma unroll
                for (int ni = 0; ni < 8; ni++) {
                    float f0 = c[mi][ni][half * 2 + 0];
                    float f1 = c[mi][ni][half * 2 + 1];
                    rsq += f0 * f0 + f1 * f1;
                }
                rsq += __shfl_xor_sync(0xffffffffu, rsq, 1);
                rsq += __shfl_xor_sync(0xffffffffu, rsq, 2);
                if (tig == 0)
                    rows2[wid & 1][m_base + mi * 16 + grp + half * 8] = rsq;
            }
        __syncthreads();
        #pragma unroll
        for (int mi = 0; mi < 2; mi++)
            #pragma unroll
            for (int half = 0; half < 2; half++) {
                int rl = m_base + mi * 16 + grp + half * 8;
                float tot = rows2[0][rl] + rows2[1][rl];
                rscale[mi][half] = 1.f / fmaxf(sqrtf(tot), 1e-12f);
            }
    }

    // ---- store ----
    #pragma unroll
    for (int mi = 0; mi < 2; mi++) {
        #pragma unroll
        for (int half = 0; half < 2; half++) {
            int row = row0 + m_base + mi * 16 + grp + half * 8;
            if (row < Nn) {
                float rs = rscale[mi][half];
                #pragma unroll
                for (int ni = 0; ni < 8; ni++) {
                    int col = n_base + ni * 8 + tig * 2;
                    float f0 = c[mi][ni][half * 2 + 0] * rs;
                    float f1 = c[mi][ni][half * 2 + 1] * rs;
                    *(float2*)(out + row * Hd + col) = make_float2(f0, f1);
                }
            }
        }
    }
}

// ---------------- BN finalize (parallel: one block per channel) -------------
__global__ void k_bnfin(const float* __restrict__ gamma, const float* __restrict__ beta,
                        int nb) {
    int c = blockIdx.x;          // channel 0..127
    int t = threadIdx.x;         // 256 threads
    float s = 0.f, s2 = 0.f;
    for (int b = t; b < nb; b += 256) {
        s  += g_part [b * Hd + c];
        s2 += g_part2[b * Hd + c];
    }
    __shared__ float ss[256], ss2[256];
    ss[t] = s; ss2[t] = s2;
    __syncthreads();
    #pragma unroll
    for (int off = 128; off; off >>= 1) {
        if (t < off) { ss[t] += ss[t + off]; ss2[t] += ss2[t + off]; }
        __syncthreads();
    }
    if (t == 0) {
        float m   = ss[0] / (float)Nn;
        float var = ss2[0] / (float)Nn - m * m;
        float inv = rsqrtf(var + 1e-5f);
        float sc  = gamma[c] * inv;
        g_scale[c] = sc;
        g_shift[c] = beta[c] - m * sc;
    }
}

// ---------------- host ----------------
extern "C" void kernel_launch(void* const* d_in, const int* in_sizes, int n_in,
                              void* d_out, int out_size) {
    const float* x  = (const float*)d_in[0];
    const int*   ei = (const int*)d_in[1];   // int32 (JAX x64 disabled)
    const float* W1 = (const float*)d_in[2];  const float* b1 = (const float*)d_in[3];
    const float* W2 = (const float*)d_in[4];  const float* b2 = (const float*)d_in[5];
    const float* W3 = (const float*)d_in[6];  const float* b3 = (const float*)d_in[7];
    const float* W4 = (const float*)d_in[8];  const float* b4 = (const float*)d_in[9];
    const float* g1 = (const float*)d_in[10]; const float* be1 = (const float*)d_in[11];
    const float* g2 = (const float*)d_in[12]; const float* be2 = (const float*)d_in[13];
    const float* g3 = (const float*)d_in[14]; const float* be3 = (const float*)d_in[15];

    float *p_t1, *p_t2, *p_t3, *p_out, *p_s1, *p_s2, *p_s3, *p_sc, *p_sh;
    cudaGetSymbolAddress((void**)&p_t1,  g_t1);
    cudaGetSymbolAddress((void**)&p_t2,  g_t2);
    cudaGetSymbolAddress((void**)&p_t3,  g_t3);
    cudaGetSymbolAddress((void**)&p_out, g_out);
    cudaGetSymbolAddress((void**)&p_s1,  g_s1);
    cudaGetSymbolAddress((void**)&p_s2,  g_s2);
    cudaGetSymbolAddress((void**)&p_s3,  g_s3);
    cudaGetSymbolAddress((void**)&p_sc,  g_scale);
    cudaGetSymbolAddress((void**)&p_sh,  g_shift);

    const int TB = 256;
    // graph build
    k_init <<<(Nn + TB - 1) / TB, TB>>>();
    k_count<<<(Ee + TB - 1) / TB, TB>>>(ei);
    k_dinv <<<(Nn + TB - 1) / TB, TB>>>();
    k_scan1<<<SCB, 1024>>>();
    k_scan2<<<1, 64>>>();
    k_scan3<<<(Nn + TB - 1) / TB, TB>>>();
    k_fill <<<(Ee + TB - 1) / TB, TB>>>(ei);

    int gP128 = (Nn + 3) / 4;
    int gGemm = (Nn + BM - 1) / BM;      // 391
    int g12   = (Nn + 31) / 32;          // 1563

    // layer 1 (F=3)
    k_prop3<<<(Nn + TB - 1) / TB, TB>>>(x, nullptr, p_s1);
    k_prop3<<<(Nn + TB - 1) / TB, TB>>>(p_s1, x, p_s2);
    k_prop3<<<(Nn + TB - 1) / TB, TB>>>(p_s2, p_s1, p_s3);
    k_gemm12<<<g12, Hd>>>(x, p_s1, p_s2, p_s3, W1, b1, p_out);
    k_bnfin<<<Hd, 256>>>(g1, be1, g12);

    // layer 2 (props consume BN(h) via fused scale/shift)
    k_prop128<<<gP128, 128>>>(p_out, nullptr, p_t1, p_sc, p_sh, 1);
    k_prop128<<<gP128, 128>>>(p_t1, p_out, p_t2, p_sc, p_sh, 2);
    k_prop128<<<gP128, 128>>>(p_t2, p_t1, p_t3, nullptr, nullptr, 0);
    k_gemm_mma<<<gGemm, 256>>>(p_out, p_t1, p_t2, p_t3, W2, b2, p_out, p_sc, p_sh, 1);
    k_bnfin<<<Hd, 256>>>(g2, be2, gGemm);

    // layer 3
    k_prop128<<<gP128, 128>>>(p_out, nullptr, p_t1, p_sc, p_sh, 1);
    k_prop128<<<gP128, 128>>>(p_t1, p_out, p_t2, p_sc, p_sh, 2);
    k_prop128<<<gP128, 128>>>(p_t2, p_t1, p_t3, nullptr, nullptr, 0);
    k_gemm_mma<<<gGemm, 256>>>(p_out, p_t1, p_t2, p_t3, W3, b3, p_out, p_sc, p_sh, 2);
    k_bnfin<<<Hd, 256>>>(g3, be3, gGemm);

    // layer 4: props + GEMM with fused row-normalize, straight to d_out
    k_prop128<<<gP128, 128>>>(p_out, nullptr, p_t1, p_sc, p_sh, 1);
    k_prop128<<<gP128, 128>>>(p_t1, p_out, p_t2, p_sc, p_sh, 2);
    k_prop128<<<gP128, 128>>>(p_t2, p_t1, p_t3, nullptr, nullptr, 0);
    k_gemm_mma<<<gGemm, 256>>>(p_out, p_t1, p_t2, p_t3, W4, b4, (float*)d_out,
                               p_sc, p_sh, 0);
}

// round 11
// speedup vs baseline: 1.4970x; 1.0268x over previous
#include <cuda_runtime.h>
#include <cuda_bf16.h>
#include <cuda_fp16.h>
#include <cstdint>

#define Nn 50000
#define Ee 800000
#define Hd 128
#define SCB 49       // scan blocks (ceil(Nn/1024))
#define PMAX 1600    // max stats-partial blocks (gemm12 uses 1563)

// ---------------- scratch ----------------
__device__ int   g_deg[Nn];
__device__ int   g_cnt[Nn];
__device__ int   g_rowptr[Nn + 1];
__device__ int   g_tmpptr[Nn];
__device__ float g_dinv[Nn];
__device__ int2  g_epk[Ee];          // (src, weight-bits)
__device__ int   g_bsum[SCB];
__device__ int   g_boff[SCB];

__device__ __align__(256) float g_t1[Nn * Hd];
__device__ __align__(256) float g_t2[Nn * Hd];
__device__ __align__(256) float g_t3[Nn * Hd];
__device__ __align__(256) float g_out[Nn * Hd];

__device__ float g_s1[Nn * 3];
__device__ float g_s2[Nn * 3];
__device__ float g_s3[Nn * 3];

__device__ float g_part [PMAX * Hd];
__device__ float g_part2[PMAX * Hd];
__device__ float g_scale[Hd];
__device__ float g_shift[Hd];

// ---------------- helpers ----------------
__device__ __forceinline__ void mma_f16(float* c, const uint32_t* a, const uint32_t* b) {
    asm volatile(
        "mma.sync.aligned.m16n8k16.row.col.f32.f16.f16.f32 "
        "{%0,%1,%2,%3}, {%4,%5,%6,%7}, {%8,%9}, {%0,%1,%2,%3};"
        : "+f"(c[0]), "+f"(c[1]), "+f"(c[2]), "+f"(c[3])
        : "r"(a[0]), "r"(a[1]), "r"(a[2]), "r"(a[3]), "r"(b[0]), "r"(b[1]));
}
__device__ __forceinline__ uint32_t pack_h2(float a, float b) {
    __half2 h = __floats2half2_rn(a, b);
    return *(uint32_t*)&h;
}

// ---------------- graph build ----------------
__global__ void k_init() {
    int i = blockIdx.x * blockDim.x + threadIdx.x;
    if (i < Nn) { g_deg[i] = 0; g_cnt[i] = 0; }
}

__global__ void k_count(const int* __restrict__ ei) {
    int e = blockIdx.x * blockDim.x + threadIdx.x;
    if (e < Ee) {
        int s = ei[e];
        int d = ei[e + Ee];
        if ((unsigned)s < Nn) atomicAdd(&g_deg[s], 1);
        if ((unsigned)d < Nn) atomicAdd(&g_cnt[d], 1);
    }
}

__global__ void k_scan1() {
    __shared__ int sd[1024];
    int b = blockIdx.x, tid = threadIdx.x;
    int i = b * 1024 + tid;
    int v = (i < Nn) ? g_cnt[i] : 0;
    sd[tid] = v;
    __syncthreads();
    for (int off = 1; off < 1024; off <<= 1) {
        int t = (tid >= off) ? sd[tid - off] : 0;
        __syncthreads();
        sd[tid] += t;
        __syncthreads();
    }
    if (i < Nn) g_rowptr[i + 1] = sd[tid];
    if (tid == 1023) g_bsum[b] = sd[1023];
}
__global__ void k_scan2() {
    if (threadIdx.x == 0) {
        int acc = 0;
        for (int b = 0; b < SCB; b++) { g_boff[b] = acc; acc += g_bsum[b]; }
        g_rowptr[0] = 0;
    }
}
// scan finalize + dinv (deg final after k_count)
__global__ void k_scan3() {
    int i = blockIdx.x * blockDim.x + threadIdx.x;
    if (i < Nn) {
        int r = g_rowptr[i + 1] + g_boff[i >> 10];
        g_rowptr[i + 1] = r;
        g_tmpptr[i] = r - g_cnt[i];
        int d = g_deg[i];
        g_dinv[i] = (d > 0) ? rsqrtf((float)d) : 0.0f;
    }
}

__global__ void k_fill(const int* __restrict__ ei) {
    int e = blockIdx.x * blockDim.x + threadIdx.x;
    if (e < Ee) {
        int s = ei[e];
        int d = ei[e + Ee];
        if ((unsigned)s >= Nn || (unsigned)d >= Nn) return;
        int p = atomicAdd(&g_tmpptr[d], 1);
        float w = -g_dinv[s] * g_dinv[d];
        g_epk[p] = make_int2(s, __float_as_int(w));
    }
}

// ---------------- propagation ----------------
__global__ void k_prop3(const float* __restrict__ hin,
                        const float* __restrict__ sub,
                        float* __restrict__ out) {
    int v = blockIdx.x * blockDim.x + threadIdx.x;
    if (v >= Nn) return;
    float a0 = 0.f, a1 = 0.f, a2 = 0.f;
    int b = g_rowptr[v], en = g_rowptr[v + 1];
    for (int i = b; i < en; i++) {
        int2 e = g_epk[i];
        float w = __int_as_float(e.y);
        const float* hp = hin + e.x * 3;
        a0 += w * hp[0]; a1 += w * hp[1]; a2 += w * hp[2];
    }
    float* o = out + v * 3;
    if (sub) {
        const float* sv = sub + v * 3;
        o[0] = 2.f * a0 - sv[0]; o[1] = 2.f * a1 - sv[1]; o[2] = 2.f * a2 - sv[2];
    } else {
        o[0] = a0; o[1] = a1; o[2] = a2;
    }
}

// warp per node. mode: 0 = plain (optional sub), 1 = BN on hin (no sub),
// 2 = BN on sub (hin plain).
__global__ void k_prop128(const float* __restrict__ hin,
                          const float* __restrict__ sub,
                          float* __restrict__ out,
                          const float* __restrict__ sc,
                          const float* __restrict__ sh,
                          int mode) {
    int v = blockIdx.x * 4 + (threadIdx.x >> 5);
    if (v >= Nn) return;
    int lane = threadIdx.x & 31;
    float4 sc4, sh4;
    if (mode) {
        sc4 = ((const float4*)sc)[lane];
        sh4 = ((const float4*)sh)[lane];
    }
    int b = g_rowptr[v], en = g_rowptr[v + 1];
    float4 acc = make_float4(0.f, 0.f, 0.f, 0.f);
    float wsum = 0.f;
    int i = b;
    for (; i + 1 < en; i += 2) {
        int2 e0 = g_epk[i];
        int2 e1 = g_epk[i + 1];
        float w0 = __int_as_float(e0.y);
        float w1 = __int_as_float(e1.y);
        float4 v0 = *(const float4*)(hin + e0.x * Hd + lane * 4);
        float4 v1 = *(const float4*)(hin + e1.x * Hd + lane * 4);
        acc.x += w0 * v0.x + w1 * v1.x;
        acc.y += w0 * v0.y + w1 * v1.y;
        acc.z += w0 * v0.z + w1 * v1.z;
        acc.w += w0 * v0.w + w1 * v1.w;
        wsum += w0 + w1;
    }
    if (i < en) {
        int2 e = g_epk[i];
        float w = __int_as_float(e.y);
        float4 g = *(const float4*)(hin + e.x * Hd + lane * 4);
        acc.x += w * g.x; acc.y += w * g.y; acc.z += w * g.z; acc.w += w * g.w;
        wsum += w;
    }
    float4 r;
    if (mode == 1) {
        r.x = sc4.x * acc.x + sh4.x * wsum;
        r.y = sc4.y * acc.y + sh4.y * wsum;
        r.z = sc4.z * acc.z + sh4.z * wsum;
        r.w = sc4.w * acc.w + sh4.w * wsum;
    } else if (mode == 2) {
        float4 sv = *(const float4*)(sub + v * Hd + lane * 4);
        r.x = 2.f * acc.x - (sc4.x * sv.x + sh4.x);
        r.y = 2.f * acc.y - (sc4.y * sv.y + sh4.y);
        r.z = 2.f * acc.z - (sc4.z * sv.z + sh4.z);
        r.w = 2.f * acc.w - (sc4.w * sv.w + sh4.w);
    } else if (sub) {
        float4 sv = *(const float4*)(sub + v * Hd + lane * 4);
        r.x = 2.f * acc.x - sv.x; r.y = 2.f * acc.y - sv.y;
        r.z = 2.f * acc.z - sv.z; r.w = 2.f * acc.w - sv.w;
    } else {
        r = acc;
    }
    *(float4*)(out + v * Hd + lane * 4) = r;
}

// ---------------- layer 1 GEMM: K=12 (+ fused stats partials) ----------------
__global__ void k_gemm12(const float* __restrict__ x,  const float* __restrict__ t1,
                         const float* __restrict__ t2, const float* __restrict__ t3,
                         const float* __restrict__ W,  const float* __restrict__ bias,
                         float* __restrict__ out) {
    __shared__ float sW[12 * Hd];
    int c = threadIdx.x;
    #pragma unroll
    for (int j = 0; j < 12; j++) sW[j * Hd + c] = W[j * Hd + c];
    __syncthreads();
    const int RPB = 32;
    int v0 = blockIdx.x * RPB;
    float bv = bias[c];
    float s = 0.f, s2 = 0.f;
    for (int r = 0; r < RPB; r++) {
        int v = v0 + r;
        if (v >= Nn) break;
        float a[12];
        #pragma unroll
        for (int f = 0; f < 3; f++) {
            a[f]     = x [v * 3 + f];
            a[3 + f] = t1[v * 3 + f];
            a[6 + f] = t2[v * 3 + f];
            a[9 + f] = t3[v * 3 + f];
        }
        float acc = bv;
        #pragma unroll
        for (int j = 0; j < 12; j++) acc += a[j] * sW[j * Hd + c];
        acc = (acc > 0.f) ? acc : 0.01f * acc;   // leaky relu
        out[v * Hd + c] = acc;
        s += acc; s2 += acc * acc;
    }
    g_part [blockIdx.x * Hd + c] = s;
    g_part2[blockIdx.x * Hd + c] = s2;
}

// ---------------- tensor-core GEMM (fp16 m16n8k16, 2-stage pipeline) --------
// mode: 1 = leaky+stats, 2 = relu+stats, 0 = no-act + row-L2-normalize
#define BM 128
#define BK 16
#define ASTR2 12      // 8 k-pairs + 4 pad words
#define BSTR2 136     // frag banks 8*tig + grp, conflict-free

__global__ __launch_bounds__(256, 2)
void k_gemm_mma(const float* __restrict__ A0, const float* __restrict__ A1,
                const float* __restrict__ A2, const float* __restrict__ A3,
                const float* __restrict__ W,  const float* __restrict__ bias,
                float* __restrict__ out,
                const float* __restrict__ scA, const float* __restrict__ shA,
                int mode) {
    __shared__ uint32_t As[2][BM][ASTR2];   // half2 (k-pair) per word, m-major
    __shared__ uint32_t Bs[2][8][BSTR2];    // [kpair][col] half2 along k
    __shared__ float sred [8][64];
    __shared__ float sred2[8][64];
    __shared__ float rows2[2][BM];
    const float* Abuf[4] = {A0, A1, A2, A3};

    int tid = threadIdx.x;
    int wid = tid >> 5;
    int lane = tid & 31;
    int grp = lane >> 2;       // 0..7
    int tig = lane & 3;        // 0..3
    int m_base = (wid >> 1) * 32;
    int n_base = (wid & 1) * 64;
    int row0 = blockIdx.x * BM;

    float c[2][8][4];
    #pragma unroll
    for (int mi = 0; mi < 2; mi++)
        #pragma unroll
        for (int ni = 0; ni < 8; ni++)
            #pragma unroll
            for (int q = 0; q < 4; q++) c[mi][ni][q] = 0.f;

    int la_r  = tid >> 1;              // 0..127
    int la_c4 = (tid & 1) * 8;         // float offset 0 or 8
    int lb_k  = tid >> 5;              // kpair 0..7
    int lb_c4 = (tid & 31) * 4;        // col 0..124

    // ---- stage loader: global -> packed regs ----
    auto load_stage = [&](int kt, uint4& ua, uint4& ub) {
        const float* A = Abuf[kt >> 3];
        int cb = (kt & 7) * BK;
        int gr = row0 + la_r;
        float4 v0 = make_float4(0.f,0.f,0.f,0.f), v1 = v0;
        if (gr < Nn) {
            const float4* src = (const float4*)(A + gr * Hd + cb + la_c4);
            v0 = src[0]; v1 = src[1];
        }
        if (scA && (kt >> 3) == 0) {
            float4 s0 = *(const float4*)(scA + cb + la_c4);
            float4 s1 = *(const float4*)(scA + cb + la_c4 + 4);
            float4 h0 = *(const float4*)(shA + cb + la_c4);
            float4 h1 = *(const float4*)(shA + cb + la_c4 + 4);
            v0.x = v0.x * s0.x + h0.x; v0.y = v0.y * s0.y + h0.y;
            v0.z = v0.z * s0.z + h0.z; v0.w = v0.w * s0.w + h0.w;
            v1.x = v1.x * s1.x + h1.x; v1.y = v1.y * s1.y + h1.y;
            v1.z = v1.z * s1.z + h1.z; v1.w = v1.w * s1.w + h1.w;
            if (gr >= Nn) { v0 = make_float4(0,0,0,0); v1 = v0; }
        }
        ua.x = pack_h2(v0.x, v0.y);
        ua.y = pack_h2(v0.z, v0.w);
        ua.z = pack_h2(v1.x, v1.y);
        ua.w = pack_h2(v1.z, v1.w);
        const float4* s0 = (const float4*)(W + (kt * BK + 2 * lb_k) * Hd + lb_c4);
        const float4* s1 = (const float4*)(W + (kt * BK + 2 * lb_k + 1) * Hd + lb_c4);
        float4 r0 = s0[0], r1 = s1[0];
        ub.x = pack_h2(r0.x, r1.x);
        ub.y = pack_h2(r0.y, r1.y);
        ub.z = pack_h2(r0.z, r1.z);
        ub.w = pack_h2(r0.w, r1.w);
    };

    // prologue
    {
        uint4 ua, ub;
        load_stage(0, ua, ub);
        *(uint4*)&As[0][la_r][la_c4 >> 1] = ua;
        *(uint4*)&Bs[0][lb_k][lb_c4] = ub;
    }
    __syncthreads();

    for (int kt = 0; kt < 32; kt++) {
        int cur = kt & 1, nxt = cur ^ 1;
        uint4 na, nb;
        if (kt < 31) load_stage(kt + 1, na, nb);
        // ---- mma from current buffer ----
        {
            uint32_t a[2][4], b[8][2];
            #pragma unroll
            for (int mi = 0; mi < 2; mi++) {
                int m0 = m_base + mi * 16 + grp;
                a[mi][0] = As[cur][m0][tig];
                a[mi][1] = As[cur][m0 + 8][tig];
                a[mi][2] = As[cur][m0][tig + 4];
                a[mi][3] = As[cur][m0 + 8][tig + 4];
            }
            #pragma unroll
            for (int ni = 0; ni < 8; ni++) {
                int nc = n_base + ni * 8 + grp;
                b[ni][0] = Bs[cur][tig][nc];
                b[ni][1] = Bs[cur][tig + 4][nc];
            }
            #pragma unroll
            for (int mi = 0; mi < 2; mi++)
                #pragma unroll
                for (int ni = 0; ni < 8; ni++)
                    mma_f16(c[mi][ni], a[mi], b[ni]);
        }
        if (kt < 31) {
            *(uint4*)&As[nxt][la_r][la_c4 >> 1] = na;
            *(uint4*)&Bs[nxt][lb_k][lb_c4] = nb;
        }
        __syncthreads();
    }

    // ---- bias + activation (zero invalid rows) ----
    #pragma unroll
    for (int mi = 0; mi < 2; mi++) {
        #pragma unroll
        for (int half = 0; half < 2; half++) {
            int row = row0 + m_base + mi * 16 + grp + half * 8;
            bool valid = row < Nn;
            #pragma unroll
            for (int ni = 0; ni < 8; ni++) {
                #pragma unroll
                for (int par = 0; par < 2; par++) {
                    int q = half * 2 + par;
                    int col = n_base + ni * 8 + tig * 2 + par;
                    float f = c[mi][ni][q] + __ldg(bias + col);
                    if (mode == 1)      f = (f > 0.f) ? f : 0.01f * f;
                    else if (mode == 2) f = fmaxf(f, 0.f);
                    c[mi][ni][q] = valid ? f : 0.f;
                }
            }
        }
    }

    float rscale[2][2] = {{1.f,1.f},{1.f,1.f}};

    if (mode != 0) {
        // ---- fused BN stats partials (deterministic) ----
        float ls[8][2], ls2[8][2];
        #pragma unroll
        for (int ni = 0; ni < 8; ni++)
            #pragma unroll
            for (int par = 0; par < 2; par++) {
                float s = 0.f, s2 = 0.f;
                #pragma unroll
                for (int mi = 0; mi < 2; mi++)
                    #pragma unroll
                    for (int half = 0; half < 2; half++) {
                        float f = c[mi][ni][half * 2 + par];
                        s += f; s2 += f * f;
                    }
                ls[ni][par] = s; ls2[ni][par] = s2;
            }
        #pragma unroll
        for (int off = 4; off < 32; off <<= 1) {
            #pragma unroll
            for (int ni = 0; ni < 8; ni++)
                #pragma unroll
                for (int par = 0; par < 2; par++) {
                    ls [ni][par] += __shfl_xor_sync(0xffffffffu, ls [ni][par], off);
                    ls2[ni][par] += __shfl_xor_sync(0xffffffffu, ls2[ni][par], off);
                }
        }
        if (lane < 4) {
            #pragma unroll
            for (int ni = 0; ni < 8; ni++)
                #pragma unroll
                for (int par = 0; par < 2; par++) {
                    sred [wid][ni * 8 + tig * 2 + par] = ls [ni][par];
                    sred2[wid][ni * 8 + tig * 2 + par] = ls2[ni][par];
                }
        }
        __syncthreads();
        if (tid < Hd) {
            int hf = tid >> 6, cl = tid & 63;
            float s = 0.f, s2 = 0.f;
            #pragma unroll
            for (int j = 0; j < 4; j++) {
                s  += sred [2 * j + hf][cl];
                s2 += sred2[2 * j + hf][cl];
            }
            g_part [blockIdx.x * Hd + tid] = s;
            g_part2[blockIdx.x * Hd + tid] = s2;
        }
    } else {
        // ---- fused row L2 normalize ----
        #pragma unroll
        for (int mi = 0; mi < 2; mi++)
            #pragma unroll
            for (int half = 0; half < 2; half++) {
                float rsq = 0.f;
                #pragma unroll
                for (int ni = 0; ni < 8; ni++) {
                    float f0 = c[mi][ni][half * 2 + 0];
                    float f1 = c[mi][ni][half * 2 + 1];
                    rsq += f0 * f0 + f1 * f1;
                }
                rsq += __shfl_xor_sync(0xffffffffu, rsq, 1);
                rsq += __shfl_xor_sync(0xffffffffu, rsq, 2);
                if (tig == 0)
                    rows2[wid & 1][m_base + mi * 16 + grp + half * 8] = rsq;
            }
        __syncthreads();
        #pragma unroll
        for (int mi = 0; mi < 2; mi++)
            #pragma unroll
            for (int half = 0; half < 2; half++) {
                int rl = m_base + mi * 16 + grp + half * 8;
                float tot = rows2[0][rl] + rows2[1][rl];
                rscale[mi][half] = 1.f / fmaxf(sqrtf(tot), 1e-12f);
            }
    }

    // ---- store ----
    #pragma unroll
    for (int mi = 0; mi < 2; mi++) {
        #pragma unroll
        for (int half = 0; half < 2; half++) {
            int row = row0 + m_base + mi * 16 + grp + half * 8;
            if (row < Nn) {
                float rs = rscale[mi][half];
                #pragma unroll
                for (int ni = 0; ni < 8; ni++) {
                    int col = n_base + ni * 8 + tig * 2;
                    float f0 = c[mi][ni][half * 2 + 0] * rs;
                    float f1 = c[mi][ni][half * 2 + 1] * rs;
                    *(float2*)(out + row * Hd + col) = make_float2(f0, f1);
                }
            }
        }
    }
}

// ---------------- BN finalize (parallel: one block per channel) -------------
__global__ void k_bnfin(const float* __restrict__ gamma, const float* __restrict__ beta,
                        int nb) {
    int c = blockIdx.x;          // channel 0..127
    int t = threadIdx.x;         // 256 threads
    float s = 0.f, s2 = 0.f;
    for (int b = t; b < nb; b += 256) {
        s  += g_part [b * Hd + c];
        s2 += g_part2[b * Hd + c];
    }
    __shared__ float ss[256], ss2[256];
    ss[t] = s; ss2[t] = s2;
    __syncthreads();
    #pragma unroll
    for (int off = 128; off; off >>= 1) {
        if (t < off) { ss[t] += ss[t + off]; ss2[t] += ss2[t + off]; }
        __syncthreads();
    }
    if (t == 0) {
        float m   = ss[0] / (float)Nn;
        float var = ss2[0] / (float)Nn - m * m;
        float inv = rsqrtf(var + 1e-5f);
        float sc  = gamma[c] * inv;
        g_scale[c] = sc;
        g_shift[c] = beta[c] - m * sc;
    }
}

// ---------------- host ----------------
extern "C" void kernel_launch(void* const* d_in, const int* in_sizes, int n_in,
                              void* d_out, int out_size) {
    const float* x  = (const float*)d_in[0];
    const int*   ei = (const int*)d_in[1];   // int32 (JAX x64 disabled)
    const float* W1 = (const float*)d_in[2];  const float* b1 = (const float*)d_in[3];
    const float* W2 = (const float*)d_in[4];  const float* b2 = (const float*)d_in[5];
    const float* W3 = (const float*)d_in[6];  const float* b3 = (const float*)d_in[7];
    const float* W4 = (const float*)d_in[8];  const float* b4 = (const float*)d_in[9];
    const float* g1 = (const float*)d_in[10]; const float* be1 = (const float*)d_in[11];
    const float* g2 = (const float*)d_in[12]; const float* be2 = (const float*)d_in[13];
    const float* g3 = (const float*)d_in[14]; const float* be3 = (const float*)d_in[15];

    float *p_t1, *p_t2, *p_t3, *p_out, *p_s1, *p_s2, *p_s3, *p_sc, *p_sh;
    cudaGetSymbolAddress((void**)&p_t1,  g_t1);
    cudaGetSymbolAddress((void**)&p_t2,  g_t2);
    cudaGetSymbolAddress((void**)&p_t3,  g_t3);
    cudaGetSymbolAddress((void**)&p_out, g_out);
    cudaGetSymbolAddress((void**)&p_s1,  g_s1);
    cudaGetSymbolAddress((void**)&p_s2,  g_s2);
    cudaGetSymbolAddress((void**)&p_s3,  g_s3);
    cudaGetSymbolAddress((void**)&p_sc,  g_scale);
    cudaGetSymbolAddress((void**)&p_sh,  g_shift);

    const int TB = 256;
    // graph build
    k_init <<<(Nn + TB - 1) / TB, TB>>>();
    k_count<<<(Ee + TB - 1) / TB, TB>>>(ei);
    k_scan1<<<SCB, 1024>>>();
    k_scan2<<<1, 64>>>();
    k_scan3<<<(Nn + TB - 1) / TB, TB>>>();
    k_fill <<<(Ee + TB - 1) / TB, TB>>>(ei);

    int gP128 = (Nn + 3) / 4;
    int gGemm = (Nn + BM - 1) / BM;      // 391
    int g12   = (Nn + 31) / 32;          // 1563

    // layer 1 (F=3)
    k_prop3<<<(Nn + TB - 1) / TB, TB>>>(x, nullptr, p_s1);
    k_prop3<<<(Nn + TB - 1) / TB, TB>>>(p_s1, x, p_s2);
    k_prop3<<<(Nn + TB - 1) / TB, TB>>>(p_s2, p_s1, p_s3);
    k_gemm12<<<g12, Hd>>>(x, p_s1, p_s2, p_s3, W1, b1, p_out);
    k_bnfin<<<Hd, 256>>>(g1, be1, g12);

    // layer 2 (props consume BN(h) via fused scale/shift)
    k_prop128<<<gP128, 128>>>(p_out, nullptr, p_t1, p_sc, p_sh, 1);
    k_prop128<<<gP128, 128>>>(p_t1, p_out, p_t2, p_sc, p_sh, 2);
    k_prop128<<<gP128, 128>>>(p_t2, p_t1, p_t3, nullptr, nullptr, 0);
    k_gemm_mma<<<gGemm, 256>>>(p_out, p_t1, p_t2, p_t3, W2, b2, p_out, p_sc, p_sh, 1);
    k_bnfin<<<Hd, 256>>>(g2, be2, gGemm);

    // layer 3
    k_prop128<<<gP128, 128>>>(p_out, nullptr, p_t1, p_sc, p_sh, 1);
    k_prop128<<<gP128, 128>>>(p_t1, p_out, p_t2, p_sc, p_sh, 2);
    k_prop128<<<gP128, 128>>>(p_t2, p_t1, p_t3, nullptr, nullptr, 0);
    k_gemm_mma<<<gGemm, 256>>>(p_out, p_t1, p_t2, p_t3, W3, b3, p_out, p_sc, p_sh, 2);
    k_bnfin<<<Hd, 256>>>(g3, be3, gGemm);

    // layer 4: props + GEMM with fused row-normalize, straight to d_out
    k_prop128<<<gP128, 128>>>(p_out, nullptr, p_t1, p_sc, p_sh, 1);
    k_prop128<<<gP128, 128>>>(p_t1, p_out, p_t2, p_sc, p_sh, 2);
    k_prop128<<<gP128, 128>>>(p_t2, p_t1, p_t3, nullptr, nullptr, 0);
    k_gemm_mma<<<gGemm, 256>>>(p_out, p_t1, p_t2, p_t3, W4, b4, (float*)d_out,
                               p_sc, p_sh, 0);
}

// round 12
// speedup vs baseline: 1.5119x; 1.0099x over previous
#include <cuda_runtime.h>
#include <cuda_bf16.h>
#include <cuda_fp16.h>
#include <cstdint>

#define Nn 50000
#define Ee 800000
#define Hd 128
#define SCB 49       // scan blocks (ceil(Nn/1024))
#define PMAX 1600    // max stats-partial blocks (gemm12 uses 1563)

// ---------------- scratch ----------------
__device__ int   g_deg[Nn];
__device__ int   g_cnt[Nn];
__device__ int   g_rowptr[Nn + 1];
__device__ int   g_tmpptr[Nn];
__device__ float g_dinv[Nn];
__device__ int2  g_epk[Ee];          // (src, weight-bits)
__device__ int   g_bsum[SCB];
__device__ int   g_boff[SCB];

__device__ __align__(256) float g_t1[Nn * Hd];
__device__ __align__(256) float g_t2[Nn * Hd];
__device__ __align__(256) float g_t3[Nn * Hd];
__device__ __align__(256) float g_out[Nn * Hd];

// pre-packed fp16 weights in Bs[kt][kpair][col] layout (32*8*128 words each)
__device__ __align__(256) uint32_t g_wh[3][32 * 8 * 128];

__device__ float g_s1[Nn * 3];
__device__ float g_s2[Nn * 3];
__device__ float g_s3[Nn * 3];

__device__ float g_part [PMAX * Hd];
__device__ float g_part2[PMAX * Hd];
__device__ float g_scale[Hd];
__device__ float g_shift[Hd];

// ---------------- helpers ----------------
__device__ __forceinline__ void mma_f16(float* c, const uint32_t* a, const uint32_t* b) {
    asm volatile(
        "mma.sync.aligned.m16n8k16.row.col.f32.f16.f16.f32 "
        "{%0,%1,%2,%3}, {%4,%5,%6,%7}, {%8,%9}, {%0,%1,%2,%3};"
        : "+f"(c[0]), "+f"(c[1]), "+f"(c[2]), "+f"(c[3])
        : "r"(a[0]), "r"(a[1]), "r"(a[2]), "r"(a[3]), "r"(b[0]), "r"(b[1]));
}
__device__ __forceinline__ uint32_t pack_h2(float a, float b) {
    __half2 h = __floats2half2_rn(a, b);
    return *(uint32_t*)&h;
}

// ---------------- graph build ----------------
__global__ void k_init() {
    int i = blockIdx.x * blockDim.x + threadIdx.x;
    if (i < Nn) { g_deg[i] = 0; g_cnt[i] = 0; }
}

__global__ void k_count(const int* __restrict__ ei) {
    int e = blockIdx.x * blockDim.x + threadIdx.x;
    if (e < Ee) {
        int s = ei[e];
        int d = ei[e + Ee];
        if ((unsigned)s < Nn) atomicAdd(&g_deg[s], 1);
        if ((unsigned)d < Nn) atomicAdd(&g_cnt[d], 1);
    }
}

__global__ void k_scan1() {
    __shared__ int sd[1024];
    int b = blockIdx.x, tid = threadIdx.x;
    int i = b * 1024 + tid;
    int v = (i < Nn) ? g_cnt[i] : 0;
    sd[tid] = v;
    __syncthreads();
    for (int off = 1; off < 1024; off <<= 1) {
        int t = (tid >= off) ? sd[tid - off] : 0;
        __syncthreads();
        sd[tid] += t;
        __syncthreads();
    }
    if (i < Nn) g_rowptr[i + 1] = sd[tid];
    if (tid == 1023) g_bsum[b] = sd[1023];
}
// parallel scan over 49 block sums (64 threads)
__global__ void k_scan2() {
    __shared__ int sd[64];
    int t = threadIdx.x;
    int v = (t < SCB) ? g_bsum[t] : 0;
    sd[t] = v;
    __syncthreads();
    #pragma unroll
    for (int off = 1; off < 64; off <<= 1) {
        int u = (t >= off) ? sd[t - off] : 0;
        __syncthreads();
        sd[t] += u;
        __syncthreads();
    }
    if (t < SCB) g_boff[t] = sd[t] - v;   // exclusive
    if (t == 0) g_rowptr[0] = 0;
}
// scan finalize + dinv (deg final after k_count)
__global__ void k_scan3() {
    int i = blockIdx.x * blockDim.x + threadIdx.x;
    if (i < Nn) {
        int r = g_rowptr[i + 1] + g_boff[i >> 10];
        g_rowptr[i + 1] = r;
        g_tmpptr[i] = r - g_cnt[i];
        int d = g_deg[i];
        g_dinv[i] = (d > 0) ? rsqrtf((float)d) : 0.0f;
    }
}

__global__ void k_fill(const int* __restrict__ ei) {
    int e = blockIdx.x * blockDim.x + threadIdx.x;
    if (e < Ee) {
        int s = ei[e];
        int d = ei[e + Ee];
        if ((unsigned)s >= Nn || (unsigned)d >= Nn) return;
        int p = atomicAdd(&g_tmpptr[d], 1);
        float w = -g_dinv[s] * g_dinv[d];
        g_epk[p] = make_int2(s, __float_as_int(w));
    }
}

// pre-pack W[512][128] fp32 -> half2 k-pair layout [kt][kpair][col]
__global__ void k_wpack(const float* __restrict__ W, uint32_t* __restrict__ out) {
    int idx = blockIdx.x * blockDim.x + threadIdx.x;
    if (idx < 32 * 8 * 128) {
        int col = idx & 127;
        int kp  = (idx >> 7) & 7;
        int kt  = idx >> 10;
        int k0  = kt * 16 + 2 * kp;
        out[idx] = pack_h2(W[k0 * Hd + col], W[(k0 + 1) * Hd + col]);
    }
}

// ---------------- propagation ----------------
__global__ void k_prop3(const float* __restrict__ hin,
                        const float* __restrict__ sub,
                        float* __restrict__ out) {
    int v = blockIdx.x * blockDim.x + threadIdx.x;
    if (v >= Nn) return;
    float a0 = 0.f, a1 = 0.f, a2 = 0.f;
    int b = g_rowptr[v], en = g_rowptr[v + 1];
    for (int i = b; i < en; i++) {
        int2 e = g_epk[i];
        float w = __int_as_float(e.y);
        const float* hp = hin + e.x * 3;
        a0 += w * hp[0]; a1 += w * hp[1]; a2 += w * hp[2];
    }
    float* o = out + v * 3;
    if (sub) {
        const float* sv = sub + v * 3;
        o[0] = 2.f * a0 - sv[0]; o[1] = 2.f * a1 - sv[1]; o[2] = 2.f * a2 - sv[2];
    } else {
        o[0] = a0; o[1] = a1; o[2] = a2;
    }
}

// warp per node. mode: 0 = plain (optional sub), 1 = BN on hin (no sub),
// 2 = BN on sub (hin plain).
__global__ void k_prop128(const float* __restrict__ hin,
                          const float* __restrict__ sub,
                          float* __restrict__ out,
                          const float* __restrict__ sc,
                          const float* __restrict__ sh,
                          int mode) {
    int v = blockIdx.x * 4 + (threadIdx.x >> 5);
    if (v >= Nn) return;
    int lane = threadIdx.x & 31;
    float4 sc4, sh4;
    if (mode) {
        sc4 = ((const float4*)sc)[lane];
        sh4 = ((const float4*)sh)[lane];
    }
    int b = g_rowptr[v], en = g_rowptr[v + 1];
    float4 acc = make_float4(0.f, 0.f, 0.f, 0.f);
    float wsum = 0.f;
    int i = b;
    for (; i + 1 < en; i += 2) {
        int2 e0 = g_epk[i];
        int2 e1 = g_epk[i + 1];
        float w0 = __int_as_float(e0.y);
        float w1 = __int_as_float(e1.y);
        float4 v0 = *(const float4*)(hin + e0.x * Hd + lane * 4);
        float4 v1 = *(const float4*)(hin + e1.x * Hd + lane * 4);
        acc.x += w0 * v0.x + w1 * v1.x;
        acc.y += w0 * v0.y + w1 * v1.y;
        acc.z += w0 * v0.z + w1 * v1.z;
        acc.w += w0 * v0.w + w1 * v1.w;
        wsum += w0 + w1;
    }
    if (i < en) {
        int2 e = g_epk[i];
        float w = __int_as_float(e.y);
        float4 g = *(const float4*)(hin + e.x * Hd + lane * 4);
        acc.x += w * g.x; acc.y += w * g.y; acc.z += w * g.z; acc.w += w * g.w;
        wsum += w;
    }
    float4 r;
    if (mode == 1) {
        r.x = sc4.x * acc.x + sh4.x * wsum;
        r.y = sc4.y * acc.y + sh4.y * wsum;
        r.z = sc4.z * acc.z + sh4.z * wsum;
        r.w = sc4.w * acc.w + sh4.w * wsum;
    } else if (mode == 2) {
        float4 sv = *(const float4*)(sub + v * Hd + lane * 4);
        r.x = 2.f * acc.x - (sc4.x * sv.x + sh4.x);
        r.y = 2.f * acc.y - (sc4.y * sv.y + sh4.y);
        r.z = 2.f * acc.z - (sc4.z * sv.z + sh4.z);
        r.w = 2.f * acc.w - (sc4.w * sv.w + sh4.w);
    } else if (sub) {
        float4 sv = *(const float4*)(sub + v * Hd + lane * 4);
        r.x = 2.f * acc.x - sv.x; r.y = 2.f * acc.y - sv.y;
        r.z = 2.f * acc.z - sv.z; r.w = 2.f * acc.w - sv.w;
    } else {
        r = acc;
    }
    *(float4*)(out + v * Hd + lane * 4) = r;
}

// ---------------- layer 1 GEMM: K=12 (+ fused stats partials) ----------------
__global__ void k_gemm12(const float* __restrict__ x,  const float* __restrict__ t1,
                         const float* __restrict__ t2, const float* __restrict__ t3,
                         const float* __restrict__ W,  const float* __restrict__ bias,
                         float* __restrict__ out) {
    __shared__ float sW[12 * Hd];
    int c = threadIdx.x;
    #pragma unroll
    for (int j = 0; j < 12; j++) sW[j * Hd + c] = W[j * Hd + c];
    __syncthreads();
    const int RPB = 32;
    int v0 = blockIdx.x * RPB;
    float bv = bias[c];
    float s = 0.f, s2 = 0.f;
    for (int r = 0; r < RPB; r++) {
        int v = v0 + r;
        if (v >= Nn) break;
        float a[12];
        #pragma unroll
        for (int f = 0; f < 3; f++) {
            a[f]     = x [v * 3 + f];
            a[3 + f] = t1[v * 3 + f];
            a[6 + f] = t2[v * 3 + f];
            a[9 + f] = t3[v * 3 + f];
        }
        float acc = bv;
        #pragma unroll
        for (int j = 0; j < 12; j++) acc += a[j] * sW[j * Hd + c];
        acc = (acc > 0.f) ? acc : 0.01f * acc;   // leaky relu
        out[v * Hd + c] = acc;
        s += acc; s2 += acc * acc;
    }
    g_part [blockIdx.x * Hd + c] = s;
    g_part2[blockIdx.x * Hd + c] = s2;
}

// ---------------- tensor-core GEMM (fp16 m16n8k16, 2-stage pipeline) --------
// B pre-packed in g_wh layout. mode: 1 = leaky+stats, 2 = relu+stats,
// 0 = no-act + row-L2-normalize
#define BM 128
#define BK 16
#define ASTR2 12      // 8 k-pairs + 4 pad words
#define BSTR2 136     // frag banks 8*tig + grp, conflict-free

__global__ __launch_bounds__(256, 2)
void k_gemm_mma(const float* __restrict__ A0, const float* __restrict__ A1,
                const float* __restrict__ A2, const float* __restrict__ A3,
                const uint32_t* __restrict__ Wp, const float* __restrict__ bias,
                float* __restrict__ out,
                const float* __restrict__ scA, const float* __restrict__ shA,
                int mode) {
    __shared__ uint32_t As[2][BM][ASTR2];   // half2 (k-pair) per word, m-major
    __shared__ uint32_t Bs[2][8][BSTR2];    // [kpair][col] half2 along k
    __shared__ float sred [8][64];
    __shared__ float sred2[8][64];
    __shared__ float rows2[2][BM];
    const float* Abuf[4] = {A0, A1, A2, A3};

    int tid = threadIdx.x;
    int wid = tid >> 5;
    int lane = tid & 31;
    int grp = lane >> 2;       // 0..7
    int tig = lane & 3;        // 0..3
    int m_base = (wid >> 1) * 32;
    int n_base = (wid & 1) * 64;
    int row0 = blockIdx.x * BM;

    float c[2][8][4];
    #pragma unroll
    for (int mi = 0; mi < 2; mi++)
        #pragma unroll
        for (int ni = 0; ni < 8; ni++)
            #pragma unroll
            for (int q = 0; q < 4; q++) c[mi][ni][q] = 0.f;

    int la_r  = tid >> 1;              // 0..127
    int la_c4 = (tid & 1) * 8;         // float offset 0 or 8
    int lb_k  = tid >> 5;              // kpair 0..7
    int lb_c4 = (tid & 31) * 4;        // col 0..124

    // ---- stage loader: global -> packed regs ----
    auto load_stage = [&](int kt, uint4& ua, uint4& ub) {
        const float* A = Abuf[kt >> 3];
        int cb = (kt & 7) * BK;
        int gr = row0 + la_r;
        float4 v0 = make_float4(0.f,0.f,0.f,0.f), v1 = v0;
        if (gr < Nn) {
            const float4* src = (const float4*)(A + gr * Hd + cb + la_c4);
            v0 = src[0]; v1 = src[1];
        }
        if (scA && (kt >> 3) == 0) {
            float4 s0 = *(const float4*)(scA + cb + la_c4);
            float4 s1 = *(const float4*)(scA + cb + la_c4 + 4);
            float4 h0 = *(const float4*)(shA + cb + la_c4);
            float4 h1 = *(const float4*)(shA + cb + la_c4 + 4);
            v0.x = v0.x * s0.x + h0.x; v0.y = v0.y * s0.y + h0.y;
            v0.z = v0.z * s0.z + h0.z; v0.w = v0.w * s0.w + h0.w;
            v1.x = v1.x * s1.x + h1.x; v1.y = v1.y * s1.y + h1.y;
            v1.z = v1.z * s1.z + h1.z; v1.w = v1.w * s1.w + h1.w;
            if (gr >= Nn) { v0 = make_float4(0,0,0,0); v1 = v0; }
        }
        ua.x = pack_h2(v0.x, v0.y);
        ua.y = pack_h2(v0.z, v0.w);
        ua.z = pack_h2(v1.x, v1.y);
        ua.w = pack_h2(v1.z, v1.w);
        ub = *(const uint4*)(Wp + kt * 1024 + lb_k * 128 + lb_c4);
    };

    // prologue
    {
        uint4 ua, ub;
        load_stage(0, ua, ub);
        *(uint4*)&As[0][la_r][la_c4 >> 1] = ua;
        *(uint4*)&Bs[0][lb_k][lb_c4] = ub;
    }
    __syncthreads();

    for (int kt = 0; kt < 32; kt++) {
        int cur = kt & 1, nxt = cur ^ 1;
        uint4 na, nb;
        if (kt < 31) load_stage(kt + 1, na, nb);
        // ---- mma from current buffer ----
        {
            uint32_t a[2][4], b[8][2];
            #pragma unroll
            for (int mi = 0; mi < 2; mi++) {
                int m0 = m_base + mi * 16 + grp;
                a[mi][0] = As[cur][m0][tig];
                a[mi][1] = As[cur][m0 + 8][tig];
                a[mi][2] = As[cur][m0][tig + 4];
                a[mi][3] = As[cur][m0 + 8][tig + 4];
            }
            #pragma unroll
            for (int ni = 0; ni < 8; ni++) {
                int nc = n_base + ni * 8 + grp;
                b[ni][0] = Bs[cur][tig][nc];
                b[ni][1] = Bs[cur][tig + 4][nc];
            }
            #pragma unroll
            for (int mi = 0; mi < 2; mi++)
                #pragma unroll
                for (int ni = 0; ni < 8; ni++)
                    mma_f16(c[mi][ni], a[mi], b[ni]);
        }
        if (kt < 31) {
            *(uint4*)&As[nxt][la_r][la_c4 >> 1] = na;
            *(uint4*)&Bs[nxt][lb_k][lb_c4] = nb;
        }
        __syncthreads();
    }

    // ---- bias + activation (zero invalid rows) ----
    #pragma unroll
    for (int mi = 0; mi < 2; mi++) {
        #pragma unroll
        for (int half = 0; half < 2; half++) {
            int row = row0 + m_base + mi * 16 + grp + half * 8;
            bool valid = row < Nn;
            #pragma unroll
            for (int ni = 0; ni < 8; ni++) {
                #pragma unroll
                for (int par = 0; par < 2; par++) {
                    int q = half * 2 + par;
                    int col = n_base + ni * 8 + tig * 2 + par;
                    float f = c[mi][ni][q] + __ldg(bias + col);
                    if (mode == 1)      f = (f > 0.f) ? f : 0.01f * f;
                    else if (mode == 2) f = fmaxf(f, 0.f);
                    c[mi][ni][q] = valid ? f : 0.f;
                }
            }
        }
    }

    float rscale[2][2] = {{1.f,1.f},{1.f,1.f}};

    if (mode != 0) {
        // ---- fused BN stats partials (deterministic) ----
        float ls[8][2], ls2[8][2];
        #pragma unroll
        for (int ni = 0; ni < 8; ni++)
            #pragma unroll
            for (int par = 0; par < 2; par++) {
                float s = 0.f, s2 = 0.f;
                #pragma unroll
                for (int mi = 0; mi < 2; mi++)
                    #pragma unroll
                    for (int half = 0; half < 2; half++) {
                        float f = c[mi][ni][half * 2 + par];
                        s += f; s2 += f * f;
                    }
                ls[ni][par] = s; ls2[ni][par] = s2;
            }
        #pragma unroll
        for (int off = 4; off < 32; off <<= 1) {
            #pragma unroll
            for (int ni = 0; ni < 8; ni++)
                #pragma unroll
                for (int par = 0; par < 2; par++) {
                    ls [ni][par] += __shfl_xor_sync(0xffffffffu, ls [ni][par], off);
                    ls2[ni][par] += __shfl_xor_sync(0xffffffffu, ls2[ni][par], off);
                }
        }
        if (lane < 4) {
            #pragma unroll
            for (int ni = 0; ni < 8; ni++)
                #pragma unroll
                for (int par = 0; par < 2; par++) {
                    sred [wid][ni * 8 + tig * 2 + par] = ls [ni][par];
                    sred2[wid][ni * 8 + tig * 2 + par] = ls2[ni][par];
                }
        }
        __syncthreads();
        if (tid < Hd) {
            int hf = tid >> 6, cl = tid & 63;
            float s = 0.f, s2 = 0.f;
            #pragma unroll
            for (int j = 0; j < 4; j++) {
                s  += sred [2 * j + hf][cl];
                s2 += sred2[2 * j + hf][cl];
            }
            g_part [blockIdx.x * Hd + tid] = s;
            g_part2[blockIdx.x * Hd + tid] = s2;
        }
    } else {
        // ---- fused row L2 normalize ----
        #pragma unroll
        for (int mi = 0; mi < 2; mi++)
            #pragma unroll
            for (int half = 0; half < 2; half++) {
                float rsq = 0.f;
                #pragma unroll
                for (int ni = 0; ni < 8; ni++) {
                    float f0 = c[mi][ni][half * 2 + 0];
                    float f1 = c[mi][ni][half * 2 + 1];
                    rsq += f0 * f0 + f1 * f1;
                }
                rsq += __shfl_xor_sync(0xffffffffu, rsq, 1);
                rsq += __shfl_xor_sync(0xffffffffu, rsq, 2);
                if (tig == 0)
                    rows2[wid & 1][m_base + mi * 16 + grp + half * 8] = rsq;
            }
        __syncthreads();
        #pragma unroll
        for (int mi = 0; mi < 2; mi++)
            #pragma unroll
            for (int half = 0; half < 2; half++) {
                int rl = m_base + mi * 16 + grp + half * 8;
                float tot = rows2[0][rl] + rows2[1][rl];
                rscale[mi][half] = 1.f / fmaxf(sqrtf(tot), 1e-12f);
            }
    }

    // ---- store ----
    #pragma unroll
    for (int mi = 0; mi < 2; mi++) {
        #pragma unroll
        for (int half = 0; half < 2; half++) {
            int row = row0 + m_base + mi * 16 + grp + half * 8;
            if (row < Nn) {
                float rs = rscale[mi][half];
                #pragma unroll
                for (int ni = 0; ni < 8; ni++) {
                    int col = n_base + ni * 8 + tig * 2;
                    float f0 = c[mi][ni][half * 2 + 0] * rs;
                    float f1 = c[mi][ni][half * 2 + 1] * rs;
                    *(float2*)(out + row * Hd + col) = make_float2(f0, f1);
                }
            }
        }
    }
}

// ---------------- BN finalize (parallel: one block per channel) -------------
__global__ void k_bnfin(const float* __restrict__ gamma, const float* __restrict__ beta,
                        int nb) {
    int c = blockIdx.x;          // channel 0..127
    int t = threadIdx.x;         // 256 threads
    float s = 0.f, s2 = 0.f;
    for (int b = t; b < nb; b += 256) {
        s  += g_part [b * Hd + c];
        s2 += g_part2[b * Hd + c];
    }
    __shared__ float ss[256], ss2[256];
    ss[t] = s; ss2[t] = s2;
    __syncthreads();
    #pragma unroll
    for (int off = 128; off; off >>= 1) {
        if (t < off) { ss[t] += ss[t + off]; ss2[t] += ss2[t + off]; }
        __syncthreads();
    }
    if (t == 0) {
        float m   = ss[0] / (float)Nn;
        float var = ss2[0] / (float)Nn - m * m;
        float inv = rsqrtf(var + 1e-5f);
        float sc  = gamma[c] * inv;
        g_scale[c] = sc;
        g_shift[c] = beta[c] - m * sc;
    }
}

// ---------------- host ----------------
extern "C" void kernel_launch(void* const* d_in, const int* in_sizes, int n_in,
                              void* d_out, int out_size) {
    const float* x  = (const float*)d_in[0];
    const int*   ei = (const int*)d_in[1];   // int32 (JAX x64 disabled)
    const float* W1 = (const float*)d_in[2];  const float* b1 = (const float*)d_in[3];
    const float* W2 = (const float*)d_in[4];  const float* b2 = (const float*)d_in[5];
    const float* W3 = (const float*)d_in[6];  const float* b3 = (const float*)d_in[7];
    const float* W4 = (const float*)d_in[8];  const float* b4 = (const float*)d_in[9];
    const float* g1 = (const float*)d_in[10]; const float* be1 = (const float*)d_in[11];
    const float* g2 = (const float*)d_in[12]; const float* be2 = (const float*)d_in[13];
    const float* g3 = (const float*)d_in[14]; const float* be3 = (const float*)d_in[15];

    float *p_t1, *p_t2, *p_t3, *p_out, *p_s1, *p_s2, *p_s3, *p_sc, *p_sh;
    uint32_t* p_wh;
    cudaGetSymbolAddress((void**)&p_t1,  g_t1);
    cudaGetSymbolAddress((void**)&p_t2,  g_t2);
    cudaGetSymbolAddress((void**)&p_t3,  g_t3);
    cudaGetSymbolAddress((void**)&p_out, g_out);
    cudaGetSymbolAddress((void**)&p_s1,  g_s1);
    cudaGetSymbolAddress((void**)&p_s2,  g_s2);
    cudaGetSymbolAddress((void**)&p_s3,  g_s3);
    cudaGetSymbolAddress((void**)&p_sc,  g_scale);
    cudaGetSymbolAddress((void**)&p_sh,  g_shift);
    cudaGetSymbolAddress((void**)&p_wh,  g_wh);

    const int TB = 256;
    const int WPW = 32 * 8 * 128;        // words per packed weight
    // graph build
    k_init <<<(Nn + TB - 1) / TB, TB>>>();
    k_count<<<(Ee + TB - 1) / TB, TB>>>(ei);
    k_scan1<<<SCB, 1024>>>();
    k_scan2<<<1, 64>>>();
    k_scan3<<<(Nn + TB - 1) / TB, TB>>>();
    k_fill <<<(Ee + TB - 1) / TB, TB>>>(ei);

    // pre-pack weights to fp16
    k_wpack<<<(WPW + TB - 1) / TB, TB>>>(W2, p_wh + 0 * WPW);
    k_wpack<<<(WPW + TB - 1) / TB, TB>>>(W3, p_wh + 1 * WPW);
    k_wpack<<<(WPW + TB - 1) / TB, TB>>>(W4, p_wh + 2 * WPW);

    int gP128 = (Nn + 3) / 4;
    int gGemm = (Nn + BM - 1) / BM;      // 391
    int g12   = (Nn + 31) / 32;          // 1563

    // layer 1 (F=3)
    k_prop3<<<(Nn + TB - 1) / TB, TB>>>(x, nullptr, p_s1);
    k_prop3<<<(Nn + TB - 1) / TB, TB>>>(p_s1, x, p_s2);
    k_prop3<<<(Nn + TB - 1) / TB, TB>>>(p_s2, p_s1, p_s3);
    k_gemm12<<<g12, Hd>>>(x, p_s1, p_s2, p_s3, W1, b1, p_out);
    k_bnfin<<<Hd, 256>>>(g1, be1, g12);

    // layer 2 (props consume BN(h) via fused scale/shift)
    k_prop128<<<gP128, 128>>>(p_out, nullptr, p_t1, p_sc, p_sh, 1);
    k_prop128<<<gP128, 128>>>(p_t1, p_out, p_t2, p_sc, p_sh, 2);
    k_prop128<<<gP128, 128>>>(p_t2, p_t1, p_t3, nullptr, nullptr, 0);
    k_gemm_mma<<<gGemm, 256>>>(p_out, p_t1, p_t2, p_t3, p_wh + 0 * WPW, b2, p_out, p_sc, p_sh, 1);
    k_bnfin<<<Hd, 256>>>(g2, be2, gGemm);

    // layer 3
    k_prop128<<<gP128, 128>>>(p_out, nullptr, p_t1, p_sc, p_sh, 1);
    k_prop128<<<gP128, 128>>>(p_t1, p_out, p_t2, p_sc, p_sh, 2);
    k_prop128<<<gP128, 128>>>(p_t2, p_t1, p_t3, nullptr, nullptr, 0);
    k_gemm_mma<<<gGemm, 256>>>(p_out, p_t1, p_t2, p_t3, p_wh + 1 * WPW, b3, p_out, p_sc, p_sh, 2);
    k_bnfin<<<Hd, 256>>>(g3, be3, gGemm);

    // layer 4: props + GEMM with fused row-normalize, straight to d_out
    k_prop128<<<gP128, 128>>>(p_out, nullptr, p_t1, p_sc, p_sh, 1);
    k_prop128<<<gP128, 128>>>(p_t1, p_out, p_t2, p_sc, p_sh, 2);
    k_prop128<<<gP128, 128>>>(p_t2, p_t1, p_t3, nullptr, nullptr, 0);
    k_gemm_mma<<<gGemm, 256>>>(p_out, p_t1, p_t2, p_t3, p_wh + 2 * WPW, b4, (float*)d_out,
                               p_sc, p_sh, 0);
}

// round 13
// speedup vs baseline: 1.5685x; 1.0375x over previous
#include <cuda_runtime.h>
#include <cuda_bf16.h>
#include <cuda_fp16.h>
#include <cstdint>

#define Nn 50000
#define Ee 800000
#define Hd 128
#define SCB 49       // scan blocks (ceil(Nn/1024))
#define PMAX 1600    // max stats-partial blocks (gemm12 uses 1563)

// ---------------- scratch ----------------
__device__ int   g_deg[Nn];
__device__ int   g_cnt[Nn];
__device__ int   g_rowptr[Nn + 1];
__device__ int   g_tmpptr[Nn];
__device__ float g_dinv[Nn];
__device__ int2  g_epk[Ee];          // (src, weight-bits)
__device__ int   g_bsum[SCB];
__device__ int   g_boff[SCB];

__device__ __align__(256) float g_t1[Nn * Hd];
__device__ __align__(256) float g_t2[Nn * Hd];
__device__ __align__(256) float g_t3[Nn * Hd];
__device__ __align__(256) float g_out[Nn * Hd];

// pre-packed fp16 combined weights in Bs[kt][kpair][col] layout
__device__ __align__(256) uint32_t g_wh[3][32 * 8 * 128];

__device__ float g_s1[Nn * 3];
__device__ float g_s2[Nn * 3];
__device__ float g_s3[Nn * 3];

__device__ float g_part [PMAX * Hd];
__device__ float g_part2[PMAX * Hd];
__device__ float g_scale[Hd];
__device__ float g_shift[Hd];

// ---------------- helpers ----------------
__device__ __forceinline__ void mma_f16(float* c, const uint32_t* a, const uint32_t* b) {
    asm volatile(
        "mma.sync.aligned.m16n8k16.row.col.f32.f16.f16.f32 "
        "{%0,%1,%2,%3}, {%4,%5,%6,%7}, {%8,%9}, {%0,%1,%2,%3};"
        : "+f"(c[0]), "+f"(c[1]), "+f"(c[2]), "+f"(c[3])
        : "r"(a[0]), "r"(a[1]), "r"(a[2]), "r"(a[3]), "r"(b[0]), "r"(b[1]));
}
__device__ __forceinline__ uint32_t pack_h2(float a, float b) {
    __half2 h = __floats2half2_rn(a, b);
    return *(uint32_t*)&h;
}

// ---------------- graph build ----------------
__global__ void k_init() {
    int i = blockIdx.x * blockDim.x + threadIdx.x;
    if (i < Nn) { g_deg[i] = 0; g_cnt[i] = 0; }
}

__global__ void k_count(const int* __restrict__ ei) {
    int e = blockIdx.x * blockDim.x + threadIdx.x;
    if (e < Ee) {
        int s = ei[e];
        int d = ei[e + Ee];
        if ((unsigned)s < Nn) atomicAdd(&g_deg[s], 1);
        if ((unsigned)d < Nn) atomicAdd(&g_cnt[d], 1);
    }
}

__global__ void k_scan1() {
    __shared__ int sd[1024];
    int b = blockIdx.x, tid = threadIdx.x;
    int i = b * 1024 + tid;
    int v = (i < Nn) ? g_cnt[i] : 0;
    sd[tid] = v;
    __syncthreads();
    for (int off = 1; off < 1024; off <<= 1) {
        int t = (tid >= off) ? sd[tid - off] : 0;
        __syncthreads();
        sd[tid] += t;
        __syncthreads();
    }
    if (i < Nn) g_rowptr[i + 1] = sd[tid];
    if (tid == 1023) g_bsum[b] = sd[1023];
}
// parallel scan over 49 block sums (64 threads)
__global__ void k_scan2() {
    __shared__ int sd[64];
    int t = threadIdx.x;
    int v = (t < SCB) ? g_bsum[t] : 0;
    sd[t] = v;
    __syncthreads();
    #pragma unroll
    for (int off = 1; off < 64; off <<= 1) {
        int u = (t >= off) ? sd[t - off] : 0;
        __syncthreads();
        sd[t] += u;
        __syncthreads();
    }
    if (t < SCB) g_boff[t] = sd[t] - v;   // exclusive
    if (t == 0) g_rowptr[0] = 0;
}
// scan finalize + dinv (deg final after k_count)
__global__ void k_scan3() {
    int i = blockIdx.x * blockDim.x + threadIdx.x;
    if (i < Nn) {
        int r = g_rowptr[i + 1] + g_boff[i >> 10];
        g_rowptr[i + 1] = r;
        g_tmpptr[i] = r - g_cnt[i];
        int d = g_deg[i];
        g_dinv[i] = (d > 0) ? rsqrtf((float)d) : 0.0f;
    }
}

__global__ void k_fill(const int* __restrict__ ei) {
    int e = blockIdx.x * blockDim.x + threadIdx.x;
    if (e < Ee) {
        int s = ei[e];
        int d = ei[e + Ee];
        if ((unsigned)s >= Nn || (unsigned)d >= Nn) return;
        int p = atomicAdd(&g_tmpptr[d], 1);
        float w = -g_dinv[s] * g_dinv[d];
        g_epk[p] = make_int2(s, __float_as_int(w));
    }
}

// pre-pack COMBINED weights -> half2 k-pair layout [kt][kpair][col].
// Monomial basis: block0: W0 - W2, block1: W1 - 3W3, block2: 2W2, block3: 4W3
// (W = [4][128][Hd] row-major, K index = blk*128 + k)
__global__ void k_wpack(const float* __restrict__ W, uint32_t* __restrict__ out) {
    int idx = blockIdx.x * blockDim.x + threadIdx.x;
    if (idx < 32 * 8 * 128) {
        int col = idx & 127;
        int kp  = (idx >> 7) & 7;
        int kt  = idx >> 10;
        int blk = kt >> 3;                  // 0..3
        int k0  = (kt & 7) * 16 + 2 * kp;   // k within block, 0..126
        float a0, a1;
        const float* Wb = W + blk * 128 * Hd;
        if (blk == 0) {
            const float* W2b = W + 2 * 128 * Hd;
            a0 = Wb[k0 * Hd + col]       - W2b[k0 * Hd + col];
            a1 = Wb[(k0 + 1) * Hd + col] - W2b[(k0 + 1) * Hd + col];
        } else if (blk == 1) {
            const float* W3b = W + 3 * 128 * Hd;
            a0 = Wb[k0 * Hd + col]       - 3.f * W3b[k0 * Hd + col];
            a1 = Wb[(k0 + 1) * Hd + col] - 3.f * W3b[(k0 + 1) * Hd + col];
        } else if (blk == 2) {
            a0 = 2.f * Wb[k0 * Hd + col];
            a1 = 2.f * Wb[(k0 + 1) * Hd + col];
        } else {
            a0 = 4.f * Wb[k0 * Hd + col];
            a1 = 4.f * Wb[(k0 + 1) * Hd + col];
        }
        out[idx] = pack_h2(a0, a1);
    }
}

// ---------------- propagation ----------------
// layer-1 (F=3) props stay in Chebyshev form (cheap)
__global__ void k_prop3(const float* __restrict__ hin,
                        const float* __restrict__ sub,
                        float* __restrict__ out) {
    int v = blockIdx.x * blockDim.x + threadIdx.x;
    if (v >= Nn) return;
    float a0 = 0.f, a1 = 0.f, a2 = 0.f;
    int b = g_rowptr[v], en = g_rowptr[v + 1];
    for (int i = b; i < en; i++) {
        int2 e = g_epk[i];
        float w = __int_as_float(e.y);
        const float* hp = hin + e.x * 3;
        a0 += w * hp[0]; a1 += w * hp[1]; a2 += w * hp[2];
    }
    float* o = out + v * 3;
    if (sub) {
        const float* sv = sub + v * 3;
        o[0] = 2.f * a0 - sv[0]; o[1] = 2.f * a1 - sv[1]; o[2] = 2.f * a2 - sv[2];
    } else {
        o[0] = a0; o[1] = a1; o[2] = a2;
    }
}

// warp per node, monomial basis: pure gather (+ optional BN on gathered input).
// bn != 0: out = sc * acc + sh * wsum (input is raw h, BN folded analytically)
__global__ void k_prop128(const float* __restrict__ hin,
                          float* __restrict__ out,
                          const float* __restrict__ sc,
                          const float* __restrict__ sh,
                          int bn) {
    int v = blockIdx.x * 4 + (threadIdx.x >> 5);
    if (v >= Nn) return;
    int lane = threadIdx.x & 31;
    float4 sc4, sh4;
    if (bn) {
        sc4 = ((const float4*)sc)[lane];
        sh4 = ((const float4*)sh)[lane];
    }
    int b = g_rowptr[v], en = g_rowptr[v + 1];
    float4 acc = make_float4(0.f, 0.f, 0.f, 0.f);
    float wsum = 0.f;
    int i = b;
    for (; i + 1 < en; i += 2) {
        int2 e0 = g_epk[i];
        int2 e1 = g_epk[i + 1];
        float w0 = __int_as_float(e0.y);
        float w1 = __int_as_float(e1.y);
        float4 v0 = *(const float4*)(hin + e0.x * Hd + lane * 4);
        float4 v1 = *(const float4*)(hin + e1.x * Hd + lane * 4);
        acc.x += w0 * v0.x + w1 * v1.x;
        acc.y += w0 * v0.y + w1 * v1.y;
        acc.z += w0 * v0.z + w1 * v1.z;
        acc.w += w0 * v0.w + w1 * v1.w;
        wsum += w0 + w1;
    }
    if (i < en) {
        int2 e = g_epk[i];
        float w = __int_as_float(e.y);
        float4 g = *(const float4*)(hin + e.x * Hd + lane * 4);
        acc.x += w * g.x; acc.y += w * g.y; acc.z += w * g.z; acc.w += w * g.w;
        wsum += w;
    }
    float4 r;
    if (bn) {
        r.x = sc4.x * acc.x + sh4.x * wsum;
        r.y = sc4.y * acc.y + sh4.y * wsum;
        r.z = sc4.z * acc.z + sh4.z * wsum;
        r.w = sc4.w * acc.w + sh4.w * wsum;
    } else {
        r = acc;
    }
    *(float4*)(out + v * Hd + lane * 4) = r;
}

// ---------------- layer 1 GEMM: K=12 (+ fused stats partials) ----------------
__global__ void k_gemm12(const float* __restrict__ x,  const float* __restrict__ t1,
                         const float* __restrict__ t2, const float* __restrict__ t3,
                         const float* __restrict__ W,  const float* __restrict__ bias,
                         float* __restrict__ out) {
    __shared__ float sW[12 * Hd];
    int c = threadIdx.x;
    #pragma unroll
    for (int j = 0; j < 12; j++) sW[j * Hd + c] = W[j * Hd + c];
    __syncthreads();
    const int RPB = 32;
    int v0 = blockIdx.x * RPB;
    float bv = bias[c];
    float s = 0.f, s2 = 0.f;
    for (int r = 0; r < RPB; r++) {
        int v = v0 + r;
        if (v >= Nn) break;
        float a[12];
        #pragma unroll
        for (int f = 0; f < 3; f++) {
            a[f]     = x [v * 3 + f];
            a[3 + f] = t1[v * 3 + f];
            a[6 + f] = t2[v * 3 + f];
            a[9 + f] = t3[v * 3 + f];
        }
        float acc = bv;
        #pragma unroll
        for (int j = 0; j < 12; j++) acc += a[j] * sW[j * Hd + c];
        acc = (acc > 0.f) ? acc : 0.01f * acc;   // leaky relu
        out[v * Hd + c] = acc;
        s += acc; s2 += acc * acc;
    }
    g_part [blockIdx.x * Hd + c] = s;
    g_part2[blockIdx.x * Hd + c] = s2;
}

// ---------------- tensor-core GEMM (fp16 m16n8k16, 2-stage pipeline) --------
// A = [h, p1, p2, p3], B pre-packed combined weights.
// mode: 1 = leaky+stats, 2 = relu+stats, 0 = no-act + row-L2-normalize
#define BM 128
#define BK 16
#define ASTR2 12
#define BSTR2 136

__global__ __launch_bounds__(256, 2)
void k_gemm_mma(const float* __restrict__ A0, const float* __restrict__ A1,
                const float* __restrict__ A2, const float* __restrict__ A3,
                const uint32_t* __restrict__ Wp, const float* __restrict__ bias,
                float* __restrict__ out,
                const float* __restrict__ scA, const float* __restrict__ shA,
                int mode) {
    __shared__ uint32_t As[2][BM][ASTR2];
    __shared__ uint32_t Bs[2][8][BSTR2];
    __shared__ float sred [8][64];
    __shared__ float sred2[8][64];
    __shared__ float rows2[2][BM];
    const float* Abuf[4] = {A0, A1, A2, A3};

    int tid = threadIdx.x;
    int wid = tid >> 5;
    int lane = tid & 31;
    int grp = lane >> 2;
    int tig = lane & 3;
    int m_base = (wid >> 1) * 32;
    int n_base = (wid & 1) * 64;
    int row0 = blockIdx.x * BM;

    float c[2][8][4];
    #pragma unroll
    for (int mi = 0; mi < 2; mi++)
        #pragma unroll
        for (int ni = 0; ni < 8; ni++)
            #pragma unroll
            for (int q = 0; q < 4; q++) c[mi][ni][q] = 0.f;

    int la_r  = tid >> 1;
    int la_c4 = (tid & 1) * 8;
    int lb_k  = tid >> 5;
    int lb_c4 = (tid & 31) * 4;

    auto load_stage = [&](int kt, uint4& ua, uint4& ub) {
        const float* A = Abuf[kt >> 3];
        int cb = (kt & 7) * BK;
        int gr = row0 + la_r;
        float4 v0 = make_float4(0.f,0.f,0.f,0.f), v1 = v0;
        if (gr < Nn) {
            const float4* src = (const float4*)(A + gr * Hd + cb + la_c4);
            v0 = src[0]; v1 = src[1];
        }
        if (scA && (kt >> 3) == 0) {
            float4 s0 = *(const float4*)(scA + cb + la_c4);
            float4 s1 = *(const float4*)(scA + cb + la_c4 + 4);
            float4 h0 = *(const float4*)(shA + cb + la_c4);
            float4 h1 = *(const float4*)(shA + cb + la_c4 + 4);
            v0.x = v0.x * s0.x + h0.x; v0.y = v0.y * s0.y + h0.y;
            v0.z = v0.z * s0.z + h0.z; v0.w = v0.w * s0.w + h0.w;
            v1.x = v1.x * s1.x + h1.x; v1.y = v1.y * s1.y + h1.y;
            v1.z = v1.z * s1.z + h1.z; v1.w = v1.w * s1.w + h1.w;
            if (gr >= Nn) { v0 = make_float4(0,0,0,0); v1 = v0; }
        }
        ua.x = pack_h2(v0.x, v0.y);
        ua.y = pack_h2(v0.z, v0.w);
        ua.z = pack_h2(v1.x, v1.y);
        ua.w = pack_h2(v1.z, v1.w);
        ub = *(const uint4*)(Wp + kt * 1024 + lb_k * 128 + lb_c4);
    };

    {
        uint4 ua, ub;
        load_stage(0, ua, ub);
        *(uint4*)&As[0][la_r][la_c4 >> 1] = ua;
        *(uint4*)&Bs[0][lb_k][lb_c4] = ub;
    }
    __syncthreads();

    for (int kt = 0; kt < 32; kt++) {
        int cur = kt & 1, nxt = cur ^ 1;
        uint4 na, nb;
        if (kt < 31) load_stage(kt + 1, na, nb);
        {
            uint32_t a[2][4], b[8][2];
            #pragma unroll
            for (int mi = 0; mi < 2; mi++) {
                int m0 = m_base + mi * 16 + grp;
                a[mi][0] = As[cur][m0][tig];
                a[mi][1] = As[cur][m0 + 8][tig];
                a[mi][2] = As[cur][m0][tig + 4];
                a[mi][3] = As[cur][m0 + 8][tig + 4];
            }
            #pragma unroll
            for (int ni = 0; ni < 8; ni++) {
                int nc = n_base + ni * 8 + grp;
                b[ni][0] = Bs[cur][tig][nc];
                b[ni][1] = Bs[cur][tig + 4][nc];
            }
            #pragma unroll
            for (int mi = 0; mi < 2; mi++)
                #pragma unroll
                for (int ni = 0; ni < 8; ni++)
                    mma_f16(c[mi][ni], a[mi], b[ni]);
        }
        if (kt < 31) {
            *(uint4*)&As[nxt][la_r][la_c4 >> 1] = na;
            *(uint4*)&Bs[nxt][lb_k][lb_c4] = nb;
        }
        __syncthreads();
    }

    // ---- bias + activation (zero invalid rows) ----
    #pragma unroll
    for (int mi = 0; mi < 2; mi++) {
        #pragma unroll
        for (int half = 0; half < 2; half++) {
            int row = row0 + m_base + mi * 16 + grp + half * 8;
            bool valid = row < Nn;
            #pragma unroll
            for (int ni = 0; ni < 8; ni++) {
                #pragma unroll
                for (int par = 0; par < 2; par++) {
                    int q = half * 2 + par;
                    int col = n_base + ni * 8 + tig * 2 + par;
                    float f = c[mi][ni][q] + __ldg(bias + col);
                    if (mode == 1)      f = (f > 0.f) ? f : 0.01f * f;
                    else if (mode == 2) f = fmaxf(f, 0.f);
                    c[mi][ni][q] = valid ? f : 0.f;
                }
            }
        }
    }

    float rscale[2][2] = {{1.f,1.f},{1.f,1.f}};

    if (mode != 0) {
        float ls[8][2], ls2[8][2];
        #pragma unroll
        for (int ni = 0; ni < 8; ni++)
            #pragma unroll
            for (int par = 0; par < 2; par++) {
                float s = 0.f, s2 = 0.f;
                #pragma unroll
                for (int mi = 0; mi < 2; mi++)
                    #pragma unroll
                    for (int half = 0; half < 2; half++) {
                        float f = c[mi][ni][half * 2 + par];
                        s += f; s2 += f * f;
                    }
                ls[ni][par] = s; ls2[ni][par] = s2;
            }
        #pragma unroll
        for (int off = 4; off < 32; off <<= 1) {
            #pragma unroll
            for (int ni = 0; ni < 8; ni++)
                #pragma unroll
                for (int par = 0; par < 2; par++) {
                    ls [ni][par] += __shfl_xor_sync(0xffffffffu, ls [ni][par], off);
                    ls2[ni][par] += __shfl_xor_sync(0xffffffffu, ls2[ni][par], off);
                }
        }
        if (lane < 4) {
            #pragma unroll
            for (int ni = 0; ni < 8; ni++)
                #pragma unroll
                for (int par = 0; par < 2; par++) {
                    sred [wid][ni * 8 + tig * 2 + par] = ls [ni][par];
                    sred2[wid][ni * 8 + tig * 2 + par] = ls2[ni][par];
                }
        }
        __syncthreads();
        if (tid < Hd) {
            int hf = tid >> 6, cl = tid & 63;
            float s = 0.f, s2 = 0.f;
            #pragma unroll
            for (int j = 0; j < 4; j++) {
                s  += sred [2 * j + hf][cl];
                s2 += sred2[2 * j + hf][cl];
            }
            g_part [blockIdx.x * Hd + tid] = s;
            g_part2[blockIdx.x * Hd + tid] = s2;
        }
    } else {
        #pragma unroll
        for (int mi = 0; mi < 2; mi++)
            #pragma unroll
            for (int half = 0; half < 2; half++) {
                float rsq = 0.f;
                #pragma unroll
                for (int ni = 0; ni < 8; ni++) {
                    float f0 = c[mi][ni][half * 2 + 0];
                    float f1 = c[mi][ni][half * 2 + 1];
                    rsq += f0 * f0 + f1 * f1;
                }
                rsq += __shfl_xor_sync(0xffffffffu, rsq, 1);
                rsq += __shfl_xor_sync(0xffffffffu, rsq, 2);
                if (tig == 0)
                    rows2[wid & 1][m_base + mi * 16 + grp + half * 8] = rsq;
            }
        __syncthreads();
        #pragma unroll
        for (int mi = 0; mi < 2; mi++)
            #pragma unroll
            for (int half = 0; half < 2; half++) {
                int rl = m_base + mi * 16 + grp + half * 8;
                float tot = rows2[0][rl] + rows2[1][rl];
                rscale[mi][half] = 1.f / fmaxf(sqrtf(tot), 1e-12f);
            }
    }

    // ---- store ----
    #pragma unroll
    for (int mi = 0; mi < 2; mi++) {
        #pragma unroll
        for (int half = 0; half < 2; half++) {
            int row = row0 + m_base + mi * 16 + grp + half * 8;
            if (row < Nn) {
                float rs = rscale[mi][half];
                #pragma unroll
                for (int ni = 0; ni < 8; ni++) {
                    int col = n_base + ni * 8 + tig * 2;
                    float f0 = c[mi][ni][half * 2 + 0] * rs;
                    float f1 = c[mi][ni][half * 2 + 1] * rs;
                    *(float2*)(out + row * Hd + col) = make_float2(f0, f1);
                }
            }
        }
    }
}

// ---------------- BN finalize (parallel: one block per channel) -------------
__global__ void k_bnfin(const float* __restrict__ gamma, const float* __restrict__ beta,
                        int nb) {
    int c = blockIdx.x;
    int t = threadIdx.x;
    float s = 0.f, s2 = 0.f;
    for (int b = t; b < nb; b += 256) {
        s  += g_part [b * Hd + c];
        s2 += g_part2[b * Hd + c];
    }
    __shared__ float ss[256], ss2[256];
    ss[t] = s; ss2[t] = s2;
    __syncthreads();
    #pragma unroll
    for (int off = 128; off; off >>= 1) {
        if (t < off) { ss[t] += ss[t + off]; ss2[t] += ss2[t + off]; }
        __syncthreads();
    }
    if (t == 0) {
        float m   = ss[0] / (float)Nn;
        float var = ss2[0] / (float)Nn - m * m;
        float inv = rsqrtf(var + 1e-5f);
        float sc  = gamma[c] * inv;
        g_scale[c] = sc;
        g_shift[c] = beta[c] - m * sc;
    }
}

// ---------------- host ----------------
extern "C" void kernel_launch(void* const* d_in, const int* in_sizes, int n_in,
                              void* d_out, int out_size) {
    const float* x  = (const float*)d_in[0];
    const int*   ei = (const int*)d_in[1];   // int32 (JAX x64 disabled)
    const float* W1 = (const float*)d_in[2];  const float* b1 = (const float*)d_in[3];
    const float* W2 = (const float*)d_in[4];  const float* b2 = (const float*)d_in[5];
    const float* W3 = (const float*)d_in[6];  const float* b3 = (const float*)d_in[7];
    const float* W4 = (const float*)d_in[8];  const float* b4 = (const float*)d_in[9];
    const float* g1 = (const float*)d_in[10]; const float* be1 = (const float*)d_in[11];
    const float* g2 = (const float*)d_in[12]; const float* be2 = (const float*)d_in[13];
    const float* g3 = (const float*)d_in[14]; const float* be3 = (const float*)d_in[15];

    float *p_t1, *p_t2, *p_t3, *p_out, *p_s1, *p_s2, *p_s3, *p_sc, *p_sh;
    uint32_t* p_wh;
    cudaGetSymbolAddress((void**)&p_t1,  g_t1);
    cudaGetSymbolAddress((void**)&p_t2,  g_t2);
    cudaGetSymbolAddress((void**)&p_t3,  g_t3);
    cudaGetSymbolAddress((void**)&p_out, g_out);
    cudaGetSymbolAddress((void**)&p_s1,  g_s1);
    cudaGetSymbolAddress((void**)&p_s2,  g_s2);
    cudaGetSymbolAddress((void**)&p_s3,  g_s3);
    cudaGetSymbolAddress((void**)&p_sc,  g_scale);
    cudaGetSymbolAddress((void**)&p_sh,  g_shift);
    cudaGetSymbolAddress((void**)&p_wh,  g_wh);

    const int TB = 256;
    const int WPW = 32 * 8 * 128;
    // graph build
    k_init <<<(Nn + TB - 1) / TB, TB>>>();
    k_count<<<(Ee + TB - 1) / TB, TB>>>(ei);
    k_scan1<<<SCB, 1024>>>();
    k_scan2<<<1, 64>>>();
    k_scan3<<<(Nn + TB - 1) / TB, TB>>>();
    k_fill <<<(Ee + TB - 1) / TB, TB>>>(ei);

    // pre-pack combined (monomial-basis) weights to fp16
    k_wpack<<<(WPW + TB - 1) / TB, TB>>>(W2, p_wh + 0 * WPW);
    k_wpack<<<(WPW + TB - 1) / TB, TB>>>(W3, p_wh + 1 * WPW);
    k_wpack<<<(WPW + TB - 1) / TB, TB>>>(W4, p_wh + 2 * WPW);

    int gP128 = (Nn + 3) / 4;
    int gGemm = (Nn + BM - 1) / BM;      // 391
    int g12   = (Nn + 31) / 32;          // 1563

    // layer 1 (F=3, Chebyshev form)
    k_prop3<<<(Nn + TB - 1) / TB, TB>>>(x, nullptr, p_s1);
    k_prop3<<<(Nn + TB - 1) / TB, TB>>>(p_s1, x, p_s2);
    k_prop3<<<(Nn + TB - 1) / TB, TB>>>(p_s2, p_s1, p_s3);
    k_gemm12<<<g12, Hd>>>(x, p_s1, p_s2, p_s3, W1, b1, p_out);
    k_bnfin<<<Hd, 256>>>(g1, be1, g12);

    // layer 2: p1 = L(bn(h)), p2 = L p1, p3 = L p2 (pure gathers)
    k_prop128<<<gP128, 128>>>(p_out, p_t1, p_sc, p_sh, 1);
    k_prop128<<<gP128, 128>>>(p_t1, p_t2, nullptr, nullptr, 0);
    k_prop128<<<gP128, 128>>>(p_t2, p_t3, nullptr, nullptr, 0);
    k_gemm_mma<<<gGemm, 256>>>(p_out, p_t1, p_t2, p_t3, p_wh + 0 * WPW, b2, p_out, p_sc, p_sh, 1);
    k_bnfin<<<Hd, 256>>>(g2, be2, gGemm);

    // layer 3
    k_prop128<<<gP128, 128>>>(p_out, p_t1, p_sc, p_sh, 1);
    k_prop128<<<gP128, 128>>>(p_t1, p_t2, nullptr, nullptr, 0);
    k_prop128<<<gP128, 128>>>(p_t2, p_t3, nullptr, nullptr, 0);
    k_gemm_mma<<<gGemm, 256>>>(p_out, p_t1, p_t2, p_t3, p_wh + 1 * WPW, b3, p_out, p_sc, p_sh, 2);
    k_bnfin<<<Hd, 256>>>(g3, be3, gGemm);

    // layer 4: props + GEMM with fused row-normalize, straight to d_out
    k_prop128<<<gP128, 128>>>(p_out, p_t1, p_sc, p_sh, 1);
    k_prop128<<<gP128, 128>>>(p_t1, p_t2, nullptr, nullptr, 0);
    k_prop128<<<gP128, 128>>>(p_t2, p_t3, nullptr, nullptr, 0);
    k_gemm_mma<<<gGemm, 256>>>(p_out, p_t1, p_t2, p_t3, p_wh + 2 * WPW, b4, (float*)d_out,
                               p_sc, p_sh, 0);
}